// round 1
// baseline (speedup 1.0000x reference)
#include <cuda_runtime.h>
#include <math.h>

// Problem constants
#define BB 4
#define NN 2048
#define DD 1024
#define ROWS 8192      // B*N
#define NF 37          // packed feature columns: charge(1)+shell(3)+class(32)+mass(1)

// ---------------- device scratch (allocation-free) ----------------
__device__ float g_senses[8192 * 3072];
__device__ float g_xnew  [8192 * 1024];
__device__ float g_V     [8192 * 1024];
__device__ float g_attnout[8192 * 1024];
__device__ float g_attn  [8192 * 2048];
__device__ float g_partial[4 * 16 * 1024];
__device__ float g_xmean [4 * 1024];
__device__ float g_ctx   [4 * 1024];
__device__ float g_selctx[4 * 3];
__device__ float g_charge[8192];
__device__ float g_mass  [8192];
__device__ float g_shell [8192 * 3];
__device__ int   g_cls   [8192];
__device__ float g_compat[1024];
__device__ float g_feat  [8192 * NF];
__device__ float g_Wfeat [1024 * NF];
__device__ float g_bfeat [NF];

__device__ __forceinline__ float sp_(float z) {
    return z > 20.f ? z : log1pf(expf(z));
}
__device__ __forceinline__ float neg_inf_() { return __int_as_float(0xff800000u); }

// ---------------- small kernels ----------------

// compat = sigmoid((L + L^T) * 0.5), 32x32
__global__ void k_compat(const float* __restrict__ L) {
    int t = threadIdx.x;                   // 1024 threads
    int i = t >> 5, j = t & 31;
    float v = (L[i * 32 + j] + L[j * 32 + i]) * 0.5f;
    g_compat[t] = 1.f / (1.f + expf(-v));
}

// column mean of x over n, stage 1: partial sums over 128-row chunks
__global__ void k_meanpart(const float* __restrict__ x) {
    int d  = blockIdx.x * 256 + threadIdx.x;   // gridDim.x = 4
    int bc = blockIdx.y;                       // 0..63 = b*16 + chunk
    int b  = bc >> 4, c = bc & 15;
    const float* xp = x + ((size_t)b * NN + c * 128) * DD + d;
    float s = 0.f;
    #pragma unroll 8
    for (int n = 0; n < 128; n++) s += xp[(size_t)n * DD];
    g_partial[bc * 1024 + d] = s;
}

__global__ void k_meanfin() {
    int idx = blockIdx.x * 256 + threadIdx.x;  // 4096 total
    int b = idx >> 10;
    int d = idx & 1023;
    float s = 0.f;
    #pragma unroll
    for (int c = 0; c < 16; c++) s += g_partial[(b * 16 + c) * 1024 + d];
    g_xmean[idx] = s * (1.f / (float)NN);
}

// ctx[b] = xmean[b] @ W_ctx + b_ctx
__global__ void k_ctx(const float* __restrict__ W_ctx, const float* __restrict__ b_ctx) {
    int b = blockIdx.y;
    int d = blockIdx.x * 256 + threadIdx.x;
    const float* xm = g_xmean + b * 1024;
    float acc = 0.f;
    #pragma unroll 4
    for (int k = 0; k < 1024; k++) acc += xm[k] * W_ctx[(size_t)k * 1024 + d];
    g_ctx[b * 1024 + d] = acc + b_ctx[d];
}

// selctx[b,s] = ctx[b] @ W_sel[D:2D, s] + b_sel[s]
__global__ void k_selctx(const float* __restrict__ W_sel, const float* __restrict__ b_sel) {
    int s = blockIdx.x, b = blockIdx.y;
    int tid = threadIdx.x;                 // 128 threads
    const float* c = g_ctx + b * 1024;
    float p = 0.f;
    for (int k = tid; k < 1024; k += 128) p += c[k] * W_sel[(size_t)(1024 + k) * 3 + s];
    __shared__ float red[128];
    red[tid] = p; __syncthreads();
    for (int o = 64; o; o >>= 1) { if (tid < o) red[tid] += red[tid + o]; __syncthreads(); }
    if (tid == 0) g_selctx[b * 3 + s] = red[0] + b_sel[s];
}

// pack W_feat (1024 x 37) and bias
__global__ void k_packfeat(const float* __restrict__ W_charge, const float* __restrict__ b_charge,
                           const float* __restrict__ W_shell,  const float* __restrict__ b_shell,
                           const float* __restrict__ W_class,  const float* __restrict__ b_class,
                           const float* __restrict__ W_mass,   const float* __restrict__ b_mass) {
    int idx = blockIdx.x * 256 + threadIdx.x;
    if (idx < 1024 * NF) {
        int k = idx / NF, c = idx % NF;
        float v;
        if (c == 0)       v = W_charge[k];
        else if (c <= 3)  v = W_shell[k * 3 + (c - 1)];
        else if (c <= 35) v = W_class[k * 32 + (c - 4)];
        else              v = W_mass[k];
        g_Wfeat[k * NF + c] = v;
    }
    if (idx < NF) {
        float v;
        if (idx == 0)       v = b_charge[0];
        else if (idx <= 3)  v = b_shell[idx - 1];
        else if (idx <= 35) v = b_class[idx - 4];
        else                v = b_mass[0];
        g_bfeat[idx] = v;
    }
}

// per-row: sel logits from x, softmax over 3, combine senses -> xnew
__global__ void k_combine(const float* __restrict__ x, const float* __restrict__ W_sel) {
    int row = blockIdx.x;          // 0..8191
    int b   = row >> 11;
    int tid = threadIdx.x;         // 256
    const float* xr = x + (size_t)row * DD;
    float p0 = 0.f, p1 = 0.f, p2 = 0.f;
    for (int k = tid; k < 1024; k += 256) {
        float xv = xr[k];
        const float* w = W_sel + (size_t)k * 3;
        p0 += xv * w[0]; p1 += xv * w[1]; p2 += xv * w[2];
    }
    __shared__ float r0[256], r1[256], r2[256];
    r0[tid] = p0; r1[tid] = p1; r2[tid] = p2; __syncthreads();
    for (int o = 128; o; o >>= 1) {
        if (tid < o) { r0[tid] += r0[tid + o]; r1[tid] += r1[tid + o]; r2[tid] += r2[tid + o]; }
        __syncthreads();
    }
    float l0 = r0[0] + g_selctx[b * 3 + 0];
    float l1 = r1[0] + g_selctx[b * 3 + 1];
    float l2 = r2[0] + g_selctx[b * 3 + 2];
    float m  = fmaxf(l0, fmaxf(l1, l2));
    float e0 = expf(l0 - m), e1 = expf(l1 - m), e2 = expf(l2 - m);
    float inv = 1.f / (e0 + e1 + e2);
    float w0 = e0 * inv, w1 = e1 * inv, w2 = e2 * inv;

    const float4* S0 = (const float4*)(g_senses + (size_t)row * 3072);
    const float4* S1 = (const float4*)(g_senses + (size_t)row * 3072 + 1024);
    const float4* S2 = (const float4*)(g_senses + (size_t)row * 3072 + 2048);
    float4* out = (float4*)(g_xnew + (size_t)row * DD);
    float4 a = S0[tid], bb = S1[tid], c = S2[tid];
    out[tid] = make_float4(w0 * a.x + w1 * bb.x + w2 * c.x,
                           w0 * a.y + w1 * bb.y + w2 * c.y,
                           w0 * a.z + w1 * bb.z + w2 * c.z,
                           w0 * a.w + w1 * bb.w + w2 * c.w);
}

// per-row features from packed feat matrix
__global__ void k_features() {
    int row = blockIdx.x * 256 + threadIdx.x;
    if (row >= ROWS) return;
    const float* f = g_feat + (size_t)row * NF;
    g_charge[row] = tanhf(f[0]);
    float s0 = f[1], s1 = f[2], s2 = f[3];
    float m = fmaxf(s0, fmaxf(s1, s2));
    float e0 = expf(s0 - m), e1 = expf(s1 - m), e2 = expf(s2 - m);
    float inv = 1.f / (e0 + e1 + e2);
    g_shell[row * 3 + 0] = e0 * inv;
    g_shell[row * 3 + 1] = e1 * inv;
    g_shell[row * 3 + 2] = e2 * inv;
    float best = f[4]; int bi = 0;
    #pragma unroll
    for (int c = 1; c < 32; c++) { float v = f[4 + c]; if (v > best) { best = v; bi = c; } }
    g_cls[row] = bi;
    g_mass[row] = sp_(f[36]) + 0.5f;
}

// energy scores + causal softmax -> attn row
__global__ void k_scores(const float* __restrict__ w_charge, const float* __restrict__ w_shell,
                         const float* __restrict__ w_distance, const float* __restrict__ w_mass,
                         const float* __restrict__ w_valence, const float* __restrict__ temperature) {
    int gi = blockIdx.x;              // 0..8191
    int b  = gi >> 11, i = gi & 2047;
    int tid = threadIdx.x;            // 256
    __shared__ float sc[2048];
    __shared__ float cp[1024];
    __shared__ float red[256];
    for (int t = tid; t < 1024; t += 256) cp[t] = g_compat[t];

    float spc = sp_(w_charge[0]);
    float sps = sp_(w_shell[0]);
    float spd = sp_(w_distance[0]);
    float spm = sp_(w_mass[0]);
    float spv = sp_(w_valence[0]);
    float invt = 1.f / sp_(temperature[0]);

    const float* ch = g_charge + b * NN;
    const float* ms = g_mass + b * NN;
    const float* sh = g_shell + (size_t)b * NN * 3;
    const int*   cl = g_cls + b * NN;
    float ci = ch[i], mi = ms[i];
    float si0 = sh[i * 3], si1 = sh[i * 3 + 1], si2 = sh[i * 3 + 2];
    int cli = cl[i] * 32;
    __syncthreads();

    for (int j = tid; j < NN; j += 256) {
        if (j <= i) {
            float cj = ch[j], mj = ms[j];
            float d0 = fabsf(si0 - sh[j * 3]);
            float d1 = fabsf(si1 - sh[j * 3 + 1]);
            float d2 = fabsf(si2 - sh[j * 3 + 2]);
            float dist = (float)(i - j);
            float E = spc * ci * cj + sps * (d0 + d1 + d2)
                    - spd * __fdividef(1.f, 1.f + 0.1f * dist)
                    + spm * 0.1f * mi * mj - spv;
            sc[j] = -E * invt * cp[cli + cl[j]];
        } else {
            sc[j] = neg_inf_();
        }
    }
    __syncthreads();

    float lm = neg_inf_();
    for (int j = tid; j < NN; j += 256) lm = fmaxf(lm, sc[j]);
    red[tid] = lm; __syncthreads();
    for (int o = 128; o; o >>= 1) { if (tid < o) red[tid] = fmaxf(red[tid], red[tid + o]); __syncthreads(); }
    float mx = red[0]; __syncthreads();

    float ls = 0.f;
    for (int j = tid; j < NN; j += 256) { float e = expf(sc[j] - mx); sc[j] = e; ls += e; }
    red[tid] = ls; __syncthreads();
    for (int o = 128; o; o >>= 1) { if (tid < o) red[tid] += red[tid + o]; __syncthreads(); }
    float inv = 1.f / red[0];

    float* ar = g_attn + (size_t)gi * NN;
    for (int j = tid; j < NN; j += 256) ar[j] = sc[j] * inv;
}

// ---------------- generic tiled SGEMM: C = A@B (+bias), row-major ----------------
// 128x128 block tile, BK=16, 256 threads, 8x8 per thread.
// batch via blockIdx.z and strides; causal: k-loop limit = rowblock end.
__global__ __launch_bounds__(256)
void sgemm128(const float* __restrict__ A, const float* __restrict__ B,
              float* __restrict__ C, const float* __restrict__ bias,
              int M, int N, int K,
              size_t sA, size_t sB, size_t sC, int causal) {
    A += (size_t)blockIdx.z * sA;
    B += (size_t)blockIdx.z * sB;
    C += (size_t)blockIdx.z * sC;
    int rowStart = blockIdx.y * 128;
    int colStart = blockIdx.x * 128;
    int kmax = causal ? min(K, rowStart + 128) : K;

    __shared__ float As[16][128];
    __shared__ float Bs[16][128];
    int tid = threadIdx.x;
    int tx = tid & 15, ty = tid >> 4;
    float acc[8][8];
    #pragma unroll
    for (int i = 0; i < 8; i++)
        #pragma unroll
        for (int j = 0; j < 8; j++) acc[i][j] = 0.f;

    const bool n_vec = ((N & 3) == 0);

    for (int k0 = 0; k0 < kmax; k0 += 16) {
        // A tile: 128 rows x 16 cols, transposed into As[k][m]
        #pragma unroll
        for (int l = 0; l < 2; l++) {
            int idx = tid + l * 256;
            int m = idx >> 2;
            int kq = (idx & 3) * 4;
            float4 v = *reinterpret_cast<const float4*>(A + (size_t)(rowStart + m) * K + k0 + kq);
            As[kq + 0][m] = v.x; As[kq + 1][m] = v.y; As[kq + 2][m] = v.z; As[kq + 3][m] = v.w;
        }
        // B tile: 16 rows x 128 cols
        #pragma unroll
        for (int l = 0; l < 2; l++) {
            int idx = tid + l * 256;
            int kr = idx >> 5;
            int nq = (idx & 31) * 4;
            int col = colStart + nq;
            float4 v;
            if (n_vec && col + 3 < N) {
                v = *reinterpret_cast<const float4*>(B + (size_t)(k0 + kr) * N + col);
            } else {
                const float* bp = B + (size_t)(k0 + kr) * N;
                v.x = (col + 0 < N) ? bp[col + 0] : 0.f;
                v.y = (col + 1 < N) ? bp[col + 1] : 0.f;
                v.z = (col + 2 < N) ? bp[col + 2] : 0.f;
                v.w = (col + 3 < N) ? bp[col + 3] : 0.f;
            }
            *reinterpret_cast<float4*>(&Bs[kr][nq]) = v;
        }
        __syncthreads();
        #pragma unroll
        for (int kk = 0; kk < 16; kk++) {
            float ra[8], rb[8];
            *(float4*)&ra[0] = *(float4*)&As[kk][ty * 8];
            *(float4*)&ra[4] = *(float4*)&As[kk][ty * 8 + 4];
            *(float4*)&rb[0] = *(float4*)&Bs[kk][tx * 8];
            *(float4*)&rb[4] = *(float4*)&Bs[kk][tx * 8 + 4];
            #pragma unroll
            for (int i = 0; i < 8; i++)
                #pragma unroll
                for (int j = 0; j < 8; j++)
                    acc[i][j] += ra[i] * rb[j];
        }
        __syncthreads();
    }

    #pragma unroll
    for (int i = 0; i < 8; i++) {
        size_t row = rowStart + ty * 8 + i;
        #pragma unroll
        for (int j = 0; j < 8; j++) {
            int col = colStart + tx * 8 + j;
            if (col < N) {
                float v = acc[i][j] + (bias ? bias[col] : 0.f);
                C[row * (size_t)N + col] = v;
            }
        }
    }
}

// ---------------- host ----------------
static void* symaddr(const void* p) { return (void*)p; }

extern "C" void kernel_launch(void* const* d_in, const int* in_sizes, int n_in,
                              void* d_out, int out_size) {
    const float* x         = (const float*)d_in[0];
    const float* W_sense   = (const float*)d_in[1];
    const float* b_sense   = (const float*)d_in[2];
    const float* W_ctx     = (const float*)d_in[3];
    const float* b_ctx     = (const float*)d_in[4];
    const float* W_sel     = (const float*)d_in[5];
    const float* b_sel     = (const float*)d_in[6];
    const float* W_charge  = (const float*)d_in[7];
    const float* b_charge  = (const float*)d_in[8];
    const float* W_shell   = (const float*)d_in[9];
    const float* b_shell   = (const float*)d_in[10];
    const float* W_class   = (const float*)d_in[11];
    const float* b_class   = (const float*)d_in[12];
    const float* W_mass    = (const float*)d_in[13];
    const float* b_mass    = (const float*)d_in[14];
    // d_in[15], d_in[16]: W_val/b_val — unused (softmax sums to 1)
    const float* compatL   = (const float*)d_in[17];
    const float* w_charge  = (const float*)d_in[18];
    const float* w_shell   = (const float*)d_in[19];
    const float* w_distance= (const float*)d_in[20];
    const float* w_mass    = (const float*)d_in[21];
    const float* w_valence = (const float*)d_in[22];
    const float* temperature=(const float*)d_in[23];
    const float* W_v       = (const float*)d_in[24];
    const float* b_v       = (const float*)d_in[25];
    const float* W_out     = (const float*)d_in[26];
    const float* b_out     = (const float*)d_in[27];
    float* out = (float*)d_out;

    void *p_senses, *p_xnew, *p_V, *p_attnout, *p_attn, *p_Wfeat, *p_bfeat, *p_feat;
    cudaGetSymbolAddress(&p_senses, g_senses);
    cudaGetSymbolAddress(&p_xnew,   g_xnew);
    cudaGetSymbolAddress(&p_V,      g_V);
    cudaGetSymbolAddress(&p_attnout,g_attnout);
    cudaGetSymbolAddress(&p_attn,   g_attn);
    cudaGetSymbolAddress(&p_Wfeat,  g_Wfeat);
    cudaGetSymbolAddress(&p_bfeat,  g_bfeat);
    cudaGetSymbolAddress(&p_feat,   g_feat);

    // independent prep
    k_compat<<<1, 1024>>>(compatL);
    k_meanpart<<<dim3(4, 64), 256>>>(x);
    k_meanfin<<<16, 256>>>();
    k_ctx<<<dim3(4, 4), 256>>>(W_ctx, b_ctx);
    k_selctx<<<dim3(3, 4), 128>>>(W_sel, b_sel);
    k_packfeat<<<(1024 * NF + 255) / 256, 256>>>(W_charge, b_charge, W_shell, b_shell,
                                                 W_class, b_class, W_mass, b_mass);

    // senses = x @ W_sense + b_sense   (8192 x 3072, K=1024)
    sgemm128<<<dim3(24, 64, 1), 256>>>(x, W_sense, (float*)p_senses, b_sense,
                                       ROWS, 3072, 1024, 0, 0, 0, 0);
    // combine -> xnew
    k_combine<<<ROWS, 256>>>(x, W_sel);

    // feat = xnew @ Wfeat + bfeat    (8192 x 37)
    sgemm128<<<dim3(1, 64, 1), 256>>>((const float*)p_xnew, (const float*)p_Wfeat,
                                      (float*)p_feat, (const float*)p_bfeat,
                                      ROWS, NF, 1024, 0, 0, 0, 0);
    k_features<<<ROWS / 256, 256>>>();

    // V = xnew @ W_v + b_v   (8192 x 1024)
    sgemm128<<<dim3(8, 64, 1), 256>>>((const float*)p_xnew, W_v, (float*)p_V, b_v,
                                      ROWS, 1024, 1024, 0, 0, 0, 0);

    // scores + causal softmax -> attn
    k_scores<<<ROWS, 256>>>(w_charge, w_shell, w_distance, w_mass, w_valence, temperature);

    // attnout = attn @ V (batched, causal k-limit)
    sgemm128<<<dim3(8, 16, 4), 256>>>((const float*)p_attn, (const float*)p_V,
                                      (float*)p_attnout, nullptr,
                                      NN, 1024, NN,
                                      (size_t)NN * NN, (size_t)NN * 1024, (size_t)NN * 1024, 1);

    // out = attnout @ W_out + b_out
    sgemm128<<<dim3(8, 64, 1), 256>>>((const float*)p_attnout, W_out, out, b_out,
                                      ROWS, 1024, 1024, 0, 0, 0, 0);
    (void)in_sizes; (void)n_in; (void)out_size; (void)symaddr;
}

// round 4
// speedup vs baseline: 1.5702x; 1.5702x over previous
#include <cuda_runtime.h>
#include <cuda_bf16.h>
#include <math.h>
#include <stdint.h>
#include <cstdint>

// Problem constants
#define BB 4
#define NN 2048
#define DD 1024
#define ROWS 8192      // B*N
#define NF 37          // packed feature columns: charge(1)+shell(3)+class(32)+mass(1)

// ---------------- device scratch (allocation-free) ----------------
__device__ float g_senses[8192 * 3072];
__device__ float g_xnew  [8192 * 1024];
__device__ float g_V     [8192 * 1024];
__device__ float g_attnout[8192 * 1024];
__device__ float g_attn  [8192 * 2048];
__device__ float g_partial[4 * 16 * 1024];
__device__ float g_xmean [4 * 1024];
__device__ float g_ctx   [4 * 1024];
__device__ float g_selctx[4 * 3];
__device__ float g_selw  [8192 * 3];
__device__ float g_charge[8192];
__device__ float g_mass  [8192];
__device__ float g_shell [8192 * 3];
__device__ int   g_cls   [8192];
__device__ float g_compat[1024];
__device__ float g_Wfeat [1024 * NF];
__device__ float g_bfeat [NF];
__device__ float g_Wcomb [1024 * 3 * NF];
__device__ float g_bcomb [3 * NF];
__device__ float g_xC    [8192 * 3 * NF];

__device__ __forceinline__ float sp_(float z) {
    return z > 20.f ? z : log1pf(expf(z));
}
__device__ __forceinline__ float neg_inf_() { return __int_as_float(0xff800000u); }

__device__ __forceinline__ uint32_t smem_u32(const void* p) {
    uint32_t a;
    asm("{ .reg .u64 t; cvta.to.shared.u64 t, %1; cvt.u32.u64 %0, t; }" : "=r"(a) : "l"(p));
    return a;
}
__device__ __forceinline__ void ldm_x4(uint32_t* r, uint32_t addr) {
    asm volatile("ldmatrix.sync.aligned.m8n8.x4.shared.b16 {%0,%1,%2,%3}, [%4];"
        : "=r"(r[0]), "=r"(r[1]), "=r"(r[2]), "=r"(r[3]) : "r"(addr));
}
__device__ __forceinline__ void mma16816(float* c, const uint32_t* a, const uint32_t* b) {
    asm volatile("mma.sync.aligned.m16n8k16.row.col.f32.bf16.bf16.f32 "
        "{%0,%1,%2,%3}, {%4,%5,%6,%7}, {%8,%9}, {%0,%1,%2,%3};"
        : "+f"(c[0]), "+f"(c[1]), "+f"(c[2]), "+f"(c[3])
        : "r"(a[0]), "r"(a[1]), "r"(a[2]), "r"(a[3]), "r"(b[0]), "r"(b[1]));
}

// ---------------- bf16 split GEMM via mma.sync (HMMA tensor cores) ----------------
// C[M,N] = A[M,K] @ B[K,N] (+bias), fp32 in/out. Each operand split into SPLIT
// bf16 components (error-free); terms with ci+cj < SPLIT accumulate in fp32 regs.
// 128x128 CTA tile, BK=32, 256 threads = 8 warps (2 M x 4 N), 64x32 per warp.
// smem rows padded to 40 bf16 (80B, 16B-aligned) -> conflict-free ldmatrix.
template<int SPLIT, bool CAUSAL>
__global__ __launch_bounds__(256, 2)
void hgemm(const float* __restrict__ A, const float* __restrict__ B,
           float* __restrict__ C, const float* __restrict__ bias,
           int K, int lda, int ldb, int ldc,
           size_t sA, size_t sB, size_t sC) {
    extern __shared__ char sm[];
    A += (size_t)blockIdx.z * sA;
    B += (size_t)blockIdx.z * sB;
    C += (size_t)blockIdx.z * sC;
    const int rowStart = blockIdx.y * 128;
    const int colStart = blockIdx.x * 128;
    const int kmax = CAUSAL ? min(K, rowStart + 128) : K;
    const int tid = threadIdx.x, lane = tid & 31, wid = tid >> 5;
    const int mW = (wid >> 2) * 64;   // warp row offset in tile
    const int nW = (wid & 3) * 32;    // warp col offset in tile

    __nv_bfloat16* aS = (__nv_bfloat16*)sm;                       // SPLIT x [128][40]
    __nv_bfloat16* bS = (__nv_bfloat16*)(sm + SPLIT * 10240);     // SPLIT x [128 n][40 k]
    const uint32_t smA = smem_u32(aS);
    const uint32_t smB = smem_u32(bS);

    float acc[4][4][4];
    #pragma unroll
    for (int i = 0; i < 4; ++i)
        #pragma unroll
        for (int j = 0; j < 4; ++j)
            #pragma unroll
            for (int e = 0; e < 4; ++e) acc[i][j][e] = 0.f;

    // per-thread ldmatrix element offsets
    const int aoff = (mW + (lane & 15)) * 40 + (lane >> 4) * 8;
    const int boff = (nW + ((lane >> 4) << 3) + (lane & 7)) * 40 + ((lane >> 3) & 1) * 8;

    for (int k0 = 0; k0 < kmax; k0 += 32) {
        __syncthreads();
        // ---- A tile: 128 rows x 32 k, float4 loads, split-convert to bf16 ----
        #pragma unroll
        for (int l = 0; l < 4; ++l) {
            int idx = l * 256 + tid;          // 0..1023
            int r = idx >> 3;                 // 0..127
            int kq = (idx & 7) * 4;           // 0..28
            float4 cur = *reinterpret_cast<const float4*>(
                A + (size_t)(rowStart + r) * lda + k0 + kq);
            #pragma unroll
            for (int c = 0; c < SPLIT; ++c) {
                __nv_bfloat16 h0 = __float2bfloat16(cur.x);
                __nv_bfloat16 h1 = __float2bfloat16(cur.y);
                __nv_bfloat16 h2 = __float2bfloat16(cur.z);
                __nv_bfloat16 h3 = __float2bfloat16(cur.w);
                if (c < SPLIT - 1) {
                    cur.x -= __bfloat162float(h0); cur.y -= __bfloat162float(h1);
                    cur.z -= __bfloat162float(h2); cur.w -= __bfloat162float(h3);
                }
                __nv_bfloat16* p = aS + c * 5120 + r * 40 + kq;
                p[0] = h0; p[1] = h1; p[2] = h2; p[3] = h3;
            }
        }
        // ---- B tile: 32 k x 128 n, scalar coalesced loads, store transposed ----
        #pragma unroll
        for (int l = 0; l < 16; ++l) {
            int idx = l * 256 + tid;          // 0..4095
            int n = idx & 127;
            int k = idx >> 7;                 // 0..31
            float v = B[(size_t)(k0 + k) * ldb + colStart + n];
            #pragma unroll
            for (int c = 0; c < SPLIT; ++c) {
                __nv_bfloat16 h = __float2bfloat16(v);
                if (c < SPLIT - 1) v -= __bfloat162float(h);
                bS[c * 5120 + n * 40 + k] = h;
            }
        }
        __syncthreads();

        // ---- compute: split terms x 2 k-steps x 16 mma ----
        #pragma unroll
        for (int ci = 0; ci < SPLIT; ++ci)
            #pragma unroll
            for (int cj = 0; cj + ci < SPLIT; ++cj) {
                #pragma unroll
                for (int ks = 0; ks < 2; ++ks) {
                    uint32_t af[4][4], bf[2][4];
                    #pragma unroll
                    for (int am = 0; am < 4; ++am)
                        ldm_x4(af[am], smA + ci * 10240u +
                               (uint32_t)(aoff + am * 640 + ks * 16) * 2u);
                    #pragma unroll
                    for (int ap = 0; ap < 2; ++ap)
                        ldm_x4(bf[ap], smB + cj * 10240u +
                               (uint32_t)(boff + ap * 640 + ks * 16) * 2u);
                    #pragma unroll
                    for (int am = 0; am < 4; ++am)
                        #pragma unroll
                        for (int an = 0; an < 4; ++an)
                            mma16816(acc[am][an], af[am], &bf[an >> 1][(an & 1) * 2]);
                }
            }
    }

    // ---- epilogue: direct register -> global (float2), +bias ----
    #pragma unroll
    for (int am = 0; am < 4; ++am) {
        int row = rowStart + mW + am * 16 + (lane >> 2);
        #pragma unroll
        for (int an = 0; an < 4; ++an) {
            int col = colStart + nW + an * 8 + (lane & 3) * 2;
            float b0 = bias ? bias[col] : 0.f;
            float b1 = bias ? bias[col + 1] : 0.f;
            float2 v0 = make_float2(acc[am][an][0] + b0, acc[am][an][1] + b1);
            float2 v1 = make_float2(acc[am][an][2] + b0, acc[am][an][3] + b1);
            *reinterpret_cast<float2*>(C + (size_t)row * ldc + col) = v0;
            *reinterpret_cast<float2*>(C + (size_t)(row + 8) * ldc + col) = v1;
        }
    }
}

// ---------------- small kernels ----------------

__global__ void k_compat(const float* __restrict__ L) {
    int t = threadIdx.x;
    int i = t >> 5, j = t & 31;
    float v = (L[i * 32 + j] + L[j * 32 + i]) * 0.5f;
    g_compat[t] = 1.f / (1.f + expf(-v));
}

__global__ void k_meanpart(const float* __restrict__ x) {
    int d  = blockIdx.x * 256 + threadIdx.x;
    int bc = blockIdx.y;
    int b  = bc >> 4, c = bc & 15;
    const float* xp = x + ((size_t)b * NN + c * 128) * DD + d;
    float s = 0.f;
    #pragma unroll 8
    for (int n = 0; n < 128; n++) s += xp[(size_t)n * DD];
    g_partial[bc * 1024 + d] = s;
}

__global__ void k_meanfin() {
    int idx = blockIdx.x * 256 + threadIdx.x;
    int b = idx >> 10;
    int d = idx & 1023;
    float s = 0.f;
    #pragma unroll
    for (int c = 0; c < 16; c++) s += g_partial[(b * 16 + c) * 1024 + d];
    g_xmean[idx] = s * (1.f / (float)NN);
}

__global__ void k_ctxpart(const float* __restrict__ W_ctx) {
    int d = blockIdx.x * 256 + threadIdx.x;
    int b = blockIdx.y;
    int z = blockIdx.z;
    const float* xm = g_xmean + b * 1024 + z * 128;
    const float* W  = W_ctx + (size_t)(z * 128) * 1024 + d;
    float acc = 0.f;
    #pragma unroll 8
    for (int k = 0; k < 128; k++) acc += xm[k] * W[(size_t)k * 1024];
    g_partial[(z * 4 + b) * 1024 + d] = acc;
}

__global__ void k_ctxfin(const float* __restrict__ b_ctx) {
    int idx = blockIdx.x * 256 + threadIdx.x;
    int b = idx >> 10, d = idx & 1023;
    float s = 0.f;
    #pragma unroll
    for (int z = 0; z < 8; z++) s += g_partial[(z * 4 + b) * 1024 + d];
    g_ctx[idx] = s + b_ctx[d];
}

__global__ void k_selctx(const float* __restrict__ W_sel, const float* __restrict__ b_sel) {
    int s = blockIdx.x, b = blockIdx.y;
    int tid = threadIdx.x;
    const float* c = g_ctx + b * 1024;
    float p = 0.f;
    for (int k = tid; k < 1024; k += 128) p += c[k] * W_sel[(size_t)(1024 + k) * 3 + s];
    __shared__ float red[128];
    red[tid] = p; __syncthreads();
    for (int o = 64; o; o >>= 1) { if (tid < o) red[tid] += red[tid + o]; __syncthreads(); }
    if (tid == 0) g_selctx[b * 3 + s] = red[0] + b_sel[s];
}

__global__ void k_packfeat(const float* __restrict__ W_charge, const float* __restrict__ b_charge,
                           const float* __restrict__ W_shell,  const float* __restrict__ b_shell,
                           const float* __restrict__ W_class,  const float* __restrict__ b_class,
                           const float* __restrict__ W_mass,   const float* __restrict__ b_mass) {
    int idx = blockIdx.x * 256 + threadIdx.x;
    if (idx < 1024 * NF) {
        int k = idx / NF, c = idx % NF;
        float v;
        if (c == 0)       v = W_charge[k];
        else if (c <= 3)  v = W_shell[k * 3 + (c - 1)];
        else if (c <= 35) v = W_class[k * 32 + (c - 4)];
        else              v = W_mass[k];
        g_Wfeat[k * NF + c] = v;
    }
    if (idx < NF) {
        float v;
        if (idx == 0)       v = b_charge[0];
        else if (idx <= 3)  v = b_shell[idx - 1];
        else if (idx <= 35) v = b_class[idx - 4];
        else                v = b_mass[0];
        g_bfeat[idx] = v;
    }
}

// bcomb[s*37+c] = b_sense_s . Wfeat[:,c]
__global__ void k_bcomb(const float* __restrict__ b_sense) {
    int c = blockIdx.x * 128 + threadIdx.x;
    if (c >= 3 * NF) return;
    int s = c / NF, cc = c % NF;
    float acc = 0.f;
    for (int k = 0; k < 1024; k++)
        acc += b_sense[s * 1024 + k] * g_Wfeat[k * NF + cc];
    g_bcomb[c] = acc;
}

// sel weights + combine senses -> xnew; stores weights for the feat path
__global__ void k_combine(const float* __restrict__ x, const float* __restrict__ W_sel) {
    int row = blockIdx.x;
    int b   = row >> 11;
    int tid = threadIdx.x;
    const float* xr = x + (size_t)row * DD;
    float p0 = 0.f, p1 = 0.f, p2 = 0.f;
    for (int k = tid; k < 1024; k += 256) {
        float xv = xr[k];
        const float* w = W_sel + (size_t)k * 3;
        p0 += xv * w[0]; p1 += xv * w[1]; p2 += xv * w[2];
    }
    __shared__ float r0[256], r1[256], r2[256];
    r0[tid] = p0; r1[tid] = p1; r2[tid] = p2; __syncthreads();
    for (int o = 128; o; o >>= 1) {
        if (tid < o) { r0[tid] += r0[tid + o]; r1[tid] += r1[tid + o]; r2[tid] += r2[tid + o]; }
        __syncthreads();
    }
    float l0 = r0[0] + g_selctx[b * 3 + 0];
    float l1 = r1[0] + g_selctx[b * 3 + 1];
    float l2 = r2[0] + g_selctx[b * 3 + 2];
    float m  = fmaxf(l0, fmaxf(l1, l2));
    float e0 = expf(l0 - m), e1 = expf(l1 - m), e2 = expf(l2 - m);
    float inv = 1.f / (e0 + e1 + e2);
    float w0 = e0 * inv, w1 = e1 * inv, w2 = e2 * inv;
    if (tid == 0) {
        g_selw[row * 3 + 0] = w0;
        g_selw[row * 3 + 1] = w1;
        g_selw[row * 3 + 2] = w2;
    }

    const float4* S0 = (const float4*)(g_senses + (size_t)row * 3072);
    const float4* S1 = (const float4*)(g_senses + (size_t)row * 3072 + 1024);
    const float4* S2 = (const float4*)(g_senses + (size_t)row * 3072 + 2048);
    float4* out = (float4*)(g_xnew + (size_t)row * DD);
    float4 a = S0[tid], bb = S1[tid], c = S2[tid];
    out[tid] = make_float4(w0 * a.x + w1 * bb.x + w2 * c.x,
                           w0 * a.y + w1 * bb.y + w2 * c.y,
                           w0 * a.z + w1 * bb.z + w2 * c.z,
                           w0 * a.w + w1 * bb.w + w2 * c.w);
}

// per-row features from the fp32 xC path: feat = sum_s w_s*(xC_s + bcomb_s) + bfeat
__global__ void k_featrow() {
    int row = blockIdx.x;
    int tid = threadIdx.x;   // 64
    __shared__ float fv[NF];
    if (tid < NF) {
        float w0 = g_selw[row * 3 + 0];
        float w1 = g_selw[row * 3 + 1];
        float w2 = g_selw[row * 3 + 2];
        const float* xc = g_xC + (size_t)row * (3 * NF);
        float acc = g_bfeat[tid]
                  + w0 * (xc[tid]          + g_bcomb[tid])
                  + w1 * (xc[NF + tid]     + g_bcomb[NF + tid])
                  + w2 * (xc[2 * NF + tid] + g_bcomb[2 * NF + tid]);
        fv[tid] = acc;
    }
    __syncthreads();
    if (tid == 0) {
        g_charge[row] = tanhf(fv[0]);
        float s0 = fv[1], s1 = fv[2], s2 = fv[3];
        float m = fmaxf(s0, fmaxf(s1, s2));
        float e0 = expf(s0 - m), e1 = expf(s1 - m), e2 = expf(s2 - m);
        float inv = 1.f / (e0 + e1 + e2);
        g_shell[row * 3 + 0] = e0 * inv;
        g_shell[row * 3 + 1] = e1 * inv;
        g_shell[row * 3 + 2] = e2 * inv;
        float best = fv[4]; int bi = 0;
        #pragma unroll
        for (int c = 1; c < 32; c++) { float v = fv[4 + c]; if (v > best) { best = v; bi = c; } }
        g_cls[row] = bi;
        g_mass[row] = sp_(fv[36]) + 0.5f;
    }
}

__global__ void k_scores(const float* __restrict__ w_charge, const float* __restrict__ w_shell,
                         const float* __restrict__ w_distance, const float* __restrict__ w_mass,
                         const float* __restrict__ w_valence, const float* __restrict__ temperature) {
    int gi = blockIdx.x;
    int b  = gi >> 11, i = gi & 2047;
    int tid = threadIdx.x;
    __shared__ float sc[2048];
    __shared__ float cp[1024];
    __shared__ float red[256];
    for (int t = tid; t < 1024; t += 256) cp[t] = g_compat[t];

    float spc = sp_(w_charge[0]);
    float sps = sp_(w_shell[0]);
    float spd = sp_(w_distance[0]);
    float spm = sp_(w_mass[0]);
    float spv = sp_(w_valence[0]);
    float invt = 1.f / sp_(temperature[0]);

    const float* ch = g_charge + b * NN;
    const float* ms = g_mass + b * NN;
    const float* sh = g_shell + (size_t)b * NN * 3;
    const int*   cl = g_cls + b * NN;
    float ci = ch[i], mi = ms[i];
    float si0 = sh[i * 3], si1 = sh[i * 3 + 1], si2 = sh[i * 3 + 2];
    int cli = cl[i] * 32;
    __syncthreads();

    for (int j = tid; j < NN; j += 256) {
        if (j <= i) {
            float cj = ch[j], mj = ms[j];
            float d0 = fabsf(si0 - sh[j * 3]);
            float d1 = fabsf(si1 - sh[j * 3 + 1]);
            float d2 = fabsf(si2 - sh[j * 3 + 2]);
            float dist = (float)(i - j);
            float E = spc * ci * cj + sps * (d0 + d1 + d2)
                    - spd * __fdividef(1.f, 1.f + 0.1f * dist)
                    + spm * 0.1f * mi * mj - spv;
            sc[j] = -E * invt * cp[cli + cl[j]];
        } else {
            sc[j] = neg_inf_();
        }
    }
    __syncthreads();

    float lm = neg_inf_();
    for (int j = tid; j < NN; j += 256) lm = fmaxf(lm, sc[j]);
    red[tid] = lm; __syncthreads();
    for (int o = 128; o; o >>= 1) { if (tid < o) red[tid] = fmaxf(red[tid], red[tid + o]); __syncthreads(); }
    float mx = red[0]; __syncthreads();

    float ls = 0.f;
    for (int j = tid; j < NN; j += 256) { float e = expf(sc[j] - mx); sc[j] = e; ls += e; }
    red[tid] = ls; __syncthreads();
    for (int o = 128; o; o >>= 1) { if (tid < o) red[tid] += red[tid + o]; __syncthreads(); }
    float inv = 1.f / red[0];

    float* ar = g_attn + (size_t)gi * NN;
    for (int j = tid; j < NN; j += 256) ar[j] = sc[j] * inv;
}

// ---------------- fp32 tiled SGEMM (small fp32 GEMMs: Wcomb, xC) ----------------
__global__ __launch_bounds__(256)
void sgemm128(const float* __restrict__ A, const float* __restrict__ B,
              float* __restrict__ C, const float* __restrict__ bias,
              int M, int N, int K, int lda, int ldb, int ldc) {
    int rowStart = blockIdx.y * 128;
    int colStart = blockIdx.x * 128;

    __shared__ float As[16][128];
    __shared__ float Bs[16][128];
    int tid = threadIdx.x;
    int tx = tid & 15, ty = tid >> 4;
    float acc[8][8];
    #pragma unroll
    for (int i = 0; i < 8; i++)
        #pragma unroll
        for (int j = 0; j < 8; j++) acc[i][j] = 0.f;

    const bool n_vec = ((N & 3) == 0);

    for (int k0 = 0; k0 < K; k0 += 16) {
        #pragma unroll
        for (int l = 0; l < 2; l++) {
            int idx = tid + l * 256;
            int m = idx >> 2;
            int kq = (idx & 3) * 4;
            float4 v = *reinterpret_cast<const float4*>(
                A + (size_t)(rowStart + m) * lda + k0 + kq);
            As[kq + 0][m] = v.x; As[kq + 1][m] = v.y; As[kq + 2][m] = v.z; As[kq + 3][m] = v.w;
        }
        #pragma unroll
        for (int l = 0; l < 2; l++) {
            int idx = tid + l * 256;
            int kr = idx >> 5;
            int nq = (idx & 31) * 4;
            int col = colStart + nq;
            float4 v;
            if (n_vec && col + 3 < N) {
                v = *reinterpret_cast<const float4*>(B + (size_t)(k0 + kr) * ldb + col);
            } else {
                const float* bp = B + (size_t)(k0 + kr) * ldb;
                v.x = (col + 0 < N) ? bp[col + 0] : 0.f;
                v.y = (col + 1 < N) ? bp[col + 1] : 0.f;
                v.z = (col + 2 < N) ? bp[col + 2] : 0.f;
                v.w = (col + 3 < N) ? bp[col + 3] : 0.f;
            }
            *reinterpret_cast<float4*>(&Bs[kr][nq]) = v;
        }
        __syncthreads();
        #pragma unroll
        for (int kk = 0; kk < 16; kk++) {
            float ra[8], rb[8];
            *(float4*)&ra[0] = *(float4*)&As[kk][ty * 8];
            *(float4*)&ra[4] = *(float4*)&As[kk][ty * 8 + 4];
            *(float4*)&rb[0] = *(float4*)&Bs[kk][tx * 8];
            *(float4*)&rb[4] = *(float4*)&Bs[kk][tx * 8 + 4];
            #pragma unroll
            for (int i = 0; i < 8; i++)
                #pragma unroll
                for (int j = 0; j < 8; j++)
                    acc[i][j] += ra[i] * rb[j];
        }
        __syncthreads();
    }

    #pragma unroll
    for (int i = 0; i < 8; i++) {
        size_t row = rowStart + ty * 8 + i;
        #pragma unroll
        for (int j = 0; j < 8; j++) {
            int col = colStart + tx * 8 + j;
            if (col < N) {
                float v = acc[i][j] + (bias ? bias[col] : 0.f);
                C[row * (size_t)ldc + col] = v;
            }
        }
    }
}

// ---------------- host ----------------
extern "C" void kernel_launch(void* const* d_in, const int* in_sizes, int n_in,
                              void* d_out, int out_size) {
    const float* x         = (const float*)d_in[0];
    const float* W_sense   = (const float*)d_in[1];
    const float* b_sense   = (const float*)d_in[2];
    const float* W_ctx     = (const float*)d_in[3];
    const float* b_ctx     = (const float*)d_in[4];
    const float* W_sel     = (const float*)d_in[5];
    const float* b_sel     = (const float*)d_in[6];
    const float* W_charge  = (const float*)d_in[7];
    const float* b_charge  = (const float*)d_in[8];
    const float* W_shell   = (const float*)d_in[9];
    const float* b_shell   = (const float*)d_in[10];
    const float* W_class   = (const float*)d_in[11];
    const float* b_class   = (const float*)d_in[12];
    const float* W_mass    = (const float*)d_in[13];
    const float* b_mass    = (const float*)d_in[14];
    const float* compatL   = (const float*)d_in[17];
    const float* w_charge  = (const float*)d_in[18];
    const float* w_shell   = (const float*)d_in[19];
    const float* w_distance= (const float*)d_in[20];
    const float* w_mass    = (const float*)d_in[21];
    const float* w_valence = (const float*)d_in[22];
    const float* temperature=(const float*)d_in[23];
    const float* W_v       = (const float*)d_in[24];
    const float* b_v       = (const float*)d_in[25];
    const float* W_out     = (const float*)d_in[26];
    const float* b_out     = (const float*)d_in[27];
    float* out = (float*)d_out;

    void *p_senses, *p_xnew, *p_V, *p_attnout, *p_attn, *p_Wfeat, *p_Wcomb, *p_xC;
    cudaGetSymbolAddress(&p_senses, g_senses);
    cudaGetSymbolAddress(&p_xnew,   g_xnew);
    cudaGetSymbolAddress(&p_V,      g_V);
    cudaGetSymbolAddress(&p_attnout,g_attnout);
    cudaGetSymbolAddress(&p_attn,   g_attn);
    cudaGetSymbolAddress(&p_Wfeat,  g_Wfeat);
    cudaGetSymbolAddress(&p_Wcomb,  g_Wcomb);
    cudaGetSymbolAddress(&p_xC,     g_xC);

    const int HSMEM = 2 * 2 * 10240;   // 40960 bytes (SPLIT=2)
    cudaFuncSetAttribute(hgemm<2, false>, cudaFuncAttributeMaxDynamicSharedMemorySize, HSMEM);
    cudaFuncSetAttribute(hgemm<2, true>,  cudaFuncAttributeMaxDynamicSharedMemorySize, HSMEM);

    // ---- independent prep ----
    k_compat<<<1, 1024>>>(compatL);
    k_meanpart<<<dim3(4, 64), 256>>>(x);
    k_meanfin<<<16, 256>>>();
    k_ctxpart<<<dim3(4, 4, 8), 256>>>(W_ctx);
    k_ctxfin<<<16, 256>>>(b_ctx);
    k_selctx<<<dim3(3, 4), 128>>>(W_sel, b_sel);
    k_packfeat<<<(1024 * NF + 255) / 256, 256>>>(W_charge, b_charge, W_shell, b_shell,
                                                 W_class, b_class, W_mass, b_mass);

    // ---- fp32 feat path: Wcomb_s = W_sense_s @ Wfeat; bcomb; xC = x @ Wcomb ----
    for (int s = 0; s < 3; ++s)
        sgemm128<<<dim3(1, 8, 1), 256>>>(W_sense + s * 1024, (const float*)p_Wfeat,
                                         (float*)p_Wcomb + s * NF, nullptr,
                                         1024, NF, 1024, 3072, NF, 3 * NF);
    k_bcomb<<<1, 128>>>(b_sense);
    sgemm128<<<dim3(1, 64, 1), 256>>>(x, (const float*)p_Wcomb, (float*)p_xC, nullptr,
                                      ROWS, 3 * NF, 1024, 1024, 3 * NF, 3 * NF);

    // ---- senses = x @ W_sense + b_sense (8192x3072, K=1024), bf16 2-split ----
    hgemm<2, false><<<dim3(24, 64, 1), 256, HSMEM>>>(
        x, W_sense, (float*)p_senses, b_sense,
        1024, 1024, 3072, 3072, 0, 0, 0);

    // ---- combine -> xnew (+store sel weights) ----
    k_combine<<<ROWS, 256>>>(x, W_sel);

    // ---- per-row discrete/continuous features from fp32 path ----
    k_featrow<<<ROWS, 64>>>();

    // ---- scores + causal softmax -> attn ----
    k_scores<<<ROWS, 256>>>(w_charge, w_shell, w_distance, w_mass, w_valence, temperature);

    // ---- V = xnew @ W_v + b_v ----
    hgemm<2, false><<<dim3(8, 64, 1), 256, HSMEM>>>(
        (const float*)p_xnew, W_v, (float*)p_V, b_v,
        1024, 1024, 1024, 1024, 0, 0, 0);

    // ---- attnout = attn @ V (batched, causal k-limit) ----
    hgemm<2, true><<<dim3(8, 16, 4), 256, HSMEM>>>(
        (const float*)p_attn, (const float*)p_V, (float*)p_attnout, nullptr,
        NN, NN, 1024, 1024,
        (size_t)NN * NN, (size_t)NN * 1024, (size_t)NN * 1024);

    // ---- out = attnout @ W_out + b_out ----
    hgemm<2, false><<<dim3(8, 64, 1), 256, HSMEM>>>(
        (const float*)p_attnout, W_out, out, b_out,
        1024, 1024, 1024, 1024, 0, 0, 0);

    (void)in_sizes; (void)n_in; (void)out_size;
}

// round 5
// speedup vs baseline: 2.3967x; 1.5264x over previous
#include <cuda_runtime.h>
#include <cuda_fp16.h>
#include <math.h>
#include <stdint.h>
#include <cstdint>

// Problem constants
#define BB 4
#define NN 2048
#define DD 1024
#define ROWS 8192      // B*N
#define NF 37

// ---------------- device scratch (allocation-free) ----------------
__device__ float g_senses[8192 * 3072];
__device__ float g_V     [8192 * 1024];
__device__ float g_partial[4 * 16 * 1024];
__device__ float g_xmean [4 * 1024];
__device__ float g_ctx   [4 * 1024];
__device__ float g_selctx[4 * 3];
__device__ float g_selw  [8192 * 3];
__device__ float g_rowf  [8192 * 8];
__device__ float g_compat[1024];
__device__ float g_Wfeat [1024 * NF];
__device__ float g_bfeat [NF];
__device__ float g_Wcomb [1024 * 128];      // cols 111..127 stay zero
__device__ float g_bcomb [3 * NF];
__device__ float g_xC    [2 * 8192 * 128];  // two split-K slabs

// fp16 split planes
__device__ __half g_xA   [2 * 8192 * 1024];
__device__ __half g_WsT  [2 * 3072 * 1024];
__device__ __half g_xnA  [2 * 8192 * 1024];
__device__ __half g_WvT  [2 * 1024 * 1024];
__device__ __half g_VT   [2 * 4 * 1024 * 2048];
__device__ __half g_attnA[8192 * 2048];
__device__ __half g_aoA  [2 * 8192 * 1024];
__device__ __half g_WoT  [2 * 1024 * 1024];

__device__ __forceinline__ float sp_(float z) {
    return z > 20.f ? z : log1pf(expf(z));
}
__device__ __forceinline__ float neg_inf_() { return __int_as_float(0xff800000u); }

__device__ __forceinline__ uint32_t smem_u32(const void* p) {
    uint32_t a;
    asm("{ .reg .u64 t; cvta.to.shared.u64 t, %1; cvt.u32.u64 %0, t; }" : "=r"(a) : "l"(p));
    return a;
}
__device__ __forceinline__ void ldm_x4(uint32_t* r, uint32_t addr) {
    asm volatile("ldmatrix.sync.aligned.m8n8.x4.shared.b16 {%0,%1,%2,%3}, [%4];"
        : "=r"(r[0]), "=r"(r[1]), "=r"(r[2]), "=r"(r[3]) : "r"(addr));
}
__device__ __forceinline__ void mma_f16(float* c, const uint32_t* a, const uint32_t* b) {
    asm volatile("mma.sync.aligned.m16n8k16.row.col.f32.f16.f16.f32 "
        "{%0,%1,%2,%3}, {%4,%5,%6,%7}, {%8,%9}, {%0,%1,%2,%3};"
        : "+f"(c[0]), "+f"(c[1]), "+f"(c[2]), "+f"(c[3])
        : "r"(a[0]), "r"(a[1]), "r"(a[2]), "r"(a[3]), "r"(b[0]), "r"(b[1]));
}
__device__ __forceinline__ void cp_async16(uint32_t s, const void* g) {
    asm volatile("cp.async.cg.shared.global [%0], [%1], 16;" :: "r"(s), "l"(g));
}
__device__ __forceinline__ void cp_commit() { asm volatile("cp.async.commit_group;" ::: "memory"); }
template<int N> __device__ __forceinline__ void cp_wait() {
    asm volatile("cp.async.wait_group %0;" :: "n"(N) : "memory");
}

// ---------------- fp16 split GEMM (mma.sync, cp.async double-buffer) ----------
// C = A@B (+bias). A: SAP fp16 planes [M][K]; B: SBP planes [N][K] (pre-transposed).
// Terms (ci,cj) with ci+cj < max(SAP,SBP) accumulate in fp32.
// 128x128 CTA tile, BK=32, 256 thr = 8 warps (2Mx4N), 64x32/warp. Swizzled smem.
template<int SAP, int SBP, bool CAUSAL, int OUTM>
__global__ __launch_bounds__(256, 1)
void hgemm(const __half* __restrict__ A, const __half* __restrict__ B,
           void* __restrict__ Cv, const float* __restrict__ bias,
           int K, int lda, int ldb, int ldc,
           size_t psA, size_t psB, size_t psC,
           size_t sA, size_t sB, size_t sC) {
    extern __shared__ char smx[];
    A += (size_t)blockIdx.z * sA;
    B += (size_t)blockIdx.z * sB;
    const int rowStart = blockIdx.y * 128;
    const int colStart = blockIdx.x * 128;
    const int kmax = CAUSAL ? min(K, rowStart + 128) : K;
    const int tid = threadIdx.x, lane = tid & 31, wid = tid >> 5;
    const int mW = (wid >> 2) * 64, nW = (wid & 3) * 32;
    const uint32_t smBase = smem_u32(smx);
    constexpr uint32_t PL  = 8192u;
    constexpr uint32_t STG = (uint32_t)(SAP + SBP) * PL;
    constexpr int MAXS = (SAP > SBP) ? SAP : SBP;

    float acc[4][4][4];
    #pragma unroll
    for (int i = 0; i < 4; ++i)
        #pragma unroll
        for (int j = 0; j < 4; ++j)
            #pragma unroll
            for (int e = 0; e < 4; ++e) acc[i][j][e] = 0.f;

    // ldmatrix addressing (swizzle nibble constant across +16 rows)
    const int rA = mW + (lane & 15);
    const int rB = nW + ((lane >> 4) << 3) + (lane & 7);
    const uint32_t swA = (uint32_t)((rA >> 1) & 3);
    const uint32_t swB = (uint32_t)((rB >> 1) & 3);
    const uint32_t cA = (uint32_t)(lane >> 4);
    const uint32_t cB = (uint32_t)((lane >> 3) & 1);
    uint32_t aRow[4], bRow[2];
    #pragma unroll
    for (int am = 0; am < 4; ++am) aRow[am] = (uint32_t)(rA + am * 16) * 64u;
    #pragma unroll
    for (int np = 0; np < 2; ++np) bRow[np] = (uint32_t)(rB + np * 16) * 64u;

    const int r2 = tid >> 2, c2 = tid & 3;

    auto loadStage = [&](uint32_t st, int k0) {
        uint32_t sb = smBase + st * STG;
        #pragma unroll
        for (int p = 0; p < SAP; ++p) {
            const __half* gp = A + (size_t)p * psA + (size_t)rowStart * lda + k0;
            #pragma unroll
            for (int l = 0; l < 2; ++l) {
                int r = l * 64 + r2;
                uint32_t sa = sb + (uint32_t)p * PL + (uint32_t)r * 64u +
                              ((((uint32_t)c2) ^ (((uint32_t)r >> 1) & 3u)) << 4);
                cp_async16(sa, gp + (size_t)r * lda + c2 * 8);
            }
        }
        #pragma unroll
        for (int p = 0; p < SBP; ++p) {
            const __half* gp = B + (size_t)p * psB + (size_t)colStart * ldb + k0;
            #pragma unroll
            for (int l = 0; l < 2; ++l) {
                int r = l * 64 + r2;
                uint32_t sa = sb + (uint32_t)(SAP + p) * PL + (uint32_t)r * 64u +
                              ((((uint32_t)c2) ^ (((uint32_t)r >> 1) & 3u)) << 4);
                cp_async16(sa, gp + (size_t)r * ldb + c2 * 8);
            }
        }
    };

    const int nIter = kmax >> 5;
    loadStage(0, 0);
    cp_commit();
    for (int it = 0; it < nIter; ++it) {
        if (it + 1 < nIter) { loadStage((uint32_t)((it + 1) & 1), (it + 1) << 5); cp_commit(); cp_wait<1>(); }
        else cp_wait<0>();
        __syncthreads();
        uint32_t sb = smBase + (uint32_t)(it & 1) * STG;
        #pragma unroll
        for (int ks = 0; ks < 2; ++ks) {
            uint32_t af[SAP][4][4], bf[SBP][2][4];
            #pragma unroll
            for (int p = 0; p < SAP; ++p)
                #pragma unroll
                for (int am = 0; am < 4; ++am)
                    ldm_x4(af[p][am], sb + (uint32_t)p * PL + aRow[am] +
                           ((((uint32_t)(2 * ks) + cA) ^ swA) << 4));
            #pragma unroll
            for (int p = 0; p < SBP; ++p)
                #pragma unroll
                for (int np = 0; np < 2; ++np)
                    ldm_x4(bf[p][np], sb + (uint32_t)(SAP + p) * PL + bRow[np] +
                           ((((uint32_t)(2 * ks) + cB) ^ swB) << 4));
            #pragma unroll
            for (int ci = 0; ci < SAP; ++ci)
                #pragma unroll
                for (int cj = 0; cj < SBP; ++cj) {
                    if (ci + cj >= MAXS) continue;
                    #pragma unroll
                    for (int am = 0; am < 4; ++am)
                        #pragma unroll
                        for (int an = 0; an < 4; ++an)
                            mma_f16(acc[am][an], af[ci][am], &bf[cj][an >> 1][(an & 1) * 2]);
                }
        }
        __syncthreads();
    }

    #pragma unroll
    for (int am = 0; am < 4; ++am) {
        int row = rowStart + mW + am * 16 + (lane >> 2);
        #pragma unroll
        for (int an = 0; an < 4; ++an) {
            int col = colStart + nW + an * 8 + (lane & 3) * 2;
            float b0 = bias ? bias[col] : 0.f, b1 = bias ? bias[col + 1] : 0.f;
            float v0 = acc[am][an][0] + b0, v1 = acc[am][an][1] + b1;
            float v2 = acc[am][an][2] + b0, v3 = acc[am][an][3] + b1;
            if (OUTM == 0) {
                float* C = (float*)Cv + (size_t)blockIdx.z * sC;
                *(float2*)(C + (size_t)row * ldc + col) = make_float2(v0, v1);
                *(float2*)(C + (size_t)(row + 8) * ldc + col) = make_float2(v2, v3);
            } else {
                __half* Cp = (__half*)Cv + (size_t)blockIdx.z * sC;
                __half h0 = __float2half(v0), h1 = __float2half(v1);
                __half h2 = __float2half(v2), h3 = __float2half(v3);
                __half2 hh01; hh01.x = h0; hh01.y = h1;
                __half2 hh23; hh23.x = h2; hh23.y = h3;
                __half2 ll01; ll01.x = __float2half(v0 - __half2float(h0));
                              ll01.y = __float2half(v1 - __half2float(h1));
                __half2 ll23; ll23.x = __float2half(v2 - __half2float(h2));
                              ll23.y = __float2half(v3 - __half2float(h3));
                *(__half2*)(Cp + (size_t)row * ldc + col) = hh01;
                *(__half2*)(Cp + (size_t)(row + 8) * ldc + col) = hh23;
                *(__half2*)(Cp + psC + (size_t)row * ldc + col) = ll01;
                *(__half2*)(Cp + psC + (size_t)(row + 8) * ldc + col) = ll23;
            }
        }
    }
}

// ---------------- conversion kernels ----------------

// fp32 [M][K] -> two fp16 planes (same layout)
__global__ void k_splitA(const float* __restrict__ src, __half* __restrict__ dst, size_t ps) {
    size_t i = ((size_t)blockIdx.x * 256 + threadIdx.x) * 4;
    float4 v = *(const float4*)(src + i);
    __half h0 = __float2half(v.x), h1 = __float2half(v.y);
    __half h2 = __float2half(v.z), h3 = __float2half(v.w);
    __half2 a; a.x = h0; a.y = h1;
    __half2 b; b.x = h2; b.y = h3;
    *(__half2*)(dst + i) = a; *(__half2*)(dst + i + 2) = b;
    __half2 c; c.x = __float2half(v.x - __half2float(h0)); c.y = __float2half(v.y - __half2float(h1));
    __half2 d; d.x = __float2half(v.z - __half2float(h2)); d.y = __float2half(v.w - __half2float(h3));
    *(__half2*)(dst + ps + i) = c; *(__half2*)(dst + ps + i + 2) = d;
}

// transpose + split: dst[n][k] planes = src[k][n]
__global__ void k_convBt(const float* __restrict__ src, __half* __restrict__ dst,
                         int lds, int ldd, size_t ps, size_t sS, size_t sD) {
    src += (size_t)blockIdx.z * sS;
    dst += (size_t)blockIdx.z * sD;
    int n0 = blockIdx.x * 32, k0 = blockIdx.y * 32;
    __shared__ float t[32][33];
    int tx = threadIdx.x & 31, ty = threadIdx.x >> 5;
    #pragma unroll
    for (int l = 0; l < 4; ++l)
        t[ty + l * 8][tx] = src[(size_t)(k0 + ty + l * 8) * lds + n0 + tx];
    __syncthreads();
    #pragma unroll
    for (int l = 0; l < 4; ++l) {
        int n = ty + l * 8;
        float v = t[tx][n];
        __half h = __float2half(v);
        dst[(size_t)(n0 + n) * ldd + k0 + tx] = h;
        dst[ps + (size_t)(n0 + n) * ldd + k0 + tx] = __float2half(v - __half2float(h));
    }
}

// ---------------- small kernels ----------------

__global__ void k_compat(const float* __restrict__ L) {
    int t = threadIdx.x;
    int i = t >> 5, j = t & 31;
    float v = (L[i * 32 + j] + L[j * 32 + i]) * 0.5f;
    g_compat[t] = 1.f / (1.f + expf(-v));
}

__global__ void k_meanpart(const float* __restrict__ x) {
    int d  = blockIdx.x * 256 + threadIdx.x;
    int bc = blockIdx.y;
    int b  = bc >> 4, c = bc & 15;
    const float* xp = x + ((size_t)b * NN + c * 128) * DD + d;
    float s = 0.f;
    #pragma unroll 8
    for (int n = 0; n < 128; n++) s += xp[(size_t)n * DD];
    g_partial[bc * 1024 + d] = s;
}

__global__ void k_meanfin() {
    int idx = blockIdx.x * 256 + threadIdx.x;
    int b = idx >> 10, d = idx & 1023;
    float s = 0.f;
    #pragma unroll
    for (int c = 0; c < 16; c++) s += g_partial[(b * 16 + c) * 1024 + d];
    g_xmean[idx] = s * (1.f / (float)NN);
}

__global__ void k_ctxpart(const float* __restrict__ W_ctx) {
    int d = blockIdx.x * 256 + threadIdx.x;
    int b = blockIdx.y;
    int z = blockIdx.z;
    const float* xm = g_xmean + b * 1024 + z * 128;
    const float* W  = W_ctx + (size_t)(z * 128) * 1024 + d;
    float acc = 0.f;
    #pragma unroll 8
    for (int k = 0; k < 128; k++) acc += xm[k] * W[(size_t)k * 1024];
    g_partial[(z * 4 + b) * 1024 + d] = acc;
}

__global__ void k_ctxfin(const float* __restrict__ b_ctx) {
    int idx = blockIdx.x * 256 + threadIdx.x;
    int b = idx >> 10, d = idx & 1023;
    float s = 0.f;
    #pragma unroll
    for (int z = 0; z < 8; z++) s += g_partial[(z * 4 + b) * 1024 + d];
    g_ctx[idx] = s + b_ctx[d];
}

__global__ void k_selctx(const float* __restrict__ W_sel, const float* __restrict__ b_sel) {
    int s = blockIdx.x, b = blockIdx.y;
    int tid = threadIdx.x;
    const float* c = g_ctx + b * 1024;
    float p = 0.f;
    for (int k = tid; k < 1024; k += 128) p += c[k] * W_sel[(size_t)(1024 + k) * 3 + s];
    __shared__ float red[128];
    red[tid] = p; __syncthreads();
    for (int o = 64; o; o >>= 1) { if (tid < o) red[tid] += red[tid + o]; __syncthreads(); }
    if (tid == 0) g_selctx[b * 3 + s] = red[0] + b_sel[s];
}

__global__ void k_packfeat(const float* __restrict__ W_charge, const float* __restrict__ b_charge,
                           const float* __restrict__ W_shell,  const float* __restrict__ b_shell,
                           const float* __restrict__ W_class,  const float* __restrict__ b_class,
                           const float* __restrict__ W_mass,   const float* __restrict__ b_mass) {
    int idx = blockIdx.x * 256 + threadIdx.x;
    if (idx < 1024 * NF) {
        int k = idx / NF, c = idx % NF;
        float v;
        if (c == 0)       v = W_charge[k];
        else if (c <= 3)  v = W_shell[k * 3 + (c - 1)];
        else if (c <= 35) v = W_class[k * 32 + (c - 4)];
        else              v = W_mass[k];
        g_Wfeat[k * NF + c] = v;
    }
    if (idx < NF) {
        float v;
        if (idx == 0)       v = b_charge[0];
        else if (idx <= 3)  v = b_shell[idx - 1];
        else if (idx <= 35) v = b_class[idx - 4];
        else                v = b_mass[0];
        g_bfeat[idx] = v;
    }
}

__global__ void k_bcomb(const float* __restrict__ b_sense) {
    int c = blockIdx.x * 128 + threadIdx.x;
    if (c >= 3 * NF) return;
    int s = c / NF, cc = c % NF;
    float acc = 0.f;
    for (int k = 0; k < 1024; k++)
        acc += b_sense[s * 1024 + k] * g_Wfeat[k * NF + cc];
    g_bcomb[c] = acc;
}

// sel weights + combine senses -> xnew fp16 split planes; store weights
__global__ void k_combine(const float* __restrict__ x, const float* __restrict__ W_sel) {
    int row = blockIdx.x;
    int b   = row >> 11;
    int tid = threadIdx.x;
    const float* xr = x + (size_t)row * DD;
    float p0 = 0.f, p1 = 0.f, p2 = 0.f;
    for (int k = tid; k < 1024; k += 256) {
        float xv = xr[k];
        const float* w = W_sel + (size_t)k * 3;
        p0 += xv * w[0]; p1 += xv * w[1]; p2 += xv * w[2];
    }
    __shared__ float r0[256], r1[256], r2[256];
    r0[tid] = p0; r1[tid] = p1; r2[tid] = p2; __syncthreads();
    for (int o = 128; o; o >>= 1) {
        if (tid < o) { r0[tid] += r0[tid + o]; r1[tid] += r1[tid + o]; r2[tid] += r2[tid + o]; }
        __syncthreads();
    }
    float l0 = r0[0] + g_selctx[b * 3 + 0];
    float l1 = r1[0] + g_selctx[b * 3 + 1];
    float l2 = r2[0] + g_selctx[b * 3 + 2];
    float m  = fmaxf(l0, fmaxf(l1, l2));
    float e0 = expf(l0 - m), e1 = expf(l1 - m), e2 = expf(l2 - m);
    float inv = 1.f / (e0 + e1 + e2);
    float w0 = e0 * inv, w1 = e1 * inv, w2 = e2 * inv;
    if (tid == 0) {
        g_selw[row * 3 + 0] = w0;
        g_selw[row * 3 + 1] = w1;
        g_selw[row * 3 + 2] = w2;
    }

    const float4* S0 = (const float4*)(g_senses + (size_t)row * 3072);
    const float4* S1 = (const float4*)(g_senses + (size_t)row * 3072 + 1024);
    const float4* S2 = (const float4*)(g_senses + (size_t)row * 3072 + 2048);
    float4 a = S0[tid], bb = S1[tid], c = S2[tid];
    float o0 = w0 * a.x + w1 * bb.x + w2 * c.x;
    float o1 = w0 * a.y + w1 * bb.y + w2 * c.y;
    float o2 = w0 * a.z + w1 * bb.z + w2 * c.z;
    float o3 = w0 * a.w + w1 * bb.w + w2 * c.w;
    __half h0 = __float2half(o0), h1 = __float2half(o1);
    __half h2 = __float2half(o2), h3 = __float2half(o3);
    size_t off = (size_t)row * 1024 + tid * 4;
    const size_t PS = (size_t)8192 * 1024;
    __half2 hh01; hh01.x = h0; hh01.y = h1;
    __half2 hh23; hh23.x = h2; hh23.y = h3;
    *(__half2*)(g_xnA + off) = hh01;
    *(__half2*)(g_xnA + off + 2) = hh23;
    __half2 ll01; ll01.x = __float2half(o0 - __half2float(h0)); ll01.y = __float2half(o1 - __half2float(h1));
    __half2 ll23; ll23.x = __float2half(o2 - __half2float(h2)); ll23.y = __float2half(o3 - __half2float(h3));
    *(__half2*)(g_xnA + PS + off) = ll01;
    *(__half2*)(g_xnA + PS + off + 2) = ll23;
}

// per-row features (fp32 xC path) -> packed g_rowf
__global__ void k_featrow() {
    int row = blockIdx.x;
    int tid = threadIdx.x;   // 64
    __shared__ float fv[NF];
    if (tid < NF) {
        float w0 = g_selw[row * 3 + 0];
        float w1 = g_selw[row * 3 + 1];
        float w2 = g_selw[row * 3 + 2];
        const float* xc0 = g_xC + (size_t)row * 128;
        const float* xc1 = g_xC + (size_t)8192 * 128 + (size_t)row * 128;
        float v0 = xc0[tid]          + xc1[tid]          + g_bcomb[tid];
        float v1 = xc0[NF + tid]     + xc1[NF + tid]     + g_bcomb[NF + tid];
        float v2 = xc0[2 * NF + tid] + xc1[2 * NF + tid] + g_bcomb[2 * NF + tid];
        fv[tid] = g_bfeat[tid] + w0 * v0 + w1 * v1 + w2 * v2;
    }
    __syncthreads();
    if (tid == 0) {
        float* rf = g_rowf + (size_t)row * 8;
        rf[0] = tanhf(fv[0]);
        float s0 = fv[1], s1 = fv[2], s2 = fv[3];
        float m = fmaxf(s0, fmaxf(s1, s2));
        float e0 = expf(s0 - m), e1 = expf(s1 - m), e2 = expf(s2 - m);
        float inv = 1.f / (e0 + e1 + e2);
        rf[1] = e0 * inv; rf[2] = e1 * inv; rf[3] = e2 * inv;
        float best = fv[4]; int bi = 0;
        #pragma unroll
        for (int c = 1; c < 32; c++) { float v = fv[4 + c]; if (v > best) { best = v; bi = c; } }
        rf[4] = sp_(fv[36]) + 0.5f;
        rf[5] = __int_as_float(bi);
        rf[6] = 0.f; rf[7] = 0.f;
    }
}

// energy scores + causal softmax -> fp16 attn plane
__global__ void k_scores(const float* __restrict__ w_charge, const float* __restrict__ w_shell,
                         const float* __restrict__ w_distance, const float* __restrict__ w_mass,
                         const float* __restrict__ w_valence, const float* __restrict__ temperature) {
    int gi = blockIdx.x;
    int b  = gi >> 11, i = gi & 2047;
    int tid = threadIdx.x;
    __shared__ float sc[2048];
    __shared__ float cp[1024];
    __shared__ float red[256];
    for (int t = tid; t < 1024; t += 256) cp[t] = g_compat[t];

    float spc = sp_(w_charge[0]);
    float sps = sp_(w_shell[0]);
    float spd = sp_(w_distance[0]);
    float spm = sp_(w_mass[0]);
    float spv = sp_(w_valence[0]);
    float invt = 1.f / sp_(temperature[0]);

    const float4* rf = (const float4*)g_rowf;
    int base = b * NN;
    float4 m0 = rf[(size_t)(base + i) * 2];
    float4 m1 = rf[(size_t)(base + i) * 2 + 1];
    float ci = m0.x, si0 = m0.y, si1 = m0.z, si2 = m0.w;
    float mi = m1.x;
    int cli = __float_as_int(m1.y) * 32;
    __syncthreads();

    for (int j = tid; j < NN; j += 256) {
        if (j <= i) {
            float4 f0 = rf[(size_t)(base + j) * 2];
            float4 f1 = rf[(size_t)(base + j) * 2 + 1];
            float d0 = fabsf(si0 - f0.y);
            float d1 = fabsf(si1 - f0.z);
            float d2 = fabsf(si2 - f0.w);
            float dist = (float)(i - j);
            float E = spc * ci * f0.x + sps * (d0 + d1 + d2)
                    - spd * __fdividef(1.f, 1.f + 0.1f * dist)
                    + spm * 0.1f * mi * f1.x - spv;
            sc[j] = -E * invt * cp[cli + __float_as_int(f1.y)];
        } else {
            sc[j] = neg_inf_();
        }
    }
    __syncthreads();

    float lm = neg_inf_();
    for (int j = tid; j < NN; j += 256) lm = fmaxf(lm, sc[j]);
    red[tid] = lm; __syncthreads();
    for (int o = 128; o; o >>= 1) { if (tid < o) red[tid] = fmaxf(red[tid], red[tid + o]); __syncthreads(); }
    float mx = red[0]; __syncthreads();

    float ls = 0.f;
    for (int j = tid; j < NN; j += 256) { float e = expf(sc[j] - mx); sc[j] = e; ls += e; }
    red[tid] = ls; __syncthreads();
    for (int o = 128; o; o >>= 1) { if (tid < o) red[tid] += red[tid + o]; __syncthreads(); }
    float inv = 1.f / red[0];

    __half* ar = g_attnA + (size_t)gi * NN;
    for (int j = tid; j < NN; j += 256) ar[j] = __float2half(sc[j] * inv);
}

// ---------------- fp32 tiled SGEMM (feat path, with batch strides) -----------
__global__ __launch_bounds__(256)
void sgemm128(const float* __restrict__ A, const float* __restrict__ B,
              float* __restrict__ C, const float* __restrict__ bias,
              int M, int N, int K, int lda, int ldb, int ldc,
              size_t sA, size_t sB, size_t sC) {
    A += (size_t)blockIdx.z * sA;
    B += (size_t)blockIdx.z * sB;
    C += (size_t)blockIdx.z * sC;
    int rowStart = blockIdx.y * 128;
    int colStart = blockIdx.x * 128;

    __shared__ float As[16][128];
    __shared__ float Bs[16][128];
    int tid = threadIdx.x;
    int tx = tid & 15, ty = tid >> 4;
    float acc[8][8];
    #pragma unroll
    for (int i = 0; i < 8; i++)
        #pragma unroll
        for (int j = 0; j < 8; j++) acc[i][j] = 0.f;

    const bool n_vec = ((N & 3) == 0);

    for (int k0 = 0; k0 < K; k0 += 16) {
        #pragma unroll
        for (int l = 0; l < 2; l++) {
            int idx = tid + l * 256;
            int m = idx >> 2;
            int kq = (idx & 3) * 4;
            float4 v = *reinterpret_cast<const float4*>(
                A + (size_t)(rowStart + m) * lda + k0 + kq);
            As[kq + 0][m] = v.x; As[kq + 1][m] = v.y; As[kq + 2][m] = v.z; As[kq + 3][m] = v.w;
        }
        #pragma unroll
        for (int l = 0; l < 2; l++) {
            int idx = tid + l * 256;
            int kr = idx >> 5;
            int nq = (idx & 31) * 4;
            int col = colStart + nq;
            float4 v;
            if (n_vec && col + 3 < N) {
                v = *reinterpret_cast<const float4*>(B + (size_t)(k0 + kr) * ldb + col);
            } else {
                const float* bp = B + (size_t)(k0 + kr) * ldb;
                v.x = (col + 0 < N) ? bp[col + 0] : 0.f;
                v.y = (col + 1 < N) ? bp[col + 1] : 0.f;
                v.z = (col + 2 < N) ? bp[col + 2] : 0.f;
                v.w = (col + 3 < N) ? bp[col + 3] : 0.f;
            }
            *reinterpret_cast<float4*>(&Bs[kr][nq]) = v;
        }
        __syncthreads();
        #pragma unroll
        for (int kk = 0; kk < 16; kk++) {
            float ra[8], rb[8];
            *(float4*)&ra[0] = *(float4*)&As[kk][ty * 8];
            *(float4*)&ra[4] = *(float4*)&As[kk][ty * 8 + 4];
            *(float4*)&rb[0] = *(float4*)&Bs[kk][tx * 8];
            *(float4*)&rb[4] = *(float4*)&Bs[kk][tx * 8 + 4];
            #pragma unroll
            for (int i = 0; i < 8; i++)
                #pragma unroll
                for (int j = 0; j < 8; j++)
                    acc[i][j] += ra[i] * rb[j];
        }
        __syncthreads();
    }

    #pragma unroll
    for (int i = 0; i < 8; i++) {
        size_t row = rowStart + ty * 8 + i;
        #pragma unroll
        for (int j = 0; j < 8; j++) {
            int col = colStart + tx * 8 + j;
            if (col < N) {
                float v = acc[i][j] + (bias ? bias[col] : 0.f);
                C[row * (size_t)ldc + col] = v;
            }
        }
    }
}

// ---------------- host ----------------
extern "C" void kernel_launch(void* const* d_in, const int* in_sizes, int n_in,
                              void* d_out, int out_size) {
    const float* x         = (const float*)d_in[0];
    const float* W_sense   = (const float*)d_in[1];
    const float* b_sense   = (const float*)d_in[2];
    const float* W_ctx     = (const float*)d_in[3];
    const float* b_ctx     = (const float*)d_in[4];
    const float* W_sel     = (const float*)d_in[5];
    const float* b_sel     = (const float*)d_in[6];
    const float* W_charge  = (const float*)d_in[7];
    const float* b_charge  = (const float*)d_in[8];
    const float* W_shell   = (const float*)d_in[9];
    const float* b_shell   = (const float*)d_in[10];
    const float* W_class   = (const float*)d_in[11];
    const float* b_class   = (const float*)d_in[12];
    const float* W_mass    = (const float*)d_in[13];
    const float* b_mass    = (const float*)d_in[14];
    const float* compatL   = (const float*)d_in[17];
    const float* w_charge  = (const float*)d_in[18];
    const float* w_shell   = (const float*)d_in[19];
    const float* w_distance= (const float*)d_in[20];
    const float* w_mass    = (const float*)d_in[21];
    const float* w_valence = (const float*)d_in[22];
    const float* temperature=(const float*)d_in[23];
    const float* W_v       = (const float*)d_in[24];
    const float* b_v       = (const float*)d_in[25];
    const float* W_out     = (const float*)d_in[26];
    const float* b_out     = (const float*)d_in[27];
    float* out = (float*)d_out;

    void *p_senses, *p_V, *p_Wfeat, *p_Wcomb, *p_xC;
    void *p_xA, *p_WsT, *p_xnA, *p_WvT, *p_VT, *p_attnA, *p_aoA, *p_WoT;
    cudaGetSymbolAddress(&p_senses, g_senses);
    cudaGetSymbolAddress(&p_V,      g_V);
    cudaGetSymbolAddress(&p_Wfeat,  g_Wfeat);
    cudaGetSymbolAddress(&p_Wcomb,  g_Wcomb);
    cudaGetSymbolAddress(&p_xC,     g_xC);
    cudaGetSymbolAddress(&p_xA,     g_xA);
    cudaGetSymbolAddress(&p_WsT,    g_WsT);
    cudaGetSymbolAddress(&p_xnA,    g_xnA);
    cudaGetSymbolAddress(&p_WvT,    g_WvT);
    cudaGetSymbolAddress(&p_VT,     g_VT);
    cudaGetSymbolAddress(&p_attnA,  g_attnA);
    cudaGetSymbolAddress(&p_aoA,    g_aoA);
    cudaGetSymbolAddress(&p_WoT,    g_WoT);

    const int SM22 = 2 * 4 * 8192;   // 65536
    const int SM12 = 2 * 3 * 8192;   // 49152
    cudaFuncSetAttribute(hgemm<2, 2, false, 0>, cudaFuncAttributeMaxDynamicSharedMemorySize, SM22);
    cudaFuncSetAttribute(hgemm<1, 2, true, 1>,  cudaFuncAttributeMaxDynamicSharedMemorySize, SM12);

    const size_t PSxA = (size_t)8192 * 1024;
    const size_t PSWs = (size_t)3072 * 1024;
    const size_t PSWv = (size_t)1024 * 1024;
    const size_t PSVT = (size_t)4 * 1024 * 2048;
    const size_t PSao = (size_t)8192 * 1024;
    const size_t PSWo = (size_t)1024 * 1024;

    // ---- prep ----
    k_compat<<<1, 1024>>>(compatL);
    k_meanpart<<<dim3(4, 64), 256>>>(x);
    k_meanfin<<<16, 256>>>();
    k_ctxpart<<<dim3(4, 4, 8), 256>>>(W_ctx);
    k_ctxfin<<<16, 256>>>(b_ctx);
    k_selctx<<<dim3(3, 4), 128>>>(W_sel, b_sel);
    k_packfeat<<<(1024 * NF + 255) / 256, 256>>>(W_charge, b_charge, W_shell, b_shell,
                                                 W_class, b_class, W_mass, b_mass);
    // Wcomb (batched over 3 senses): C[i][z*37+c] = sum_j Ws[i][z*1024+j] Wfeat[j][c]
    sgemm128<<<dim3(1, 8, 3), 256>>>(W_sense, (const float*)p_Wfeat, (float*)p_Wcomb, nullptr,
                                     1024, NF, 1024, 3072, NF, 128,
                                     1024, 0, NF);
    k_bcomb<<<1, 128>>>(b_sense);
    // xC = x @ Wcomb, split-K into 2 slabs
    sgemm128<<<dim3(1, 64, 2), 256>>>(x, (const float*)p_Wcomb, (float*)p_xC, nullptr,
                                      ROWS, 128, 512, 1024, 128, 128,
                                      512, (size_t)512 * 128, (size_t)8192 * 128);

    // ---- operand conversion ----
    k_splitA<<<8192, 256>>>(x, (__half*)p_xA, PSxA);
    k_convBt<<<dim3(96, 32, 1), 256>>>(W_sense, (__half*)p_WsT, 3072, 1024, PSWs, 0, 0);

    // ---- senses = x @ W_sense + b_sense ----
    hgemm<2, 2, false, 0><<<dim3(24, 64, 1), 256, SM22>>>(
        (const __half*)p_xA, (const __half*)p_WsT, p_senses, b_sense,
        1024, 1024, 1024, 3072, PSxA, PSWs, 0, 0, 0, 0);

    // ---- combine -> xnew planes (+sel weights) ----
    k_combine<<<ROWS, 256>>>(x, W_sel);

    // ---- per-row features ----
    k_featrow<<<ROWS, 64>>>();

    // ---- scores + causal softmax -> fp16 attn ----
    k_scores<<<ROWS, 256>>>(w_charge, w_shell, w_distance, w_mass, w_valence, temperature);

    // ---- V = xnew @ W_v + b_v (fp32 out for transpose) ----
    k_convBt<<<dim3(32, 32, 1), 256>>>(W_v, (__half*)p_WvT, 1024, 1024, PSWv, 0, 0);
    hgemm<2, 2, false, 0><<<dim3(8, 64, 1), 256, SM22>>>(
        (const __half*)p_xnA, (const __half*)p_WvT, p_V, b_v,
        1024, 1024, 1024, 1024, PSxA, PSWv, 0, 0, 0, 0);

    // ---- V -> transposed split planes ----
    k_convBt<<<dim3(32, 64, 4), 256>>>((const float*)p_V, (__half*)p_VT, 1024, 2048, PSVT,
                                       (size_t)2048 * 1024, (size_t)1024 * 2048);

    // ---- attnout = attn @ V (causal, batched) -> split planes ----
    hgemm<1, 2, true, 1><<<dim3(8, 16, 4), 256, SM12>>>(
        (const __half*)p_attnA, (const __half*)p_VT, p_aoA, nullptr,
        2048, 2048, 2048, 1024, 0, PSVT, PSao,
        (size_t)2048 * 2048, (size_t)1024 * 2048, (size_t)2048 * 1024);

    // ---- out = attnout @ W_out + b_out ----
    k_convBt<<<dim3(32, 32, 1), 256>>>(W_out, (__half*)p_WoT, 1024, 1024, PSWo, 0, 0);
    hgemm<2, 2, false, 0><<<dim3(8, 64, 1), 256, SM22>>>(
        (const __half*)p_aoA, (const __half*)p_WoT, out, b_out,
        1024, 1024, 1024, 1024, PSao, PSWo, 0, 0, 0, 0);

    (void)in_sizes; (void)n_in; (void)out_size;
}

// round 6
// speedup vs baseline: 2.5948x; 1.0827x over previous
#include <cuda_runtime.h>
#include <cuda_fp16.h>
#include <math.h>
#include <stdint.h>
#include <cstdint>

// Problem constants
#define BB 4
#define NN 2048
#define DD 1024
#define ROWS 8192      // B*N
#define NF 37

// ---------------- device scratch (allocation-free) ----------------
__device__ float g_senses[8192 * 3072];
__device__ float g_V     [8192 * 1024];
__device__ float g_partial[4 * 16 * 1024];
__device__ float g_xmean [4 * 1024];
__device__ float g_ctx   [4 * 1024];
__device__ float g_selctx[4 * 3];
__device__ float g_selw  [8192 * 3];
__device__ float g_rowf  [8192 * 8];
__device__ float g_compat[1024];
__device__ float g_Wfeat [1024 * NF];
__device__ float g_bfeat [NF];
__device__ float g_Wcomb [1024 * 128];
__device__ float g_bcomb [3 * NF];
__device__ float g_xC    [2 * 8192 * 128];

// fp16 split planes
__device__ __half g_xA   [2 * 8192 * 1024];
__device__ __half g_WsT  [2 * 3072 * 1024];
__device__ __half g_xnA  [2 * 8192 * 1024];
__device__ __half g_WvT  [2 * 1024 * 1024];
__device__ __half g_VT   [2 * 4 * 1024 * 2048];
__device__ __half g_attnA[8192 * 2048];
__device__ __half g_aoA  [2 * 8192 * 1024];
__device__ __half g_WoT  [2 * 1024 * 1024];

__device__ __forceinline__ float sp_(float z) {
    return z > 20.f ? z : log1pf(expf(z));
}
__device__ __forceinline__ float neg_inf_() { return __int_as_float(0xff800000u); }

__device__ __forceinline__ uint32_t smem_u32(const void* p) {
    uint32_t a;
    asm("{ .reg .u64 t; cvta.to.shared.u64 t, %1; cvt.u32.u64 %0, t; }" : "=r"(a) : "l"(p));
    return a;
}
__device__ __forceinline__ void ldm_x4(uint32_t* r, uint32_t addr) {
    asm volatile("ldmatrix.sync.aligned.m8n8.x4.shared.b16 {%0,%1,%2,%3}, [%4];"
        : "=r"(r[0]), "=r"(r[1]), "=r"(r[2]), "=r"(r[3]) : "r"(addr));
}
__device__ __forceinline__ void mma_f16(float* c, const uint32_t* a, const uint32_t* b) {
    asm volatile("mma.sync.aligned.m16n8k16.row.col.f32.f16.f16.f32 "
        "{%0,%1,%2,%3}, {%4,%5,%6,%7}, {%8,%9}, {%0,%1,%2,%3};"
        : "+f"(c[0]), "+f"(c[1]), "+f"(c[2]), "+f"(c[3])
        : "r"(a[0]), "r"(a[1]), "r"(a[2]), "r"(a[3]), "r"(b[0]), "r"(b[1]));
}
__device__ __forceinline__ void cp_async16(uint32_t s, const void* g) {
    asm volatile("cp.async.cg.shared.global [%0], [%1], 16;" :: "r"(s), "l"(g));
}
__device__ __forceinline__ void cp_commit() { asm volatile("cp.async.commit_group;" ::: "memory"); }
template<int N> __device__ __forceinline__ void cp_wait() {
    asm volatile("cp.async.wait_group %0;" :: "n"(N) : "memory");
}

// ---------------- fp16 split GEMM (mma.sync, 3-stage cp.async pipeline) ------
// C = A@B (+bias). A: SAP fp16 planes [M][K]; B: SBP planes [N][K] (pre-transposed).
// Terms (ci,cj) with ci+cj < max(SAP,SBP) accumulate in fp32.
// 128x128 CTA tile, BK=32, 256 thr = 8 warps (2Mx4N), 64x32/warp, 2 CTAs/SM.
template<int SAP, int SBP, bool CAUSAL, int OUTM>
__global__ __launch_bounds__(256, 2)
void hgemm(const __half* __restrict__ A, const __half* __restrict__ B,
           void* __restrict__ Cv, const float* __restrict__ bias,
           int K, int lda, int ldb, int ldc,
           size_t psA, size_t psB, size_t psC,
           size_t sA, size_t sB, size_t sC) {
    extern __shared__ char smx[];
    A += (size_t)blockIdx.z * sA;
    B += (size_t)blockIdx.z * sB;
    const int by = CAUSAL ? (gridDim.y - 1 - blockIdx.y) : blockIdx.y;
    const int rowStart = by * 128;
    const int colStart = blockIdx.x * 128;
    const int kmax = CAUSAL ? min(K, rowStart + 128) : K;
    const int tid = threadIdx.x, lane = tid & 31, wid = tid >> 5;
    const int mW = (wid >> 2) * 64, nW = (wid & 3) * 32;
    const uint32_t smBase = smem_u32(smx);
    constexpr uint32_t PL  = 8192u;
    constexpr uint32_t STG = (uint32_t)(SAP + SBP) * PL;
    constexpr int MAXS = (SAP > SBP) ? SAP : SBP;

    float acc[4][4][4];
    #pragma unroll
    for (int i = 0; i < 4; ++i)
        #pragma unroll
        for (int j = 0; j < 4; ++j)
            #pragma unroll
            for (int e = 0; e < 4; ++e) acc[i][j][e] = 0.f;

    const int rA = mW + (lane & 15);
    const int rB = nW + ((lane >> 4) << 3) + (lane & 7);
    const uint32_t swA = (uint32_t)((rA >> 1) & 3);
    const uint32_t swB = (uint32_t)((rB >> 1) & 3);
    const uint32_t cA = (uint32_t)(lane >> 4);
    const uint32_t cB = (uint32_t)((lane >> 3) & 1);
    uint32_t aRow[4], bRow[2];
    #pragma unroll
    for (int am = 0; am < 4; ++am) aRow[am] = (uint32_t)(rA + am * 16) * 64u;
    #pragma unroll
    for (int np = 0; np < 2; ++np) bRow[np] = (uint32_t)(rB + np * 16) * 64u;

    const int r2 = tid >> 2, c2 = tid & 3;

    auto loadStage = [&](int st, int k0) {
        uint32_t sb = smBase + (uint32_t)st * STG;
        #pragma unroll
        for (int p = 0; p < SAP; ++p) {
            const __half* gp = A + (size_t)p * psA + (size_t)rowStart * lda + k0;
            #pragma unroll
            for (int l = 0; l < 2; ++l) {
                int r = l * 64 + r2;
                uint32_t sa = sb + (uint32_t)p * PL + (uint32_t)r * 64u +
                              ((((uint32_t)c2) ^ (((uint32_t)r >> 1) & 3u)) << 4);
                cp_async16(sa, gp + (size_t)r * lda + c2 * 8);
            }
        }
        #pragma unroll
        for (int p = 0; p < SBP; ++p) {
            const __half* gp = B + (size_t)p * psB + (size_t)colStart * ldb + k0;
            #pragma unroll
            for (int l = 0; l < 2; ++l) {
                int r = l * 64 + r2;
                uint32_t sa = sb + (uint32_t)(SAP + p) * PL + (uint32_t)r * 64u +
                              ((((uint32_t)c2) ^ (((uint32_t)r >> 1) & 3u)) << 4);
                cp_async16(sa, gp + (size_t)r * ldb + c2 * 8);
            }
        }
    };

    const int nIter = kmax >> 5;
    // prologue: stages 0,1
    if (0 < nIter) loadStage(0, 0);
    cp_commit();
    if (1 < nIter) loadStage(1, 32);
    cp_commit();

    for (int it = 0; it < nIter; ++it) {
        if (it + 1 < nIter) cp_wait<1>(); else cp_wait<0>();
        __syncthreads();
        int nl = it + 2;
        if (nl < nIter) loadStage(nl - (nl / 3) * 3, nl << 5);
        cp_commit();

        uint32_t sb = smBase + (uint32_t)(it - (it / 3) * 3) * STG;
        #pragma unroll
        for (int ks = 0; ks < 2; ++ks) {
            uint32_t af[SAP][4][4], bf[SBP][2][4];
            #pragma unroll
            for (int p = 0; p < SAP; ++p)
                #pragma unroll
                for (int am = 0; am < 4; ++am)
                    ldm_x4(af[p][am], sb + (uint32_t)p * PL + aRow[am] +
                           ((((uint32_t)(2 * ks) + cA) ^ swA) << 4));
            #pragma unroll
            for (int p = 0; p < SBP; ++p)
                #pragma unroll
                for (int np = 0; np < 2; ++np)
                    ldm_x4(bf[p][np], sb + (uint32_t)(SAP + p) * PL + bRow[np] +
                           ((((uint32_t)(2 * ks) + cB) ^ swB) << 4));
            #pragma unroll
            for (int ci = 0; ci < SAP; ++ci)
                #pragma unroll
                for (int cj = 0; cj < SBP; ++cj) {
                    if (ci + cj >= MAXS) continue;
                    #pragma unroll
                    for (int am = 0; am < 4; ++am)
                        #pragma unroll
                        for (int an = 0; an < 4; ++an)
                            mma_f16(acc[am][an], af[ci][am], &bf[cj][an >> 1][(an & 1) * 2]);
                }
        }
    }

    #pragma unroll
    for (int am = 0; am < 4; ++am) {
        int row = rowStart + mW + am * 16 + (lane >> 2);
        #pragma unroll
        for (int an = 0; an < 4; ++an) {
            int col = colStart + nW + an * 8 + (lane & 3) * 2;
            float b0 = bias ? bias[col] : 0.f, b1 = bias ? bias[col + 1] : 0.f;
            float v0 = acc[am][an][0] + b0, v1 = acc[am][an][1] + b1;
            float v2 = acc[am][an][2] + b0, v3 = acc[am][an][3] + b1;
            if (OUTM == 0) {
                float* C = (float*)Cv + (size_t)blockIdx.z * sC;
                *(float2*)(C + (size_t)row * ldc + col) = make_float2(v0, v1);
                *(float2*)(C + (size_t)(row + 8) * ldc + col) = make_float2(v2, v3);
            } else {
                __half* Cp = (__half*)Cv + (size_t)blockIdx.z * sC;
                __half h0 = __float2half(v0), h1 = __float2half(v1);
                __half h2 = __float2half(v2), h3 = __float2half(v3);
                __half2 hh01; hh01.x = h0; hh01.y = h1;
                __half2 hh23; hh23.x = h2; hh23.y = h3;
                __half2 ll01; ll01.x = __float2half(v0 - __half2float(h0));
                              ll01.y = __float2half(v1 - __half2float(h1));
                __half2 ll23; ll23.x = __float2half(v2 - __half2float(h2));
                              ll23.y = __float2half(v3 - __half2float(h3));
                *(__half2*)(Cp + (size_t)row * ldc + col) = hh01;
                *(__half2*)(Cp + (size_t)(row + 8) * ldc + col) = hh23;
                *(__half2*)(Cp + psC + (size_t)row * ldc + col) = ll01;
                *(__half2*)(Cp + psC + (size_t)(row + 8) * ldc + col) = ll23;
            }
        }
    }
}

// ---------------- conversion kernels ----------------

__global__ void k_splitA(const float* __restrict__ src, __half* __restrict__ dst, size_t ps) {
    size_t i = ((size_t)blockIdx.x * 256 + threadIdx.x) * 4;
    float4 v = *(const float4*)(src + i);
    __half h0 = __float2half(v.x), h1 = __float2half(v.y);
    __half h2 = __float2half(v.z), h3 = __float2half(v.w);
    __half2 a; a.x = h0; a.y = h1;
    __half2 b; b.x = h2; b.y = h3;
    *(__half2*)(dst + i) = a; *(__half2*)(dst + i + 2) = b;
    __half2 c; c.x = __float2half(v.x - __half2float(h0)); c.y = __float2half(v.y - __half2float(h1));
    __half2 d; d.x = __float2half(v.z - __half2float(h2)); d.y = __float2half(v.w - __half2float(h3));
    *(__half2*)(dst + ps + i) = c; *(__half2*)(dst + ps + i + 2) = d;
}

__global__ void k_convBt(const float* __restrict__ src, __half* __restrict__ dst,
                         int lds, int ldd, size_t ps, size_t sS, size_t sD) {
    src += (size_t)blockIdx.z * sS;
    dst += (size_t)blockIdx.z * sD;
    int n0 = blockIdx.x * 32, k0 = blockIdx.y * 32;
    __shared__ float t[32][33];
    int tx = threadIdx.x & 31, ty = threadIdx.x >> 5;
    #pragma unroll
    for (int l = 0; l < 4; ++l)
        t[ty + l * 8][tx] = src[(size_t)(k0 + ty + l * 8) * lds + n0 + tx];
    __syncthreads();
    #pragma unroll
    for (int l = 0; l < 4; ++l) {
        int n = ty + l * 8;
        float v = t[tx][n];
        __half h = __float2half(v);
        dst[(size_t)(n0 + n) * ldd + k0 + tx] = h;
        dst[ps + (size_t)(n0 + n) * ldd + k0 + tx] = __float2half(v - __half2float(h));
    }
}

// ---------------- small kernels ----------------

__global__ void k_compat(const float* __restrict__ L) {
    int t = threadIdx.x;
    int i = t >> 5, j = t & 31;
    float v = (L[i * 32 + j] + L[j * 32 + i]) * 0.5f;
    g_compat[t] = 1.f / (1.f + expf(-v));
}

__global__ void k_meanpart(const float* __restrict__ x) {
    int d  = blockIdx.x * 256 + threadIdx.x;
    int bc = blockIdx.y;
    int b  = bc >> 4, c = bc & 15;
    const float* xp = x + ((size_t)b * NN + c * 128) * DD + d;
    float s = 0.f;
    #pragma unroll 8
    for (int n = 0; n < 128; n++) s += xp[(size_t)n * DD];
    g_partial[bc * 1024 + d] = s;
}

__global__ void k_meanfin() {
    int idx = blockIdx.x * 256 + threadIdx.x;
    int b = idx >> 10, d = idx & 1023;
    float s = 0.f;
    #pragma unroll
    for (int c = 0; c < 16; c++) s += g_partial[(b * 16 + c) * 1024 + d];
    g_xmean[idx] = s * (1.f / (float)NN);
}

// ctx partials: W_ctx read once, 4 batch accumulators per thread
__global__ void k_ctxpart(const float* __restrict__ W_ctx) {
    int d = blockIdx.x * 256 + threadIdx.x;  // 4 x-blocks
    int z = blockIdx.z;                      // 8
    const float* W = W_ctx + (size_t)(z * 128) * 1024 + d;
    const float* m0 = g_xmean + 0 * 1024 + z * 128;
    const float* m1 = g_xmean + 1 * 1024 + z * 128;
    const float* m2 = g_xmean + 2 * 1024 + z * 128;
    const float* m3 = g_xmean + 3 * 1024 + z * 128;
    float a0 = 0.f, a1 = 0.f, a2 = 0.f, a3 = 0.f;
    #pragma unroll 4
    for (int k = 0; k < 128; k++) {
        float w = W[(size_t)k * 1024];
        a0 += m0[k] * w; a1 += m1[k] * w; a2 += m2[k] * w; a3 += m3[k] * w;
    }
    g_partial[(z * 4 + 0) * 1024 + d] = a0;
    g_partial[(z * 4 + 1) * 1024 + d] = a1;
    g_partial[(z * 4 + 2) * 1024 + d] = a2;
    g_partial[(z * 4 + 3) * 1024 + d] = a3;
}

__global__ void k_ctxfin(const float* __restrict__ b_ctx) {
    int idx = blockIdx.x * 256 + threadIdx.x;
    int b = idx >> 10, d = idx & 1023;
    float s = 0.f;
    #pragma unroll
    for (int z = 0; z < 8; z++) s += g_partial[(z * 4 + b) * 1024 + d];
    g_ctx[idx] = s + b_ctx[d];
}

__global__ void k_selctx(const float* __restrict__ W_sel, const float* __restrict__ b_sel) {
    int s = blockIdx.x, b = blockIdx.y;
    int tid = threadIdx.x;
    const float* c = g_ctx + b * 1024;
    float p = 0.f;
    for (int k = tid; k < 1024; k += 128) p += c[k] * W_sel[(size_t)(1024 + k) * 3 + s];
    __shared__ float red[128];
    red[tid] = p; __syncthreads();
    for (int o = 64; o; o >>= 1) { if (tid < o) red[tid] += red[tid + o]; __syncthreads(); }
    if (tid == 0) g_selctx[b * 3 + s] = red[0] + b_sel[s];
}

__global__ void k_packfeat(const float* __restrict__ W_charge, const float* __restrict__ b_charge,
                           const float* __restrict__ W_shell,  const float* __restrict__ b_shell,
                           const float* __restrict__ W_class,  const float* __restrict__ b_class,
                           const float* __restrict__ W_mass,   const float* __restrict__ b_mass) {
    int idx = blockIdx.x * 256 + threadIdx.x;
    if (idx < 1024 * NF) {
        int k = idx / NF, c = idx % NF;
        float v;
        if (c == 0)       v = W_charge[k];
        else if (c <= 3)  v = W_shell[k * 3 + (c - 1)];
        else if (c <= 35) v = W_class[k * 32 + (c - 4)];
        else              v = W_mass[k];
        g_Wfeat[k * NF + c] = v;
    }
    if (idx < NF) {
        float v;
        if (idx == 0)       v = b_charge[0];
        else if (idx <= 3)  v = b_shell[idx - 1];
        else if (idx <= 35) v = b_class[idx - 4];
        else                v = b_mass[0];
        g_bfeat[idx] = v;
    }
}

__global__ void k_bcomb(const float* __restrict__ b_sense) {
    int c = blockIdx.x * 128 + threadIdx.x;
    if (c >= 3 * NF) return;
    int s = c / NF, cc = c % NF;
    float acc = 0.f;
    for (int k = 0; k < 1024; k++)
        acc += b_sense[s * 1024 + k] * g_Wfeat[k * NF + cc];
    g_bcomb[c] = acc;
}

// sel weights + combine senses -> xnew fp16 split planes; store weights
__global__ void k_combine(const float* __restrict__ x, const float* __restrict__ W_sel) {
    int row = blockIdx.x;
    int b   = row >> 11;
    int tid = threadIdx.x;
    const float* xr = x + (size_t)row * DD;
    float p0 = 0.f, p1 = 0.f, p2 = 0.f;
    for (int k = tid; k < 1024; k += 256) {
        float xv = xr[k];
        const float* w = W_sel + (size_t)k * 3;
        p0 += xv * w[0]; p1 += xv * w[1]; p2 += xv * w[2];
    }
    __shared__ float r0[256], r1[256], r2[256];
    r0[tid] = p0; r1[tid] = p1; r2[tid] = p2; __syncthreads();
    for (int o = 128; o; o >>= 1) {
        if (tid < o) { r0[tid] += r0[tid + o]; r1[tid] += r1[tid + o]; r2[tid] += r2[tid + o]; }
        __syncthreads();
    }
    float l0 = r0[0] + g_selctx[b * 3 + 0];
    float l1 = r1[0] + g_selctx[b * 3 + 1];
    float l2 = r2[0] + g_selctx[b * 3 + 2];
    float m  = fmaxf(l0, fmaxf(l1, l2));
    float e0 = expf(l0 - m), e1 = expf(l1 - m), e2 = expf(l2 - m);
    float inv = 1.f / (e0 + e1 + e2);
    float w0 = e0 * inv, w1 = e1 * inv, w2 = e2 * inv;
    if (tid == 0) {
        g_selw[row * 3 + 0] = w0;
        g_selw[row * 3 + 1] = w1;
        g_selw[row * 3 + 2] = w2;
    }

    const float4* S0 = (const float4*)(g_senses + (size_t)row * 3072);
    const float4* S1 = (const float4*)(g_senses + (size_t)row * 3072 + 1024);
    const float4* S2 = (const float4*)(g_senses + (size_t)row * 3072 + 2048);
    float4 a = S0[tid], bb = S1[tid], c = S2[tid];
    float o0 = w0 * a.x + w1 * bb.x + w2 * c.x;
    float o1 = w0 * a.y + w1 * bb.y + w2 * c.y;
    float o2 = w0 * a.z + w1 * bb.z + w2 * c.z;
    float o3 = w0 * a.w + w1 * bb.w + w2 * c.w;
    __half h0 = __float2half(o0), h1 = __float2half(o1);
    __half h2 = __float2half(o2), h3 = __float2half(o3);
    size_t off = (size_t)row * 1024 + tid * 4;
    const size_t PS = (size_t)8192 * 1024;
    __half2 hh01; hh01.x = h0; hh01.y = h1;
    __half2 hh23; hh23.x = h2; hh23.y = h3;
    *(__half2*)(g_xnA + off) = hh01;
    *(__half2*)(g_xnA + off + 2) = hh23;
    __half2 ll01; ll01.x = __float2half(o0 - __half2float(h0)); ll01.y = __float2half(o1 - __half2float(h1));
    __half2 ll23; ll23.x = __float2half(o2 - __half2float(h2)); ll23.y = __float2half(o3 - __half2float(h3));
    *(__half2*)(g_xnA + PS + off) = ll01;
    *(__half2*)(g_xnA + PS + off + 2) = ll23;
}

// per-row features (fp32 xC path) -> packed g_rowf
__global__ void k_featrow() {
    int row = blockIdx.x;
    int tid = threadIdx.x;   // 64
    __shared__ float fv[NF];
    if (tid < NF) {
        float w0 = g_selw[row * 3 + 0];
        float w1 = g_selw[row * 3 + 1];
        float w2 = g_selw[row * 3 + 2];
        const float* xc0 = g_xC + (size_t)row * 128;
        const float* xc1 = g_xC + (size_t)8192 * 128 + (size_t)row * 128;
        float v0 = xc0[tid]          + xc1[tid]          + g_bcomb[tid];
        float v1 = xc0[NF + tid]     + xc1[NF + tid]     + g_bcomb[NF + tid];
        float v2 = xc0[2 * NF + tid] + xc1[2 * NF + tid] + g_bcomb[2 * NF + tid];
        fv[tid] = g_bfeat[tid] + w0 * v0 + w1 * v1 + w2 * v2;
    }
    __syncthreads();
    if (tid == 0) {
        float* rf = g_rowf + (size_t)row * 8;
        rf[0] = tanhf(fv[0]);
        float s0 = fv[1], s1 = fv[2], s2 = fv[3];
        float m = fmaxf(s0, fmaxf(s1, s2));
        float e0 = expf(s0 - m), e1 = expf(s1 - m), e2 = expf(s2 - m);
        float inv = 1.f / (e0 + e1 + e2);
        rf[1] = e0 * inv; rf[2] = e1 * inv; rf[3] = e2 * inv;
        float best = fv[4]; int bi = 0;
        #pragma unroll
        for (int c = 1; c < 32; c++) { float v = fv[4 + c]; if (v > best) { best = v; bi = c; } }
        rf[4] = sp_(fv[36]) + 0.5f;
        rf[5] = __int_as_float(bi);
        rf[6] = 0.f; rf[7] = 0.f;
    }
}

// energy scores + causal softmax (bounded loops) -> fp16 attn plane
__global__ void k_scores(const float* __restrict__ w_charge, const float* __restrict__ w_shell,
                         const float* __restrict__ w_distance, const float* __restrict__ w_mass,
                         const float* __restrict__ w_valence, const float* __restrict__ temperature) {
    int gi = blockIdx.x;
    int b  = gi >> 11;
    int i  = NN - 1 - (gi & 2047);        // heavy rows first
    int rowEnd = ((i >> 7) + 1) << 7;     // 128-aligned: what attn@V reads
    int tid = threadIdx.x;
    __shared__ float sc[2048];
    __shared__ float cp[1024];
    __shared__ float red[256];
    for (int t = tid; t < 1024; t += 256) cp[t] = g_compat[t];

    float spc = sp_(w_charge[0]);
    float sps = sp_(w_shell[0]);
    float spd = sp_(w_distance[0]);
    float spm = sp_(w_mass[0]);
    float spv = sp_(w_valence[0]);
    float invt = 1.f / sp_(temperature[0]);

    const float4* rf = (const float4*)g_rowf;
    int base = b * NN;
    float4 m0 = rf[(size_t)(base + i) * 2];
    float4 m1 = rf[(size_t)(base + i) * 2 + 1];
    float ci = m0.x, si0 = m0.y, si1 = m0.z, si2 = m0.w;
    float mi = m1.x;
    int cli = __float_as_int(m1.y) * 32;
    __syncthreads();

    for (int j = tid; j <= i; j += 256) {
        float4 f0 = rf[(size_t)(base + j) * 2];
        float4 f1 = rf[(size_t)(base + j) * 2 + 1];
        float d0 = fabsf(si0 - f0.y);
        float d1 = fabsf(si1 - f0.z);
        float d2 = fabsf(si2 - f0.w);
        float dist = (float)(i - j);
        float E = spc * ci * f0.x + sps * (d0 + d1 + d2)
                - spd * __fdividef(1.f, 1.f + 0.1f * dist)
                + spm * 0.1f * mi * f1.x - spv;
        sc[j] = -E * invt * cp[cli + __float_as_int(f1.y)];
    }
    __syncthreads();

    float lm = neg_inf_();
    for (int j = tid; j <= i; j += 256) lm = fmaxf(lm, sc[j]);
    red[tid] = lm; __syncthreads();
    for (int o = 128; o; o >>= 1) { if (tid < o) red[tid] = fmaxf(red[tid], red[tid + o]); __syncthreads(); }
    float mx = red[0]; __syncthreads();

    float ls = 0.f;
    for (int j = tid; j <= i; j += 256) { float e = expf(sc[j] - mx); sc[j] = e; ls += e; }
    red[tid] = ls; __syncthreads();
    for (int o = 128; o; o >>= 1) { if (tid < o) red[tid] += red[tid + o]; __syncthreads(); }
    float inv = 1.f / red[0];

    __half* ar = g_attnA + (size_t)(base + i) * NN;
    for (int j = tid; j < rowEnd; j += 256)
        ar[j] = __float2half(j <= i ? sc[j] * inv : 0.f);
}

// ---------------- fp32 tiled SGEMM (feat path, with batch strides) -----------
__global__ __launch_bounds__(256)
void sgemm128(const float* __restrict__ A, const float* __restrict__ B,
              float* __restrict__ C, const float* __restrict__ bias,
              int M, int N, int K, int lda, int ldb, int ldc,
              size_t sA, size_t sB, size_t sC) {
    A += (size_t)blockIdx.z * sA;
    B += (size_t)blockIdx.z * sB;
    C += (size_t)blockIdx.z * sC;
    int rowStart = blockIdx.y * 128;
    int colStart = blockIdx.x * 128;

    __shared__ float As[16][128];
    __shared__ float Bs[16][128];
    int tid = threadIdx.x;
    int tx = tid & 15, ty = tid >> 4;
    float acc[8][8];
    #pragma unroll
    for (int i = 0; i < 8; i++)
        #pragma unroll
        for (int j = 0; j < 8; j++) acc[i][j] = 0.f;

    const bool n_vec = ((N & 3) == 0);

    for (int k0 = 0; k0 < K; k0 += 16) {
        #pragma unroll
        for (int l = 0; l < 2; l++) {
            int idx = tid + l * 256;
            int m = idx >> 2;
            int kq = (idx & 3) * 4;
            float4 v = *reinterpret_cast<const float4*>(
                A + (size_t)(rowStart + m) * lda + k0 + kq);
            As[kq + 0][m] = v.x; As[kq + 1][m] = v.y; As[kq + 2][m] = v.z; As[kq + 3][m] = v.w;
        }
        #pragma unroll
        for (int l = 0; l < 2; l++) {
            int idx = tid + l * 256;
            int kr = idx >> 5;
            int nq = (idx & 31) * 4;
            int col = colStart + nq;
            float4 v;
            if (n_vec && col + 3 < N) {
                v = *reinterpret_cast<const float4*>(B + (size_t)(k0 + kr) * ldb + col);
            } else {
                const float* bp = B + (size_t)(k0 + kr) * ldb;
                v.x = (col + 0 < N) ? bp[col + 0] : 0.f;
                v.y = (col + 1 < N) ? bp[col + 1] : 0.f;
                v.z = (col + 2 < N) ? bp[col + 2] : 0.f;
                v.w = (col + 3 < N) ? bp[col + 3] : 0.f;
            }
            *reinterpret_cast<float4*>(&Bs[kr][nq]) = v;
        }
        __syncthreads();
        #pragma unroll
        for (int kk = 0; kk < 16; kk++) {
            float ra[8], rb[8];
            *(float4*)&ra[0] = *(float4*)&As[kk][ty * 8];
            *(float4*)&ra[4] = *(float4*)&As[kk][ty * 8 + 4];
            *(float4*)&rb[0] = *(float4*)&Bs[kk][tx * 8];
            *(float4*)&rb[4] = *(float4*)&Bs[kk][tx * 8 + 4];
            #pragma unroll
            for (int i = 0; i < 8; i++)
                #pragma unroll
                for (int j = 0; j < 8; j++)
                    acc[i][j] += ra[i] * rb[j];
        }
        __syncthreads();
    }

    #pragma unroll
    for (int i = 0; i < 8; i++) {
        size_t row = rowStart + ty * 8 + i;
        #pragma unroll
        for (int j = 0; j < 8; j++) {
            int col = colStart + tx * 8 + j;
            if (col < N) {
                float v = acc[i][j] + (bias ? bias[col] : 0.f);
                C[row * (size_t)ldc + col] = v;
            }
        }
    }
}

// ---------------- host ----------------
extern "C" void kernel_launch(void* const* d_in, const int* in_sizes, int n_in,
                              void* d_out, int out_size) {
    const float* x         = (const float*)d_in[0];
    const float* W_sense   = (const float*)d_in[1];
    const float* b_sense   = (const float*)d_in[2];
    const float* W_ctx     = (const float*)d_in[3];
    const float* b_ctx     = (const float*)d_in[4];
    const float* W_sel     = (const float*)d_in[5];
    const float* b_sel     = (const float*)d_in[6];
    const float* W_charge  = (const float*)d_in[7];
    const float* b_charge  = (const float*)d_in[8];
    const float* W_shell   = (const float*)d_in[9];
    const float* b_shell   = (const float*)d_in[10];
    const float* W_class   = (const float*)d_in[11];
    const float* b_class   = (const float*)d_in[12];
    const float* W_mass    = (const float*)d_in[13];
    const float* b_mass    = (const float*)d_in[14];
    const float* compatL   = (const float*)d_in[17];
    const float* w_charge  = (const float*)d_in[18];
    const float* w_shell   = (const float*)d_in[19];
    const float* w_distance= (const float*)d_in[20];
    const float* w_mass    = (const float*)d_in[21];
    const float* w_valence = (const float*)d_in[22];
    const float* temperature=(const float*)d_in[23];
    const float* W_v       = (const float*)d_in[24];
    const float* b_v       = (const float*)d_in[25];
    const float* W_out     = (const float*)d_in[26];
    const float* b_out     = (const float*)d_in[27];
    float* out = (float*)d_out;

    void *p_senses, *p_V, *p_Wfeat, *p_Wcomb, *p_xC;
    void *p_xA, *p_WsT, *p_xnA, *p_WvT, *p_VT, *p_attnA, *p_aoA, *p_WoT;
    cudaGetSymbolAddress(&p_senses, g_senses);
    cudaGetSymbolAddress(&p_V,      g_V);
    cudaGetSymbolAddress(&p_Wfeat,  g_Wfeat);
    cudaGetSymbolAddress(&p_Wcomb,  g_Wcomb);
    cudaGetSymbolAddress(&p_xC,     g_xC);
    cudaGetSymbolAddress(&p_xA,     g_xA);
    cudaGetSymbolAddress(&p_WsT,    g_WsT);
    cudaGetSymbolAddress(&p_xnA,    g_xnA);
    cudaGetSymbolAddress(&p_WvT,    g_WvT);
    cudaGetSymbolAddress(&p_VT,     g_VT);
    cudaGetSymbolAddress(&p_attnA,  g_attnA);
    cudaGetSymbolAddress(&p_aoA,    g_aoA);
    cudaGetSymbolAddress(&p_WoT,    g_WoT);

    const int SM22 = 3 * 4 * 8192;   // 98304 (3 stages)
    const int SM12 = 3 * 3 * 8192;   // 73728
    cudaFuncSetAttribute(hgemm<2, 2, false, 0>, cudaFuncAttributeMaxDynamicSharedMemorySize, SM22);
    cudaFuncSetAttribute(hgemm<1, 2, true, 1>,  cudaFuncAttributeMaxDynamicSharedMemorySize, SM12);

    const size_t PSxA = (size_t)8192 * 1024;
    const size_t PSWs = (size_t)3072 * 1024;
    const size_t PSWv = (size_t)1024 * 1024;
    const size_t PSVT = (size_t)4 * 1024 * 2048;
    const size_t PSao = (size_t)8192 * 1024;
    const size_t PSWo = (size_t)1024 * 1024;

    // ---- prep ----
    k_compat<<<1, 1024>>>(compatL);
    k_meanpart<<<dim3(4, 64), 256>>>(x);
    k_meanfin<<<16, 256>>>();
    k_ctxpart<<<dim3(4, 1, 8), 256>>>(W_ctx);
    k_ctxfin<<<16, 256>>>(b_ctx);
    k_selctx<<<dim3(3, 4), 128>>>(W_sel, b_sel);
    k_packfeat<<<(1024 * NF + 255) / 256, 256>>>(W_charge, b_charge, W_shell, b_shell,
                                                 W_class, b_class, W_mass, b_mass);
    sgemm128<<<dim3(1, 8, 3), 256>>>(W_sense, (const float*)p_Wfeat, (float*)p_Wcomb, nullptr,
                                     1024, NF, 1024, 3072, NF, 128,
                                     1024, 0, NF);
    k_bcomb<<<1, 128>>>(b_sense);
    sgemm128<<<dim3(1, 64, 2), 256>>>(x, (const float*)p_Wcomb, (float*)p_xC, nullptr,
                                      ROWS, 128, 512, 1024, 128, 128,
                                      512, (size_t)512 * 128, (size_t)8192 * 128);

    // ---- operand conversion ----
    k_splitA<<<8192, 256>>>(x, (__half*)p_xA, PSxA);
    k_convBt<<<dim3(96, 32, 1), 256>>>(W_sense, (__half*)p_WsT, 3072, 1024, PSWs, 0, 0);

    // ---- senses = x @ W_sense + b_sense ----
    hgemm<2, 2, false, 0><<<dim3(24, 64, 1), 256, SM22>>>(
        (const __half*)p_xA, (const __half*)p_WsT, p_senses, b_sense,
        1024, 1024, 1024, 3072, PSxA, PSWs, 0, 0, 0, 0);

    // ---- combine -> xnew planes (+sel weights) ----
    k_combine<<<ROWS, 256>>>(x, W_sel);

    // ---- per-row features ----
    k_featrow<<<ROWS, 64>>>();

    // ---- scores + causal softmax -> fp16 attn ----
    k_scores<<<ROWS, 256>>>(w_charge, w_shell, w_distance, w_mass, w_valence, temperature);

    // ---- V = xnew @ W_v + b_v ----
    k_convBt<<<dim3(32, 32, 1), 256>>>(W_v, (__half*)p_WvT, 1024, 1024, PSWv, 0, 0);
    hgemm<2, 2, false, 0><<<dim3(8, 64, 1), 256, SM22>>>(
        (const __half*)p_xnA, (const __half*)p_WvT, p_V, b_v,
        1024, 1024, 1024, 1024, PSxA, PSWv, 0, 0, 0, 0);

    // ---- V -> transposed split planes ----
    k_convBt<<<dim3(32, 64, 4), 256>>>((const float*)p_V, (__half*)p_VT, 1024, 2048, PSVT,
                                       (size_t)2048 * 1024, (size_t)1024 * 2048);

    // ---- attnout = attn @ V (causal, batched) -> split planes ----
    hgemm<1, 2, true, 1><<<dim3(8, 16, 4), 256, SM12>>>(
        (const __half*)p_attnA, (const __half*)p_VT, p_aoA, nullptr,
        2048, 2048, 2048, 1024, 0, PSVT, PSao,
        (size_t)2048 * 2048, (size_t)1024 * 2048, (size_t)2048 * 1024);

    // ---- out = attnout @ W_out + b_out ----
    k_convBt<<<dim3(32, 32, 1), 256>>>(W_out, (__half*)p_WoT, 1024, 1024, PSWo, 0, 0);
    hgemm<2, 2, false, 0><<<dim3(8, 64, 1), 256, SM22>>>(
        (const __half*)p_aoA, (const __half*)p_WoT, out, b_out,
        1024, 1024, 1024, 1024, PSao, PSWo, 0, 0, 0, 0);

    (void)in_sizes; (void)n_in; (void)out_size;
}

// round 8
// speedup vs baseline: 3.1075x; 1.1976x over previous
#include <cuda_runtime.h>
#include <cuda_fp16.h>
#include <math.h>
#include <stdint.h>
#include <cstdint>

// Problem constants
#define BB 4
#define NN 2048
#define DD 1024
#define ROWS 8192      // B*N
#define NF 37

// ---------------- device scratch (allocation-free) ----------------
__device__ float g_senses[8192 * 3072];
__device__ float g_V     [8192 * 1024];
__device__ float g_partial[4 * 16 * 1024];
__device__ float g_xmean [4 * 1024];
__device__ float g_ctx   [4 * 1024];
__device__ float g_selctx[4 * 3];
__device__ float g_selw  [8192 * 3];
__device__ float g_rowf  [8192 * 8];
__device__ float g_compat[1024];
__device__ float g_Wfeat [1024 * NF];
__device__ float g_bfeat [NF];
__device__ float g_Wcomb [1024 * 128];
__device__ float g_bcomb [3 * NF];
__device__ float g_xC    [2 * 8192 * 128];

// fp16 split planes
__device__ __half g_xA   [2 * 8192 * 1024];
__device__ __half g_WsT  [2 * 3072 * 1024];
__device__ __half g_xnA  [2 * 8192 * 1024];
__device__ __half g_WvT  [2 * 1024 * 1024];
__device__ __half g_VT   [2 * 4 * 1024 * 2048];
__device__ __half g_attnA[8192 * 2048];
__device__ __half g_aoA  [2 * 8192 * 1024];
__device__ __half g_WoT  [2 * 1024 * 1024];

__device__ __forceinline__ float sp_(float z) {
    return z > 20.f ? z : log1pf(expf(z));
}
__device__ __forceinline__ float neg_inf_() { return __int_as_float(0xff800000u); }

__device__ __forceinline__ uint32_t smem_u32(const void* p) {
    uint32_t a;
    asm("{ .reg .u64 t; cvta.to.shared.u64 t, %1; cvt.u32.u64 %0, t; }" : "=r"(a) : "l"(p));
    return a;
}
__device__ __forceinline__ void ldm_x4(uint32_t* r, uint32_t addr) {
    asm volatile("ldmatrix.sync.aligned.m8n8.x4.shared.b16 {%0,%1,%2,%3}, [%4];"
        : "=r"(r[0]), "=r"(r[1]), "=r"(r[2]), "=r"(r[3]) : "r"(addr));
}
__device__ __forceinline__ void mma_f16(float* c, const uint32_t* a, const uint32_t* b) {
    asm volatile("mma.sync.aligned.m16n8k16.row.col.f32.f16.f16.f32 "
        "{%0,%1,%2,%3}, {%4,%5,%6,%7}, {%8,%9}, {%0,%1,%2,%3};"
        : "+f"(c[0]), "+f"(c[1]), "+f"(c[2]), "+f"(c[3])
        : "r"(a[0]), "r"(a[1]), "r"(a[2]), "r"(a[3]), "r"(b[0]), "r"(b[1]));
}
__device__ __forceinline__ void cp_async16(uint32_t s, const void* g) {
    asm volatile("cp.async.cg.shared.global [%0], [%1], 16;" :: "r"(s), "l"(g));
}
__device__ __forceinline__ void cp_commit() { asm volatile("cp.async.commit_group;" ::: "memory"); }
template<int N> __device__ __forceinline__ void cp_wait() {
    asm volatile("cp.async.wait_group %0;" :: "n"(N) : "memory");
}

// ---------------- fp16 split GEMM (mma.sync, 3-stage cp.async pipeline) ------
// C = A@B (+bias). A: SAP fp16 planes [M][K]; B: SBP planes [N][K] (pre-transposed).
// Terms (ci,cj) with ci+cj < max(SAP,SBP) accumulate in fp32.
// 128x128 CTA tile, BK=32, 256 thr = 8 warps (2Mx4N), 64x32/warp, 2 CTAs/SM.
template<int SAP, int SBP, bool CAUSAL, int OUTM>
__global__ __launch_bounds__(256, 2)
void hgemm(const __half* __restrict__ A, const __half* __restrict__ B,
           void* __restrict__ Cv, const float* __restrict__ bias,
           int K, int lda, int ldb, int ldc,
           size_t psA, size_t psB, size_t psC,
           size_t sA, size_t sB, size_t sC) {
    extern __shared__ char smx[];
    A += (size_t)blockIdx.z * sA;
    B += (size_t)blockIdx.z * sB;
    const int by = CAUSAL ? (gridDim.y - 1 - blockIdx.y) : blockIdx.y;
    const int rowStart = by * 128;
    const int colStart = blockIdx.x * 128;
    const int kmax = CAUSAL ? min(K, rowStart + 128) : K;
    const int tid = threadIdx.x, lane = tid & 31, wid = tid >> 5;
    const int mW = (wid >> 2) * 64, nW = (wid & 3) * 32;
    const uint32_t smBase = smem_u32(smx);
    constexpr uint32_t PL  = 8192u;
    constexpr uint32_t STG = (uint32_t)(SAP + SBP) * PL;
    constexpr int MAXS = (SAP > SBP) ? SAP : SBP;

    float acc[4][4][4];
    #pragma unroll
    for (int i = 0; i < 4; ++i)
        #pragma unroll
        for (int j = 0; j < 4; ++j)
            #pragma unroll
            for (int e = 0; e < 4; ++e) acc[i][j][e] = 0.f;

    const int rA = mW + (lane & 15);
    const int rB = nW + ((lane >> 4) << 3) + (lane & 7);
    const uint32_t swA = (uint32_t)((rA >> 1) & 3);
    const uint32_t swB = (uint32_t)((rB >> 1) & 3);
    const uint32_t cA = (uint32_t)(lane >> 4);
    const uint32_t cB = (uint32_t)((lane >> 3) & 1);
    uint32_t aRow[4], bRow[2];
    #pragma unroll
    for (int am = 0; am < 4; ++am) aRow[am] = (uint32_t)(rA + am * 16) * 64u;
    #pragma unroll
    for (int np = 0; np < 2; ++np) bRow[np] = (uint32_t)(rB + np * 16) * 64u;

    const int r2 = tid >> 2, c2 = tid & 3;

    auto loadStage = [&](int st, int k0) {
        uint32_t sb = smBase + (uint32_t)st * STG;
        #pragma unroll
        for (int p = 0; p < SAP; ++p) {
            const __half* gp = A + (size_t)p * psA + (size_t)rowStart * lda + k0;
            #pragma unroll
            for (int l = 0; l < 2; ++l) {
                int r = l * 64 + r2;
                uint32_t sa = sb + (uint32_t)p * PL + (uint32_t)r * 64u +
                              ((((uint32_t)c2) ^ (((uint32_t)r >> 1) & 3u)) << 4);
                cp_async16(sa, gp + (size_t)r * lda + c2 * 8);
            }
        }
        #pragma unroll
        for (int p = 0; p < SBP; ++p) {
            const __half* gp = B + (size_t)p * psB + (size_t)colStart * ldb + k0;
            #pragma unroll
            for (int l = 0; l < 2; ++l) {
                int r = l * 64 + r2;
                uint32_t sa = sb + (uint32_t)(SAP + p) * PL + (uint32_t)r * 64u +
                              ((((uint32_t)c2) ^ (((uint32_t)r >> 1) & 3u)) << 4);
                cp_async16(sa, gp + (size_t)r * ldb + c2 * 8);
            }
        }
    };

    const int nIter = kmax >> 5;
    if (0 < nIter) loadStage(0, 0);
    cp_commit();
    if (1 < nIter) loadStage(1, 32);
    cp_commit();

    for (int it = 0; it < nIter; ++it) {
        if (it + 1 < nIter) cp_wait<1>(); else cp_wait<0>();
        __syncthreads();
        int nl = it + 2;
        if (nl < nIter) loadStage(nl - (nl / 3) * 3, nl << 5);
        cp_commit();

        uint32_t sb = smBase + (uint32_t)(it - (it / 3) * 3) * STG;
        #pragma unroll
        for (int ks = 0; ks < 2; ++ks) {
            uint32_t af[SAP][4][4], bf[SBP][2][4];
            #pragma unroll
            for (int p = 0; p < SAP; ++p)
                #pragma unroll
                for (int am = 0; am < 4; ++am)
                    ldm_x4(af[p][am], sb + (uint32_t)p * PL + aRow[am] +
                           ((((uint32_t)(2 * ks) + cA) ^ swA) << 4));
            #pragma unroll
            for (int p = 0; p < SBP; ++p)
                #pragma unroll
                for (int np = 0; np < 2; ++np)
                    ldm_x4(bf[p][np], sb + (uint32_t)(SAP + p) * PL + bRow[np] +
                           ((((uint32_t)(2 * ks) + cB) ^ swB) << 4));
            #pragma unroll
            for (int ci = 0; ci < SAP; ++ci)
                #pragma unroll
                for (int cj = 0; cj < SBP; ++cj) {
                    if (ci + cj >= MAXS) continue;
                    #pragma unroll
                    for (int am = 0; am < 4; ++am)
                        #pragma unroll
                        for (int an = 0; an < 4; ++an)
                            mma_f16(acc[am][an], af[ci][am], &bf[cj][an >> 1][(an & 1) * 2]);
                }
        }
    }

    #pragma unroll
    for (int am = 0; am < 4; ++am) {
        int row = rowStart + mW + am * 16 + (lane >> 2);
        #pragma unroll
        for (int an = 0; an < 4; ++an) {
            int col = colStart + nW + an * 8 + (lane & 3) * 2;
            float b0 = bias ? bias[col] : 0.f, b1 = bias ? bias[col + 1] : 0.f;
            float v0 = acc[am][an][0] + b0, v1 = acc[am][an][1] + b1;
            float v2 = acc[am][an][2] + b0, v3 = acc[am][an][3] + b1;
            if (OUTM == 0) {
                float* C = (float*)Cv + (size_t)blockIdx.z * sC;
                *(float2*)(C + (size_t)row * ldc + col) = make_float2(v0, v1);
                *(float2*)(C + (size_t)(row + 8) * ldc + col) = make_float2(v2, v3);
            } else {
                __half* Cp = (__half*)Cv + (size_t)blockIdx.z * sC;
                __half h0 = __float2half(v0), h1 = __float2half(v1);
                __half h2 = __float2half(v2), h3 = __float2half(v3);
                __half2 hh01; hh01.x = h0; hh01.y = h1;
                __half2 hh23; hh23.x = h2; hh23.y = h3;
                __half2 ll01; ll01.x = __float2half(v0 - __half2float(h0));
                              ll01.y = __float2half(v1 - __half2float(h1));
                __half2 ll23; ll23.x = __float2half(v2 - __half2float(h2));
                              ll23.y = __float2half(v3 - __half2float(h3));
                *(__half2*)(Cp + (size_t)row * ldc + col) = hh01;
                *(__half2*)(Cp + (size_t)(row + 8) * ldc + col) = hh23;
                *(__half2*)(Cp + psC + (size_t)row * ldc + col) = ll01;
                *(__half2*)(Cp + psC + (size_t)(row + 8) * ldc + col) = ll23;
            }
        }
    }
}

// ---------------- conversion kernels ----------------

__global__ void k_splitA(const float* __restrict__ src, __half* __restrict__ dst, size_t ps) {
    size_t i = ((size_t)blockIdx.x * 256 + threadIdx.x) * 4;
    float4 v = *(const float4*)(src + i);
    __half h0 = __float2half(v.x), h1 = __float2half(v.y);
    __half h2 = __float2half(v.z), h3 = __float2half(v.w);
    __half2 a; a.x = h0; a.y = h1;
    __half2 b; b.x = h2; b.y = h3;
    *(__half2*)(dst + i) = a; *(__half2*)(dst + i + 2) = b;
    __half2 c; c.x = __float2half(v.x - __half2float(h0)); c.y = __float2half(v.y - __half2float(h1));
    __half2 d; d.x = __float2half(v.z - __half2float(h2)); d.y = __float2half(v.w - __half2float(h3));
    *(__half2*)(dst + ps + i) = c; *(__half2*)(dst + ps + i + 2) = d;
}

// transpose + split (hi plane always; lo plane only if WRLO)
__global__ void k_convBt(const float* __restrict__ src, __half* __restrict__ dst,
                         int lds, int ldd, size_t ps, size_t sS, size_t sD, int wrlo) {
    src += (size_t)blockIdx.z * sS;
    dst += (size_t)blockIdx.z * sD;
    int n0 = blockIdx.x * 32, k0 = blockIdx.y * 32;
    __shared__ float t[32][33];
    int tx = threadIdx.x & 31, ty = threadIdx.x >> 5;
    #pragma unroll
    for (int l = 0; l < 4; ++l)
        t[ty + l * 8][tx] = src[(size_t)(k0 + ty + l * 8) * lds + n0 + tx];
    __syncthreads();
    #pragma unroll
    for (int l = 0; l < 4; ++l) {
        int n = ty + l * 8;
        float v = t[tx][n];
        __half h = __float2half(v);
        dst[(size_t)(n0 + n) * ldd + k0 + tx] = h;
        if (wrlo)
            dst[ps + (size_t)(n0 + n) * ldd + k0 + tx] = __float2half(v - __half2float(h));
    }
}

// ---------------- small kernels ----------------

__global__ void k_compat(const float* __restrict__ L) {
    int t = threadIdx.x;
    int i = t >> 5, j = t & 31;
    float v = (L[i * 32 + j] + L[j * 32 + i]) * 0.5f;
    g_compat[t] = 1.f / (1.f + expf(-v));
}

__global__ void k_meanpart(const float* __restrict__ x) {
    int d  = blockIdx.x * 256 + threadIdx.x;
    int bc = blockIdx.y;
    int b  = bc >> 4, c = bc & 15;
    const float* xp = x + ((size_t)b * NN + c * 128) * DD + d;
    float s = 0.f;
    #pragma unroll 8
    for (int n = 0; n < 128; n++) s += xp[(size_t)n * DD];
    g_partial[bc * 1024 + d] = s;
}

__global__ void k_meanfin() {
    int idx = blockIdx.x * 256 + threadIdx.x;
    int b = idx >> 10, d = idx & 1023;
    float s = 0.f;
    #pragma unroll
    for (int c = 0; c < 16; c++) s += g_partial[(b * 16 + c) * 1024 + d];
    g_xmean[idx] = s * (1.f / (float)NN);
}

// ctx partial: K split 8 ways across blockIdx.z (128 blocks, latency-friendly)
__global__ void k_ctxpart(const float* __restrict__ W_ctx) {
    int d = blockIdx.x * 256 + threadIdx.x;  // 4 x-blocks
    int b = blockIdx.y;                      // 4
    int z = blockIdx.z;                      // 8
    const float* xm = g_xmean + b * 1024 + z * 128;
    const float* W  = W_ctx + (size_t)(z * 128) * 1024 + d;
    float acc = 0.f;
    #pragma unroll 8
    for (int k = 0; k < 128; k++) acc += xm[k] * W[(size_t)k * 1024];
    g_partial[(z * 4 + b) * 1024 + d] = acc;
}

__global__ void k_ctxfin(const float* __restrict__ b_ctx) {
    int idx = blockIdx.x * 256 + threadIdx.x;
    int b = idx >> 10, d = idx & 1023;
    float s = 0.f;
    #pragma unroll
    for (int z = 0; z < 8; z++) s += g_partial[(z * 4 + b) * 1024 + d];
    g_ctx[idx] = s + b_ctx[d];
}

__global__ void k_selctx(const float* __restrict__ W_sel, const float* __restrict__ b_sel) {
    int s = blockIdx.x, b = blockIdx.y;
    int tid = threadIdx.x;
    const float* c = g_ctx + b * 1024;
    float p = 0.f;
    for (int k = tid; k < 1024; k += 128) p += c[k] * W_sel[(size_t)(1024 + k) * 3 + s];
    __shared__ float red[128];
    red[tid] = p; __syncthreads();
    for (int o = 64; o; o >>= 1) { if (tid < o) red[tid] += red[tid + o]; __syncthreads(); }
    if (tid == 0) g_selctx[b * 3 + s] = red[0] + b_sel[s];
}

__global__ void k_packfeat(const float* __restrict__ W_charge, const float* __restrict__ b_charge,
                           const float* __restrict__ W_shell,  const float* __restrict__ b_shell,
                           const float* __restrict__ W_class,  const float* __restrict__ b_class,
                           const float* __restrict__ W_mass,   const float* __restrict__ b_mass) {
    int idx = blockIdx.x * 256 + threadIdx.x;
    if (idx < 1024 * NF) {
        int k = idx / NF, c = idx % NF;
        float v;
        if (c == 0)       v = W_charge[k];
        else if (c <= 3)  v = W_shell[k * 3 + (c - 1)];
        else if (c <= 35) v = W_class[k * 32 + (c - 4)];
        else              v = W_mass[k];
        g_Wfeat[k * NF + c] = v;
    }
    if (idx < NF) {
        float v;
        if (idx == 0)       v = b_charge[0];
        else if (idx <= 3)  v = b_shell[idx - 1];
        else if (idx <= 35) v = b_class[idx - 4];
        else                v = b_mass[0];
        g_bfeat[idx] = v;
    }
}

__global__ void k_bcomb(const float* __restrict__ b_sense) {
    int c = blockIdx.x * 128 + threadIdx.x;
    if (c >= 3 * NF) return;
    int s = c / NF, cc = c % NF;
    float acc = 0.f;
    for (int k = 0; k < 1024; k++)
        acc += b_sense[s * 1024 + k] * g_Wfeat[k * NF + cc];
    g_bcomb[c] = acc;
}

// sel weights + combine senses -> xnew fp16 split planes; store weights
__global__ void k_combine(const float* __restrict__ x, const float* __restrict__ W_sel) {
    int row = blockIdx.x;
    int b   = row >> 11;
    int tid = threadIdx.x;
    const float* xr = x + (size_t)row * DD;
    float p0 = 0.f, p1 = 0.f, p2 = 0.f;
    for (int k = tid; k < 1024; k += 256) {
        float xv = xr[k];
        const float* w = W_sel + (size_t)k * 3;
        p0 += xv * w[0]; p1 += xv * w[1]; p2 += xv * w[2];
    }
    __shared__ float r0[256], r1[256], r2[256];
    r0[tid] = p0; r1[tid] = p1; r2[tid] = p2; __syncthreads();
    for (int o = 128; o; o >>= 1) {
        if (tid < o) { r0[tid] += r0[tid + o]; r1[tid] += r1[tid + o]; r2[tid] += r2[tid + o]; }
        __syncthreads();
    }
    float l0 = r0[0] + g_selctx[b * 3 + 0];
    float l1 = r1[0] + g_selctx[b * 3 + 1];
    float l2 = r2[0] + g_selctx[b * 3 + 2];
    float m  = fmaxf(l0, fmaxf(l1, l2));
    float e0 = expf(l0 - m), e1 = expf(l1 - m), e2 = expf(l2 - m);
    float inv = 1.f / (e0 + e1 + e2);
    float w0 = e0 * inv, w1 = e1 * inv, w2 = e2 * inv;
    if (tid == 0) {
        g_selw[row * 3 + 0] = w0;
        g_selw[row * 3 + 1] = w1;
        g_selw[row * 3 + 2] = w2;
    }

    const float4* S0 = (const float4*)(g_senses + (size_t)row * 3072);
    const float4* S1 = (const float4*)(g_senses + (size_t)row * 3072 + 1024);
    const float4* S2 = (const float4*)(g_senses + (size_t)row * 3072 + 2048);
    float4 a = S0[tid], bb = S1[tid], c = S2[tid];
    float o0 = w0 * a.x + w1 * bb.x + w2 * c.x;
    float o1 = w0 * a.y + w1 * bb.y + w2 * c.y;
    float o2 = w0 * a.z + w1 * bb.z + w2 * c.z;
    float o3 = w0 * a.w + w1 * bb.w + w2 * c.w;
    __half h0 = __float2half(o0), h1 = __float2half(o1);
    __half h2 = __float2half(o2), h3 = __float2half(o3);
    size_t off = (size_t)row * 1024 + tid * 4;
    const size_t PS = (size_t)8192 * 1024;
    __half2 hh01; hh01.x = h0; hh01.y = h1;
    __half2 hh23; hh23.x = h2; hh23.y = h3;
    *(__half2*)(g_xnA + off) = hh01;
    *(__half2*)(g_xnA + off + 2) = hh23;
    __half2 ll01; ll01.x = __float2half(o0 - __half2float(h0)); ll01.y = __float2half(o1 - __half2float(h1));
    __half2 ll23; ll23.x = __float2half(o2 - __half2float(h2)); ll23.y = __float2half(o3 - __half2float(h3));
    *(__half2*)(g_xnA + PS + off) = ll01;
    *(__half2*)(g_xnA + PS + off + 2) = ll23;
}

// per-row features (fp32 xC path) -> packed g_rowf
__global__ void k_featrow() {
    int row = blockIdx.x;
    int tid = threadIdx.x;   // 64
    __shared__ float fv[NF];
    if (tid < NF) {
        float w0 = g_selw[row * 3 + 0];
        float w1 = g_selw[row * 3 + 1];
        float w2 = g_selw[row * 3 + 2];
        const float* xc0 = g_xC + (size_t)row * 128;
        const float* xc1 = g_xC + (size_t)8192 * 128 + (size_t)row * 128;
        float v0 = xc0[tid]          + xc1[tid]          + g_bcomb[tid];
        float v1 = xc0[NF + tid]     + xc1[NF + tid]     + g_bcomb[NF + tid];
        float v2 = xc0[2 * NF + tid] + xc1[2 * NF + tid] + g_bcomb[2 * NF + tid];
        fv[tid] = g_bfeat[tid] + w0 * v0 + w1 * v1 + w2 * v2;
    }
    __syncthreads();
    if (tid == 0) {
        float* rf = g_rowf + (size_t)row * 8;
        rf[0] = tanhf(fv[0]);
        float s0 = fv[1], s1 = fv[2], s2 = fv[3];
        float m = fmaxf(s0, fmaxf(s1, s2));
        float e0 = expf(s0 - m), e1 = expf(s1 - m), e2 = expf(s2 - m);
        float inv = 1.f / (e0 + e1 + e2);
        rf[1] = e0 * inv; rf[2] = e1 * inv; rf[3] = e2 * inv;
        float best = fv[4]; int bi = 0;
        #pragma unroll
        for (int c = 1; c < 32; c++) { float v = fv[4 + c]; if (v > best) { best = v; bi = c; } }
        rf[4] = sp_(fv[36]) + 0.5f;
        rf[5] = __int_as_float(bi);
        rf[6] = 0.f; rf[7] = 0.f;
    }
}

// energy scores + causal softmax (bounded loops) -> fp16 attn plane
__global__ void k_scores(const float* __restrict__ w_charge, const float* __restrict__ w_shell,
                         const float* __restrict__ w_distance, const float* __restrict__ w_mass,
                         const float* __restrict__ w_valence, const float* __restrict__ temperature) {
    int gi = blockIdx.x;
    int b  = gi >> 11;
    int i  = NN - 1 - (gi & 2047);
    int rowEnd = ((i >> 7) + 1) << 7;
    int tid = threadIdx.x;
    __shared__ float sc[2048];
    __shared__ float cp[1024];
    __shared__ float red[256];
    for (int t = tid; t < 1024; t += 256) cp[t] = g_compat[t];

    float spc = sp_(w_charge[0]);
    float sps = sp_(w_shell[0]);
    float spd = sp_(w_distance[0]);
    float spm = sp_(w_mass[0]);
    float spv = sp_(w_valence[0]);
    float invt = 1.f / sp_(temperature[0]);

    const float4* rf = (const float4*)g_rowf;
    int base = b * NN;
    float4 m0 = rf[(size_t)(base + i) * 2];
    float4 m1 = rf[(size_t)(base + i) * 2 + 1];
    float ci = m0.x, si0 = m0.y, si1 = m0.z, si2 = m0.w;
    float mi = m1.x;
    int cli = __float_as_int(m1.y) * 32;
    __syncthreads();

    for (int j = tid; j <= i; j += 256) {
        float4 f0 = rf[(size_t)(base + j) * 2];
        float4 f1 = rf[(size_t)(base + j) * 2 + 1];
        float d0 = fabsf(si0 - f0.y);
        float d1 = fabsf(si1 - f0.z);
        float d2 = fabsf(si2 - f0.w);
        float dist = (float)(i - j);
        float E = spc * ci * f0.x + sps * (d0 + d1 + d2)
                - spd * __fdividef(1.f, 1.f + 0.1f * dist)
                + spm * 0.1f * mi * f1.x - spv;
        sc[j] = -E * invt * cp[cli + __float_as_int(f1.y)];
    }
    __syncthreads();

    float lm = neg_inf_();
    for (int j = tid; j <= i; j += 256) lm = fmaxf(lm, sc[j]);
    red[tid] = lm; __syncthreads();
    for (int o = 128; o; o >>= 1) { if (tid < o) red[tid] = fmaxf(red[tid], red[tid + o]); __syncthreads(); }
    float mx = red[0]; __syncthreads();

    float ls = 0.f;
    for (int j = tid; j <= i; j += 256) { float e = expf(sc[j] - mx); sc[j] = e; ls += e; }
    red[tid] = ls; __syncthreads();
    for (int o = 128; o; o >>= 1) { if (tid < o) red[tid] += red[tid + o]; __syncthreads(); }
    float inv = 1.f / red[0];

    __half* ar = g_attnA + (size_t)(base + i) * NN;
    for (int j = tid; j < rowEnd; j += 256)
        ar[j] = __float2half(j <= i ? sc[j] * inv : 0.f);
}

// ---------------- fp32 tiled SGEMM (feat path, with batch strides) -----------
__global__ __launch_bounds__(256)
void sgemm128(const float* __restrict__ A, const float* __restrict__ B,
              float* __restrict__ C, const float* __restrict__ bias,
              int M, int N, int K, int lda, int ldb, int ldc,
              size_t sA, size_t sB, size_t sC) {
    A += (size_t)blockIdx.z * sA;
    B += (size_t)blockIdx.z * sB;
    C += (size_t)blockIdx.z * sC;
    int rowStart = blockIdx.y * 128;
    int colStart = blockIdx.x * 128;

    __shared__ float As[16][128];
    __shared__ float Bs[16][128];
    int tid = threadIdx.x;
    int tx = tid & 15, ty = tid >> 4;
    float acc[8][8];
    #pragma unroll
    for (int i = 0; i < 8; i++)
        #pragma unroll
        for (int j = 0; j < 8; j++) acc[i][j] = 0.f;

    const bool n_vec = ((N & 3) == 0);

    for (int k0 = 0; k0 < K; k0 += 16) {
        #pragma unroll
        for (int l = 0; l < 2; l++) {
            int idx = tid + l * 256;
            int m = idx >> 2;
            int kq = (idx & 3) * 4;
            float4 v = *reinterpret_cast<const float4*>(
                A + (size_t)(rowStart + m) * lda + k0 + kq);
            As[kq + 0][m] = v.x; As[kq + 1][m] = v.y; As[kq + 2][m] = v.z; As[kq + 3][m] = v.w;
        }
        #pragma unroll
        for (int l = 0; l < 2; l++) {
            int idx = tid + l * 256;
            int kr = idx >> 5;
            int nq = (idx & 31) * 4;
            int col = colStart + nq;
            float4 v;
            if (n_vec && col + 3 < N) {
                v = *reinterpret_cast<const float4*>(B + (size_t)(k0 + kr) * ldb + col);
            } else {
                const float* bp = B + (size_t)(k0 + kr) * ldb;
                v.x = (col + 0 < N) ? bp[col + 0] : 0.f;
                v.y = (col + 1 < N) ? bp[col + 1] : 0.f;
                v.z = (col + 2 < N) ? bp[col + 2] : 0.f;
                v.w = (col + 3 < N) ? bp[col + 3] : 0.f;
            }
            *reinterpret_cast<float4*>(&Bs[kr][nq]) = v;
        }
        __syncthreads();
        #pragma unroll
        for (int kk = 0; kk < 16; kk++) {
            float ra[8], rb[8];
            *(float4*)&ra[0] = *(float4*)&As[kk][ty * 8];
            *(float4*)&ra[4] = *(float4*)&As[kk][ty * 8 + 4];
            *(float4*)&rb[0] = *(float4*)&Bs[kk][tx * 8];
            *(float4*)&rb[4] = *(float4*)&Bs[kk][tx * 8 + 4];
            #pragma unroll
            for (int i = 0; i < 8; i++)
                #pragma unroll
                for (int j = 0; j < 8; j++)
                    acc[i][j] += ra[i] * rb[j];
        }
        __syncthreads();
    }

    #pragma unroll
    for (int i = 0; i < 8; i++) {
        size_t row = rowStart + ty * 8 + i;
        #pragma unroll
        for (int j = 0; j < 8; j++) {
            int col = colStart + tx * 8 + j;
            if (col < N) {
                float v = acc[i][j] + (bias ? bias[col] : 0.f);
                C[row * (size_t)ldc + col] = v;
            }
        }
    }
}

// ---------------- host ----------------
extern "C" void kernel_launch(void* const* d_in, const int* in_sizes, int n_in,
                              void* d_out, int out_size) {
    const float* x         = (const float*)d_in[0];
    const float* W_sense   = (const float*)d_in[1];
    const float* b_sense   = (const float*)d_in[2];
    const float* W_ctx     = (const float*)d_in[3];
    const float* b_ctx     = (const float*)d_in[4];
    const float* W_sel     = (const float*)d_in[5];
    const float* b_sel     = (const float*)d_in[6];
    const float* W_charge  = (const float*)d_in[7];
    const float* b_charge  = (const float*)d_in[8];
    const float* W_shell   = (const float*)d_in[9];
    const float* b_shell   = (const float*)d_in[10];
    const float* W_class   = (const float*)d_in[11];
    const float* b_class   = (const float*)d_in[12];
    const float* W_mass    = (const float*)d_in[13];
    const float* b_mass    = (const float*)d_in[14];
    const float* compatL   = (const float*)d_in[17];
    const float* w_charge  = (const float*)d_in[18];
    const float* w_shell   = (const float*)d_in[19];
    const float* w_distance= (const float*)d_in[20];
    const float* w_mass    = (const float*)d_in[21];
    const float* w_valence = (const float*)d_in[22];
    const float* temperature=(const float*)d_in[23];
    const float* W_v       = (const float*)d_in[24];
    const float* b_v       = (const float*)d_in[25];
    const float* W_out     = (const float*)d_in[26];
    const float* b_out     = (const float*)d_in[27];
    float* out = (float*)d_out;

    void *p_senses, *p_V, *p_Wfeat, *p_Wcomb, *p_xC;
    void *p_xA, *p_WsT, *p_xnA, *p_WvT, *p_VT, *p_attnA, *p_aoA, *p_WoT;
    cudaGetSymbolAddress(&p_senses, g_senses);
    cudaGetSymbolAddress(&p_V,      g_V);
    cudaGetSymbolAddress(&p_Wfeat,  g_Wfeat);
    cudaGetSymbolAddress(&p_Wcomb,  g_Wcomb);
    cudaGetSymbolAddress(&p_xC,     g_xC);
    cudaGetSymbolAddress(&p_xA,     g_xA);
    cudaGetSymbolAddress(&p_WsT,    g_WsT);
    cudaGetSymbolAddress(&p_xnA,    g_xnA);
    cudaGetSymbolAddress(&p_WvT,    g_WvT);
    cudaGetSymbolAddress(&p_VT,     g_VT);
    cudaGetSymbolAddress(&p_attnA,  g_attnA);
    cudaGetSymbolAddress(&p_aoA,    g_aoA);
    cudaGetSymbolAddress(&p_WoT,    g_WoT);

    const int SM21 = 3 * 3 * 8192;   // 73728 (3 stages x 3 planes)
    const int SM12 = 3 * 3 * 8192;   // 73728
    cudaFuncSetAttribute(hgemm<2, 1, false, 0>, cudaFuncAttributeMaxDynamicSharedMemorySize, SM21);
    cudaFuncSetAttribute(hgemm<1, 2, true, 1>,  cudaFuncAttributeMaxDynamicSharedMemorySize, SM12);

    const size_t PSxA = (size_t)8192 * 1024;
    const size_t PSWs = (size_t)3072 * 1024;
    const size_t PSWv = (size_t)1024 * 1024;
    const size_t PSVT = (size_t)4 * 1024 * 2048;
    const size_t PSao = (size_t)8192 * 1024;
    const size_t PSWo = (size_t)1024 * 1024;

    // ---- prep ----
    k_compat<<<1, 1024>>>(compatL);
    k_meanpart<<<dim3(4, 64), 256>>>(x);
    k_meanfin<<<16, 256>>>();
    k_ctxpart<<<dim3(4, 4, 8), 256>>>(W_ctx);
    k_ctxfin<<<16, 256>>>(b_ctx);
    k_selctx<<<dim3(3, 4), 128>>>(W_sel, b_sel);
    k_packfeat<<<(1024 * NF + 255) / 256, 256>>>(W_charge, b_charge, W_shell, b_shell,
                                                 W_class, b_class, W_mass, b_mass);
    sgemm128<<<dim3(1, 8, 3), 256>>>(W_sense, (const float*)p_Wfeat, (float*)p_Wcomb, nullptr,
                                     1024, NF, 1024, 3072, NF, 128,
                                     1024, 0, NF);
    k_bcomb<<<1, 128>>>(b_sense);
    sgemm128<<<dim3(1, 64, 2), 256>>>(x, (const float*)p_Wcomb, (float*)p_xC, nullptr,
                                      ROWS, 128, 512, 1024, 128, 128,
                                      512, (size_t)512 * 128, (size_t)8192 * 128);

    // ---- operand conversion (weights: hi plane only) ----
    k_splitA<<<8192, 256>>>(x, (__half*)p_xA, PSxA);
    k_convBt<<<dim3(96, 32, 1), 256>>>(W_sense, (__half*)p_WsT, 3072, 1024, PSWs, 0, 0, 0);

    // ---- senses = x @ W_sense + b_sense (A 2-plane, W 1-plane) ----
    hgemm<2, 1, false, 0><<<dim3(24, 64, 1), 256, SM21>>>(
        (const __half*)p_xA, (const __half*)p_WsT, p_senses, b_sense,
        1024, 1024, 1024, 3072, PSxA, PSWs, 0, 0, 0, 0);

    // ---- combine -> xnew planes (+sel weights) ----
    k_combine<<<ROWS, 256>>>(x, W_sel);

    // ---- per-row features ----
    k_featrow<<<ROWS, 64>>>();

    // ---- scores + causal softmax -> fp16 attn ----
    k_scores<<<ROWS, 256>>>(w_charge, w_shell, w_distance, w_mass, w_valence, temperature);

    // ---- V = xnew @ W_v + b_v ----
    k_convBt<<<dim3(32, 32, 1), 256>>>(W_v, (__half*)p_WvT, 1024, 1024, PSWv, 0, 0, 0);
    hgemm<2, 1, false, 0><<<dim3(8, 64, 1), 256, SM21>>>(
        (const __half*)p_xnA, (const __half*)p_WvT, p_V, b_v,
        1024, 1024, 1024, 1024, PSxA, PSWv, 0, 0, 0, 0);

    // ---- V -> transposed split planes (both planes) ----
    k_convBt<<<dim3(32, 64, 4), 256>>>((const float*)p_V, (__half*)p_VT, 1024, 2048, PSVT,
                                       (size_t)2048 * 1024, (size_t)1024 * 2048, 1);

    // ---- attnout = attn @ V (causal, batched) -> split planes ----
    hgemm<1, 2, true, 1><<<dim3(8, 16, 4), 256, SM12>>>(
        (const __half*)p_attnA, (const __half*)p_VT, p_aoA, nullptr,
        2048, 2048, 2048, 1024, 0, PSVT, PSao,
        (size_t)2048 * 2048, (size_t)1024 * 2048, (size_t)2048 * 1024);

    // ---- out = attnout @ W_out + b_out ----
    k_convBt<<<dim3(32, 32, 1), 256>>>(W_out, (__half*)p_WoT, 1024, 1024, PSWo, 0, 0, 0);
    hgemm<2, 1, false, 0><<<dim3(8, 64, 1), 256, SM21>>>(
        (const __half*)p_aoA, (const __half*)p_WoT, out, b_out,
        1024, 1024, 1024, 1024, PSao, PSWo, 0, 0, 0, 0);

    (void)in_sizes; (void)n_in; (void)out_size;
}

// round 9
// speedup vs baseline: 3.4840x; 1.1212x over previous
#include <cuda_runtime.h>
#include <cuda_fp16.h>
#include <math.h>
#include <stdint.h>
#include <cstdint>

// Problem constants
#define BB 4
#define NN 2048
#define DD 1024
#define ROWS 8192      // B*N
#define NF 37

// ---------------- device scratch (allocation-free) ----------------
__device__ float g_senses[8192 * 3072];
__device__ float g_partial[4 * 16 * 1024];
__device__ float g_xmean [4 * 1024];
__device__ float g_ctx   [4 * 1024];
__device__ float g_selctx[4 * 3];
__device__ float g_selw  [8192 * 3];
__device__ float g_rowf  [8192 * 8];
__device__ float g_compat[1024];
__device__ float g_Wfeat [1024 * NF];
__device__ float g_bfeat [NF];
__device__ float g_Wcomb [1024 * 128];   // cols 0..110 = Wsense@Wfeat, 111..113 = W_sel[:D], 114..127 zero
__device__ float g_bcomb [3 * NF];
__device__ float g_xC    [2 * 8192 * 128];

// fp16 split planes
__device__ __half g_xA   [2 * 8192 * 1024];
__device__ __half g_WsT  [2 * 3072 * 1024];
__device__ __half g_xnA  [2 * 8192 * 1024];
__device__ __half g_WvT  [2 * 1024 * 1024];
__device__ __half g_VT   [2 * 4 * 1024 * 2048];
__device__ __half g_attnA[8192 * 2048];
__device__ __half g_aoA  [8192 * 1024];   // hi plane only
__device__ __half g_WoT  [2 * 1024 * 1024];

__device__ __forceinline__ float sp_(float z) {
    return z > 20.f ? z : log1pf(expf(z));
}
__device__ __forceinline__ float neg_inf_() { return __int_as_float(0xff800000u); }

__device__ __forceinline__ uint32_t smem_u32(const void* p) {
    uint32_t a;
    asm("{ .reg .u64 t; cvta.to.shared.u64 t, %1; cvt.u32.u64 %0, t; }" : "=r"(a) : "l"(p));
    return a;
}
__device__ __forceinline__ void ldm_x4(uint32_t* r, uint32_t addr) {
    asm volatile("ldmatrix.sync.aligned.m8n8.x4.shared.b16 {%0,%1,%2,%3}, [%4];"
        : "=r"(r[0]), "=r"(r[1]), "=r"(r[2]), "=r"(r[3]) : "r"(addr));
}
__device__ __forceinline__ void mma_f16(float* c, const uint32_t* a, const uint32_t* b) {
    asm volatile("mma.sync.aligned.m16n8k16.row.col.f32.f16.f16.f32 "
        "{%0,%1,%2,%3}, {%4,%5,%6,%7}, {%8,%9}, {%0,%1,%2,%3};"
        : "+f"(c[0]), "+f"(c[1]), "+f"(c[2]), "+f"(c[3])
        : "r"(a[0]), "r"(a[1]), "r"(a[2]), "r"(a[3]), "r"(b[0]), "r"(b[1]));
}
__device__ __forceinline__ void cp_async16(uint32_t s, const void* g) {
    asm volatile("cp.async.cg.shared.global [%0], [%1], 16;" :: "r"(s), "l"(g));
}
__device__ __forceinline__ void cp_commit() { asm volatile("cp.async.commit_group;" ::: "memory"); }
template<int N> __device__ __forceinline__ void cp_wait() {
    asm volatile("cp.async.wait_group %0;" :: "n"(N) : "memory");
}

// ---------------- fp16 split GEMM (mma.sync, 3-stage cp.async pipeline) ------
// C = A@B (+bias). A: SAP fp16 planes [M][K]; B: SBP planes [N][K] (pre-transposed).
// Terms (ci,cj) with ci+cj < max(SAP,SBP) accumulate in fp32.
// OUTM: 0 = fp32 row-major; 1 = fp16 hi plane (+lo plane iff psC!=0);
//       2 = fp16 hi/lo planes written TRANSPOSED batch-split (VT layout).
template<int SAP, int SBP, bool CAUSAL, int OUTM>
__global__ __launch_bounds__(256, 2)
void hgemm(const __half* __restrict__ A, const __half* __restrict__ B,
           void* __restrict__ Cv, const float* __restrict__ bias,
           int K, int lda, int ldb, int ldc,
           size_t psA, size_t psB, size_t psC,
           size_t sA, size_t sB, size_t sC) {
    extern __shared__ char smx[];
    A += (size_t)blockIdx.z * sA;
    B += (size_t)blockIdx.z * sB;
    const int by = CAUSAL ? (gridDim.y - 1 - blockIdx.y) : blockIdx.y;
    const int rowStart = by * 128;
    const int colStart = blockIdx.x * 128;
    const int kmax = CAUSAL ? min(K, rowStart + 128) : K;
    const int tid = threadIdx.x, lane = tid & 31, wid = tid >> 5;
    const int mW = (wid >> 2) * 64, nW = (wid & 3) * 32;
    const uint32_t smBase = smem_u32(smx);
    constexpr uint32_t PL  = 8192u;
    constexpr uint32_t STG = (uint32_t)(SAP + SBP) * PL;
    constexpr int MAXS = (SAP > SBP) ? SAP : SBP;

    float acc[4][4][4];
    #pragma unroll
    for (int i = 0; i < 4; ++i)
        #pragma unroll
        for (int j = 0; j < 4; ++j)
            #pragma unroll
            for (int e = 0; e < 4; ++e) acc[i][j][e] = 0.f;

    const int rA = mW + (lane & 15);
    const int rB = nW + ((lane >> 4) << 3) + (lane & 7);
    const uint32_t swA = (uint32_t)((rA >> 1) & 3);
    const uint32_t swB = (uint32_t)((rB >> 1) & 3);
    const uint32_t cA = (uint32_t)(lane >> 4);
    const uint32_t cB = (uint32_t)((lane >> 3) & 1);
    uint32_t aRow[4], bRow[2];
    #pragma unroll
    for (int am = 0; am < 4; ++am) aRow[am] = (uint32_t)(rA + am * 16) * 64u;
    #pragma unroll
    for (int np = 0; np < 2; ++np) bRow[np] = (uint32_t)(rB + np * 16) * 64u;

    const int r2 = tid >> 2, c2 = tid & 3;

    auto loadStage = [&](int st, int k0) {
        uint32_t sb = smBase + (uint32_t)st * STG;
        #pragma unroll
        for (int p = 0; p < SAP; ++p) {
            const __half* gp = A + (size_t)p * psA + (size_t)rowStart * lda + k0;
            #pragma unroll
            for (int l = 0; l < 2; ++l) {
                int r = l * 64 + r2;
                uint32_t sa = sb + (uint32_t)p * PL + (uint32_t)r * 64u +
                              ((((uint32_t)c2) ^ (((uint32_t)r >> 1) & 3u)) << 4);
                cp_async16(sa, gp + (size_t)r * lda + c2 * 8);
            }
        }
        #pragma unroll
        for (int p = 0; p < SBP; ++p) {
            const __half* gp = B + (size_t)p * psB + (size_t)colStart * ldb + k0;
            #pragma unroll
            for (int l = 0; l < 2; ++l) {
                int r = l * 64 + r2;
                uint32_t sa = sb + (uint32_t)(SAP + p) * PL + (uint32_t)r * 64u +
                              ((((uint32_t)c2) ^ (((uint32_t)r >> 1) & 3u)) << 4);
                cp_async16(sa, gp + (size_t)r * ldb + c2 * 8);
            }
        }
    };

    const int nIter = kmax >> 5;
    if (0 < nIter) loadStage(0, 0);
    cp_commit();
    if (1 < nIter) loadStage(1, 32);
    cp_commit();

    for (int it = 0; it < nIter; ++it) {
        if (it + 1 < nIter) cp_wait<1>(); else cp_wait<0>();
        __syncthreads();
        int nl = it + 2;
        if (nl < nIter) loadStage(nl - (nl / 3) * 3, nl << 5);
        cp_commit();

        uint32_t sb = smBase + (uint32_t)(it - (it / 3) * 3) * STG;
        #pragma unroll
        for (int ks = 0; ks < 2; ++ks) {
            uint32_t af[SAP][4][4], bf[SBP][2][4];
            #pragma unroll
            for (int p = 0; p < SAP; ++p)
                #pragma unroll
                for (int am = 0; am < 4; ++am)
                    ldm_x4(af[p][am], sb + (uint32_t)p * PL + aRow[am] +
                           ((((uint32_t)(2 * ks) + cA) ^ swA) << 4));
            #pragma unroll
            for (int p = 0; p < SBP; ++p)
                #pragma unroll
                for (int np = 0; np < 2; ++np)
                    ldm_x4(bf[p][np], sb + (uint32_t)(SAP + p) * PL + bRow[np] +
                           ((((uint32_t)(2 * ks) + cB) ^ swB) << 4));
            #pragma unroll
            for (int ci = 0; ci < SAP; ++ci)
                #pragma unroll
                for (int cj = 0; cj < SBP; ++cj) {
                    if (ci + cj >= MAXS) continue;
                    #pragma unroll
                    for (int am = 0; am < 4; ++am)
                        #pragma unroll
                        for (int an = 0; an < 4; ++an)
                            mma_f16(acc[am][an], af[ci][am], &bf[cj][an >> 1][(an & 1) * 2]);
                }
        }
    }

    #pragma unroll
    for (int am = 0; am < 4; ++am) {
        int row = rowStart + mW + am * 16 + (lane >> 2);
        #pragma unroll
        for (int an = 0; an < 4; ++an) {
            int col = colStart + nW + an * 8 + (lane & 3) * 2;
            float b0 = bias ? bias[col] : 0.f, b1 = bias ? bias[col + 1] : 0.f;
            float v0 = acc[am][an][0] + b0, v1 = acc[am][an][1] + b1;
            float v2 = acc[am][an][2] + b0, v3 = acc[am][an][3] + b1;
            if (OUTM == 0) {
                float* C = (float*)Cv + (size_t)blockIdx.z * sC;
                *(float2*)(C + (size_t)row * ldc + col) = make_float2(v0, v1);
                *(float2*)(C + (size_t)(row + 8) * ldc + col) = make_float2(v2, v3);
            } else if (OUTM == 1) {
                __half* Cp = (__half*)Cv + (size_t)blockIdx.z * sC;
                __half h0 = __float2half(v0), h1 = __float2half(v1);
                __half h2 = __float2half(v2), h3 = __float2half(v3);
                __half2 hh01; hh01.x = h0; hh01.y = h1;
                __half2 hh23; hh23.x = h2; hh23.y = h3;
                *(__half2*)(Cp + (size_t)row * ldc + col) = hh01;
                *(__half2*)(Cp + (size_t)(row + 8) * ldc + col) = hh23;
                if (psC) {
                    __half2 ll01; ll01.x = __float2half(v0 - __half2float(h0));
                                  ll01.y = __float2half(v1 - __half2float(h1));
                    __half2 ll23; ll23.x = __float2half(v2 - __half2float(h2));
                                  ll23.y = __float2half(v3 - __half2float(h3));
                    *(__half2*)(Cp + psC + (size_t)row * ldc + col) = ll01;
                    *(__half2*)(Cp + psC + (size_t)(row + 8) * ldc + col) = ll23;
                }
            } else {
                // OUTM == 2: transposed batch-split VT write: VT[b][col][row&2047]
                __half* Cp = (__half*)Cv;
                size_t a0 = ((size_t)(row >> 11) << 21) + (size_t)col * 2048 + (row & 2047);
                __half h0 = __float2half(v0), h1 = __float2half(v1);
                __half h2 = __float2half(v2), h3 = __float2half(v3);
                Cp[a0]            = h0;
                Cp[a0 + 2048]     = h1;
                Cp[a0 + 8]        = h2;
                Cp[a0 + 2056]     = h3;
                Cp[psC + a0]        = __float2half(v0 - __half2float(h0));
                Cp[psC + a0 + 2048] = __float2half(v1 - __half2float(h1));
                Cp[psC + a0 + 8]    = __float2half(v2 - __half2float(h2));
                Cp[psC + a0 + 2056] = __float2half(v3 - __half2float(h3));
            }
        }
    }
}

// ---------------- conversion kernels ----------------

__global__ void k_splitA(const float* __restrict__ src, __half* __restrict__ dst, size_t ps) {
    size_t i = ((size_t)blockIdx.x * 256 + threadIdx.x) * 4;
    float4 v = *(const float4*)(src + i);
    __half h0 = __float2half(v.x), h1 = __float2half(v.y);
    __half h2 = __float2half(v.z), h3 = __float2half(v.w);
    __half2 a; a.x = h0; a.y = h1;
    __half2 b; b.x = h2; b.y = h3;
    *(__half2*)(dst + i) = a; *(__half2*)(dst + i + 2) = b;
    __half2 c; c.x = __float2half(v.x - __half2float(h0)); c.y = __float2half(v.y - __half2float(h1));
    __half2 d; d.x = __float2half(v.z - __half2float(h2)); d.y = __float2half(v.w - __half2float(h3));
    *(__half2*)(dst + ps + i) = c; *(__half2*)(dst + ps + i + 2) = d;
}

// transpose + split (hi plane always; lo plane only if wrlo)
__global__ void k_convBt(const float* __restrict__ src, __half* __restrict__ dst,
                         int lds, int ldd, size_t ps, size_t sS, size_t sD, int wrlo) {
    src += (size_t)blockIdx.z * sS;
    dst += (size_t)blockIdx.z * sD;
    int n0 = blockIdx.x * 32, k0 = blockIdx.y * 32;
    __shared__ float t[32][33];
    int tx = threadIdx.x & 31, ty = threadIdx.x >> 5;
    #pragma unroll
    for (int l = 0; l < 4; ++l)
        t[ty + l * 8][tx] = src[(size_t)(k0 + ty + l * 8) * lds + n0 + tx];
    __syncthreads();
    #pragma unroll
    for (int l = 0; l < 4; ++l) {
        int n = ty + l * 8;
        float v = t[tx][n];
        __half h = __float2half(v);
        dst[(size_t)(n0 + n) * ldd + k0 + tx] = h;
        if (wrlo)
            dst[ps + (size_t)(n0 + n) * ldd + k0 + tx] = __float2half(v - __half2float(h));
    }
}

// ---------------- merged prep kernels ----------------

// blocks [0,256): meanpart | 256: compat | [257,405): packfeat | [405,417): packsel
__global__ void k_prep1(const float* __restrict__ x, const float* __restrict__ L,
                        const float* __restrict__ W_charge, const float* __restrict__ b_charge,
                        const float* __restrict__ W_shell,  const float* __restrict__ b_shell,
                        const float* __restrict__ W_class,  const float* __restrict__ b_class,
                        const float* __restrict__ W_mass,   const float* __restrict__ b_mass,
                        const float* __restrict__ W_sel) {
    int blk = blockIdx.x, tid = threadIdx.x;
    if (blk < 256) {
        int d  = (blk & 3) * 256 + tid;
        int bc = blk >> 2;
        int b  = bc >> 4, c = bc & 15;
        const float* xp = x + ((size_t)b * NN + c * 128) * DD + d;
        float s = 0.f;
        #pragma unroll 8
        for (int n = 0; n < 128; n++) s += xp[(size_t)n * DD];
        g_partial[bc * 1024 + d] = s;
    } else if (blk == 256) {
        for (int t = tid; t < 1024; t += 256) {
            int i = t >> 5, j = t & 31;
            float v = (L[i * 32 + j] + L[j * 32 + i]) * 0.5f;
            g_compat[t] = 1.f / (1.f + expf(-v));
        }
    } else if (blk < 405) {
        int idx = (blk - 257) * 256 + tid;
        if (idx < 1024 * NF) {
            int k = idx / NF, c = idx % NF;
            float v;
            if (c == 0)       v = W_charge[k];
            else if (c <= 3)  v = W_shell[k * 3 + (c - 1)];
            else if (c <= 35) v = W_class[k * 32 + (c - 4)];
            else              v = W_mass[k];
            g_Wfeat[k * NF + c] = v;
        }
        if (idx < NF) {
            float v;
            if (idx == 0)       v = b_charge[0];
            else if (idx <= 3)  v = b_shell[idx - 1];
            else if (idx <= 35) v = b_class[idx - 4];
            else                v = b_mass[0];
            g_bfeat[idx] = v;
        }
    } else {
        int idx = (blk - 405) * 256 + tid;    // 0..3071
        if (idx < 3072) {
            int k = idx / 3, s = idx % 3;
            g_Wcomb[k * 128 + 111 + s] = W_sel[(size_t)k * 3 + s];
        }
    }
}

// blocks [0,16): meanfin | 16: bcomb
__global__ void k_prep2(const float* __restrict__ b_sense) {
    int blk = blockIdx.x, tid = threadIdx.x;
    if (blk < 16) {
        int idx = blk * 256 + tid;
        int b = idx >> 10, d = idx & 1023;
        float s = 0.f;
        #pragma unroll
        for (int c = 0; c < 16; c++) s += g_partial[(b * 16 + c) * 1024 + d];
        g_xmean[idx] = s * (1.f / (float)NN);
    } else {
        int c = tid;
        if (c < 3 * NF) {
            int s = c / NF, cc = c % NF;
            float acc = 0.f;
            for (int k = 0; k < 1024; k++)
                acc += b_sense[s * 1024 + k] * g_Wfeat[k * NF + cc];
            g_bcomb[c] = acc;
        }
    }
}

__global__ void k_ctxpart(const float* __restrict__ W_ctx) {
    int d = blockIdx.x * 256 + threadIdx.x;
    int b = blockIdx.y;
    int z = blockIdx.z;
    const float* xm = g_xmean + b * 1024 + z * 128;
    const float* W  = W_ctx + (size_t)(z * 128) * 1024 + d;
    float acc = 0.f;
    #pragma unroll 8
    for (int k = 0; k < 128; k++) acc += xm[k] * W[(size_t)k * 1024];
    g_partial[(z * 4 + b) * 1024 + d] = acc;
}

__global__ void k_ctxfin(const float* __restrict__ b_ctx) {
    int idx = blockIdx.x * 256 + threadIdx.x;
    int b = idx >> 10, d = idx & 1023;
    float s = 0.f;
    #pragma unroll
    for (int z = 0; z < 8; z++) s += g_partial[(z * 4 + b) * 1024 + d];
    g_ctx[idx] = s + b_ctx[d];
}

__global__ void k_selctx(const float* __restrict__ W_sel, const float* __restrict__ b_sel) {
    int s = blockIdx.x, b = blockIdx.y;
    int tid = threadIdx.x;
    const float* c = g_ctx + b * 1024;
    float p = 0.f;
    for (int k = tid; k < 1024; k += 128) p += c[k] * W_sel[(size_t)(1024 + k) * 3 + s];
    __shared__ float red[128];
    red[tid] = p; __syncthreads();
    for (int o = 64; o; o >>= 1) { if (tid < o) red[tid] += red[tid + o]; __syncthreads(); }
    if (tid == 0) g_selctx[b * 3 + s] = red[0] + b_sel[s];
}

// per-row: sel softmax (from xC cols 111..113) -> g_selw, then features -> g_rowf
__global__ void k_rowprep() {
    int row = blockIdx.x;
    int b   = row >> 11;
    int tid = threadIdx.x;   // 64
    __shared__ float fv[NF];
    __shared__ float sw[3];
    const float* xc0 = g_xC + (size_t)row * 128;
    const float* xc1 = g_xC + (size_t)8192 * 128 + (size_t)row * 128;
    if (tid < 3)
        fv[tid] = xc0[111 + tid] + xc1[111 + tid] + g_selctx[b * 3 + tid];
    __syncthreads();
    if (tid == 0) {
        float l0 = fv[0], l1 = fv[1], l2 = fv[2];
        float m = fmaxf(l0, fmaxf(l1, l2));
        float e0 = expf(l0 - m), e1 = expf(l1 - m), e2 = expf(l2 - m);
        float inv = 1.f / (e0 + e1 + e2);
        sw[0] = e0 * inv; sw[1] = e1 * inv; sw[2] = e2 * inv;
        g_selw[row * 3 + 0] = sw[0];
        g_selw[row * 3 + 1] = sw[1];
        g_selw[row * 3 + 2] = sw[2];
    }
    __syncthreads();
    if (tid < NF) {
        float v0 = xc0[tid]          + xc1[tid]          + g_bcomb[tid];
        float v1 = xc0[NF + tid]     + xc1[NF + tid]     + g_bcomb[NF + tid];
        float v2 = xc0[2 * NF + tid] + xc1[2 * NF + tid] + g_bcomb[2 * NF + tid];
        fv[tid] = g_bfeat[tid] + sw[0] * v0 + sw[1] * v1 + sw[2] * v2;
    }
    __syncthreads();
    if (tid == 0) {
        float* rf = g_rowf + (size_t)row * 8;
        rf[0] = tanhf(fv[0]);
        float s0 = fv[1], s1 = fv[2], s2 = fv[3];
        float m = fmaxf(s0, fmaxf(s1, s2));
        float e0 = expf(s0 - m), e1 = expf(s1 - m), e2 = expf(s2 - m);
        float inv = 1.f / (e0 + e1 + e2);
        rf[1] = e0 * inv; rf[2] = e1 * inv; rf[3] = e2 * inv;
        float best = fv[4]; int bi = 0;
        #pragma unroll
        for (int c = 1; c < 32; c++) { float v = fv[4 + c]; if (v > best) { best = v; bi = c; } }
        rf[4] = sp_(fv[36]) + 0.5f;
        rf[5] = __int_as_float(bi);
        rf[6] = 0.f; rf[7] = 0.f;
    }
}

// elementwise combine: xnew = sum_s w_s * senses_s -> fp16 hi/lo planes
__global__ void k_combine2() {
    int row = blockIdx.x;
    int tid = threadIdx.x;   // 256
    float w0 = g_selw[row * 3 + 0];
    float w1 = g_selw[row * 3 + 1];
    float w2 = g_selw[row * 3 + 2];
    const float4* S0 = (const float4*)(g_senses + (size_t)row * 3072);
    const float4* S1 = (const float4*)(g_senses + (size_t)row * 3072 + 1024);
    const float4* S2 = (const float4*)(g_senses + (size_t)row * 3072 + 2048);
    float4 a = S0[tid], bb = S1[tid], c = S2[tid];
    float o0 = w0 * a.x + w1 * bb.x + w2 * c.x;
    float o1 = w0 * a.y + w1 * bb.y + w2 * c.y;
    float o2 = w0 * a.z + w1 * bb.z + w2 * c.z;
    float o3 = w0 * a.w + w1 * bb.w + w2 * c.w;
    __half h0 = __float2half(o0), h1 = __float2half(o1);
    __half h2 = __float2half(o2), h3 = __float2half(o3);
    size_t off = (size_t)row * 1024 + tid * 4;
    const size_t PS = (size_t)8192 * 1024;
    __half2 hh01; hh01.x = h0; hh01.y = h1;
    __half2 hh23; hh23.x = h2; hh23.y = h3;
    *(__half2*)(g_xnA + off) = hh01;
    *(__half2*)(g_xnA + off + 2) = hh23;
    __half2 ll01; ll01.x = __float2half(o0 - __half2float(h0)); ll01.y = __float2half(o1 - __half2float(h1));
    __half2 ll23; ll23.x = __float2half(o2 - __half2float(h2)); ll23.y = __float2half(o3 - __half2float(h3));
    *(__half2*)(g_xnA + PS + off) = ll01;
    *(__half2*)(g_xnA + PS + off + 2) = ll23;
}

// energy scores + causal softmax (bounded loops) -> fp16 attn plane
__global__ void k_scores(const float* __restrict__ w_charge, const float* __restrict__ w_shell,
                         const float* __restrict__ w_distance, const float* __restrict__ w_mass,
                         const float* __restrict__ w_valence, const float* __restrict__ temperature) {
    int gi = blockIdx.x;
    int b  = gi >> 11;
    int i  = NN - 1 - (gi & 2047);
    int rowEnd = ((i >> 7) + 1) << 7;
    int tid = threadIdx.x;
    __shared__ float sc[2048];
    __shared__ float cp[1024];
    __shared__ float red[256];
    for (int t = tid; t < 1024; t += 256) cp[t] = g_compat[t];

    float spc = sp_(w_charge[0]);
    float sps = sp_(w_shell[0]);
    float spd = sp_(w_distance[0]);
    float spm = sp_(w_mass[0]);
    float spv = sp_(w_valence[0]);
    float invt = 1.f / sp_(temperature[0]);

    const float4* rf = (const float4*)g_rowf;
    int base = b * NN;
    float4 m0 = rf[(size_t)(base + i) * 2];
    float4 m1 = rf[(size_t)(base + i) * 2 + 1];
    float ci = m0.x, si0 = m0.y, si1 = m0.z, si2 = m0.w;
    float mi = m1.x;
    int cli = __float_as_int(m1.y) * 32;
    __syncthreads();

    for (int j = tid; j <= i; j += 256) {
        float4 f0 = rf[(size_t)(base + j) * 2];
        float4 f1 = rf[(size_t)(base + j) * 2 + 1];
        float d0 = fabsf(si0 - f0.y);
        float d1 = fabsf(si1 - f0.z);
        float d2 = fabsf(si2 - f0.w);
        float dist = (float)(i - j);
        float E = spc * ci * f0.x + sps * (d0 + d1 + d2)
                - spd * __fdividef(1.f, 1.f + 0.1f * dist)
                + spm * 0.1f * mi * f1.x - spv;
        sc[j] = -E * invt * cp[cli + __float_as_int(f1.y)];
    }
    __syncthreads();

    float lm = neg_inf_();
    for (int j = tid; j <= i; j += 256) lm = fmaxf(lm, sc[j]);
    red[tid] = lm; __syncthreads();
    for (int o = 128; o; o >>= 1) { if (tid < o) red[tid] = fmaxf(red[tid], red[tid + o]); __syncthreads(); }
    float mx = red[0]; __syncthreads();

    float ls = 0.f;
    for (int j = tid; j <= i; j += 256) { float e = expf(sc[j] - mx); sc[j] = e; ls += e; }
    red[tid] = ls; __syncthreads();
    for (int o = 128; o; o >>= 1) { if (tid < o) red[tid] += red[tid + o]; __syncthreads(); }
    float inv = 1.f / red[0];

    __half* ar = g_attnA + (size_t)(base + i) * NN;
    for (int j = tid; j < rowEnd; j += 256)
        ar[j] = __float2half(j <= i ? sc[j] * inv : 0.f);
}

// ---------------- fp32 tiled SGEMM (feat path, with batch strides) -----------
__global__ __launch_bounds__(256)
void sgemm128(const float* __restrict__ A, const float* __restrict__ B,
              float* __restrict__ C, const float* __restrict__ bias,
              int M, int N, int K, int lda, int ldb, int ldc,
              size_t sA, size_t sB, size_t sC) {
    A += (size_t)blockIdx.z * sA;
    B += (size_t)blockIdx.z * sB;
    C += (size_t)blockIdx.z * sC;
    int rowStart = blockIdx.y * 128;
    int colStart = blockIdx.x * 128;

    __shared__ float As[16][128];
    __shared__ float Bs[16][128];
    int tid = threadIdx.x;
    int tx = tid & 15, ty = tid >> 4;
    float acc[8][8];
    #pragma unroll
    for (int i = 0; i < 8; i++)
        #pragma unroll
        for (int j = 0; j < 8; j++) acc[i][j] = 0.f;

    const bool n_vec = ((N & 3) == 0);

    for (int k0 = 0; k0 < K; k0 += 16) {
        #pragma unroll
        for (int l = 0; l < 2; l++) {
            int idx = tid + l * 256;
            int m = idx >> 2;
            int kq = (idx & 3) * 4;
            float4 v = *reinterpret_cast<const float4*>(
                A + (size_t)(rowStart + m) * lda + k0 + kq);
            As[kq + 0][m] = v.x; As[kq + 1][m] = v.y; As[kq + 2][m] = v.z; As[kq + 3][m] = v.w;
        }
        #pragma unroll
        for (int l = 0; l < 2; l++) {
            int idx = tid + l * 256;
            int kr = idx >> 5;
            int nq = (idx & 31) * 4;
            int col = colStart + nq;
            float4 v;
            if (n_vec && col + 3 < N) {
                v = *reinterpret_cast<const float4*>(B + (size_t)(k0 + kr) * ldb + col);
            } else {
                const float* bp = B + (size_t)(k0 + kr) * ldb;
                v.x = (col + 0 < N) ? bp[col + 0] : 0.f;
                v.y = (col + 1 < N) ? bp[col + 1] : 0.f;
                v.z = (col + 2 < N) ? bp[col + 2] : 0.f;
                v.w = (col + 3 < N) ? bp[col + 3] : 0.f;
            }
            *reinterpret_cast<float4*>(&Bs[kr][nq]) = v;
        }
        __syncthreads();
        #pragma unroll
        for (int kk = 0; kk < 16; kk++) {
            float ra[8], rb[8];
            *(float4*)&ra[0] = *(float4*)&As[kk][ty * 8];
            *(float4*)&ra[4] = *(float4*)&As[kk][ty * 8 + 4];
            *(float4*)&rb[0] = *(float4*)&Bs[kk][tx * 8];
            *(float4*)&rb[4] = *(float4*)&Bs[kk][tx * 8 + 4];
            #pragma unroll
            for (int i = 0; i < 8; i++)
                #pragma unroll
                for (int j = 0; j < 8; j++)
                    acc[i][j] += ra[i] * rb[j];
        }
        __syncthreads();
    }

    #pragma unroll
    for (int i = 0; i < 8; i++) {
        size_t row = rowStart + ty * 8 + i;
        #pragma unroll
        for (int j = 0; j < 8; j++) {
            int col = colStart + tx * 8 + j;
            if (col < N) {
                float v = acc[i][j] + (bias ? bias[col] : 0.f);
                C[row * (size_t)ldc + col] = v;
            }
        }
    }
}

// ---------------- host ----------------
extern "C" void kernel_launch(void* const* d_in, const int* in_sizes, int n_in,
                              void* d_out, int out_size) {
    const float* x         = (const float*)d_in[0];
    const float* W_sense   = (const float*)d_in[1];
    const float* b_sense   = (const float*)d_in[2];
    const float* W_ctx     = (const float*)d_in[3];
    const float* b_ctx     = (const float*)d_in[4];
    const float* W_sel     = (const float*)d_in[5];
    const float* b_sel     = (const float*)d_in[6];
    const float* W_charge  = (const float*)d_in[7];
    const float* b_charge  = (const float*)d_in[8];
    const float* W_shell   = (const float*)d_in[9];
    const float* b_shell   = (const float*)d_in[10];
    const float* W_class   = (const float*)d_in[11];
    const float* b_class   = (const float*)d_in[12];
    const float* W_mass    = (const float*)d_in[13];
    const float* b_mass    = (const float*)d_in[14];
    const float* compatL   = (const float*)d_in[17];
    const float* w_charge  = (const float*)d_in[18];
    const float* w_shell   = (const float*)d_in[19];
    const float* w_distance= (const float*)d_in[20];
    const float* w_mass    = (const float*)d_in[21];
    const float* w_valence = (const float*)d_in[22];
    const float* temperature=(const float*)d_in[23];
    const float* W_v       = (const float*)d_in[24];
    const float* b_v       = (const float*)d_in[25];
    const float* W_out     = (const float*)d_in[26];
    const float* b_out     = (const float*)d_in[27];
    float* out = (float*)d_out;

    void *p_senses, *p_Wfeat, *p_Wcomb, *p_xC;
    void *p_xA, *p_WsT, *p_xnA, *p_WvT, *p_VT, *p_attnA, *p_aoA, *p_WoT;
    cudaGetSymbolAddress(&p_senses, g_senses);
    cudaGetSymbolAddress(&p_Wfeat,  g_Wfeat);
    cudaGetSymbolAddress(&p_Wcomb,  g_Wcomb);
    cudaGetSymbolAddress(&p_xC,     g_xC);
    cudaGetSymbolAddress(&p_xA,     g_xA);
    cudaGetSymbolAddress(&p_WsT,    g_WsT);
    cudaGetSymbolAddress(&p_xnA,    g_xnA);
    cudaGetSymbolAddress(&p_WvT,    g_WvT);
    cudaGetSymbolAddress(&p_VT,     g_VT);
    cudaGetSymbolAddress(&p_attnA,  g_attnA);
    cudaGetSymbolAddress(&p_aoA,    g_aoA);
    cudaGetSymbolAddress(&p_WoT,    g_WoT);

    const int SM21 = 3 * 3 * 8192;   // 73728
    const int SM12 = 3 * 3 * 8192;   // 73728
    const int SM11 = 3 * 2 * 8192;   // 49152
    cudaFuncSetAttribute(hgemm<2, 1, false, 0>, cudaFuncAttributeMaxDynamicSharedMemorySize, SM21);
    cudaFuncSetAttribute(hgemm<2, 1, false, 2>, cudaFuncAttributeMaxDynamicSharedMemorySize, SM21);
    cudaFuncSetAttribute(hgemm<1, 2, true, 1>,  cudaFuncAttributeMaxDynamicSharedMemorySize, SM12);
    cudaFuncSetAttribute(hgemm<1, 1, false, 0>, cudaFuncAttributeMaxDynamicSharedMemorySize, SM11);

    const size_t PSxA = (size_t)8192 * 1024;
    const size_t PSWs = (size_t)3072 * 1024;
    const size_t PSWv = (size_t)1024 * 1024;
    const size_t PSVT = (size_t)4 * 1024 * 2048;
    const size_t PSWo = (size_t)1024 * 1024;

    // ---- prep (merged) ----
    k_prep1<<<417, 256>>>(x, compatL, W_charge, b_charge, W_shell, b_shell,
                          W_class, b_class, W_mass, b_mass, W_sel);
    k_prep2<<<17, 256>>>(b_sense);
    k_ctxpart<<<dim3(4, 4, 8), 256>>>(W_ctx);
    k_ctxfin<<<16, 256>>>(b_ctx);
    k_selctx<<<dim3(3, 4), 128>>>(W_sel, b_sel);
    // Wcomb cols 0..110
    sgemm128<<<dim3(1, 8, 3), 256>>>(W_sense, (const float*)p_Wfeat, (float*)p_Wcomb, nullptr,
                                     1024, NF, 1024, 3072, NF, 128,
                                     1024, 0, NF);
    // xC = x @ Wcomb (feat partials + sel logits), split-K 2
    sgemm128<<<dim3(1, 64, 2), 256>>>(x, (const float*)p_Wcomb, (float*)p_xC, nullptr,
                                      ROWS, 128, 512, 1024, 128, 128,
                                      512, (size_t)512 * 128, (size_t)8192 * 128);
    // sel softmax + row features
    k_rowprep<<<ROWS, 64>>>();

    // ---- operand conversion ----
    k_splitA<<<8192, 256>>>(x, (__half*)p_xA, PSxA);
    k_convBt<<<dim3(96, 32, 1), 256>>>(W_sense, (__half*)p_WsT, 3072, 1024, PSWs, 0, 0, 0);

    // ---- senses = x @ W_sense + b_sense (A 2-plane, W 1-plane) ----
    hgemm<2, 1, false, 0><<<dim3(24, 64, 1), 256, SM21>>>(
        (const __half*)p_xA, (const __half*)p_WsT, p_senses, b_sense,
        1024, 1024, 1024, 3072, PSxA, PSWs, 0, 0, 0, 0);

    // ---- combine (elementwise) -> xnew planes ----
    k_combine2<<<ROWS, 256>>>();

    // ---- scores + causal softmax -> fp16 attn ----
    k_scores<<<ROWS, 256>>>(w_charge, w_shell, w_distance, w_mass, w_valence, temperature);

    // ---- V = xnew @ W_v + b_v -> VT planes directly (transposed epilogue) ----
    k_convBt<<<dim3(32, 32, 1), 256>>>(W_v, (__half*)p_WvT, 1024, 1024, PSWv, 0, 0, 0);
    hgemm<2, 1, false, 2><<<dim3(8, 64, 1), 256, SM21>>>(
        (const __half*)p_xnA, (const __half*)p_WvT, p_VT, b_v,
        1024, 1024, 1024, 0, PSxA, PSWv, PSVT, 0, 0, 0);

    // ---- attnout = attn @ V (causal, batched) -> aoA hi plane only ----
    hgemm<1, 2, true, 1><<<dim3(8, 16, 4), 256, SM12>>>(
        (const __half*)p_attnA, (const __half*)p_VT, p_aoA, nullptr,
        2048, 2048, 2048, 1024, 0, PSVT, 0,
        (size_t)2048 * 2048, (size_t)1024 * 2048, (size_t)2048 * 1024);

    // ---- out = attnout @ W_out + b_out (1-term) ----
    k_convBt<<<dim3(32, 32, 1), 256>>>(W_out, (__half*)p_WoT, 1024, 1024, PSWo, 0, 0, 0);
    hgemm<1, 1, false, 0><<<dim3(8, 64, 1), 256, SM11>>>(
        (const __half*)p_aoA, (const __half*)p_WoT, out, b_out,
        1024, 1024, 1024, 1024, PSxA, PSWo, 0, 0, 0, 0);

    (void)in_sizes; (void)n_in; (void)out_size;
}

// round 10
// speedup vs baseline: 4.1575x; 1.1933x over previous
#include <cuda_runtime.h>
#include <cuda_fp16.h>
#include <math.h>
#include <stdint.h>
#include <cstdint>

// Problem constants
#define BB 4
#define NN 2048
#define DD 1024
#define ROWS 8192      // B*N
#define NF 37

// ---------------- device scratch (allocation-free) ----------------
__device__ float g_senses[8192 * 3072];
__device__ float g_partial[4 * 16 * 1024];
__device__ float g_xmean [4 * 1024];
__device__ float g_ctx   [4 * 1024];
__device__ float g_selctx[4 * 3];
__device__ float g_selw  [8192 * 3];
__device__ float g_rowf  [8192 * 8];
__device__ float g_compat[1024];
__device__ float g_Wfeat [1024 * NF];
__device__ float g_bfeat [NF];
__device__ float g_Wcomb [1024 * 128];   // cols 0..110 = Wsense@Wfeat, 111..113 = W_sel[:D], 114..127 zero
__device__ float g_bcomb [3 * NF];
__device__ float g_xC    [2 * 8192 * 128];

// fp16 planes
__device__ __half g_xA   [8192 * 1024];       // hi only
__device__ __half g_WsT  [3072 * 1024];       // hi only
__device__ __half g_xnA  [8192 * 1024];       // hi only
__device__ __half g_WvT  [1024 * 1024];       // hi only
__device__ __half g_VT   [2 * 4 * 1024 * 2048];  // hi+lo (refines V in attn@V)
__device__ __half g_attnA[8192 * 2048];
__device__ __half g_aoA  [8192 * 1024];       // hi only
__device__ __half g_WoT  [1024 * 1024];       // hi only

__device__ __forceinline__ float sp_(float z) {
    return z > 20.f ? z : log1pf(expf(z));
}
__device__ __forceinline__ float neg_inf_() { return __int_as_float(0xff800000u); }

__device__ __forceinline__ uint32_t smem_u32(const void* p) {
    uint32_t a;
    asm("{ .reg .u64 t; cvta.to.shared.u64 t, %1; cvt.u32.u64 %0, t; }" : "=r"(a) : "l"(p));
    return a;
}
__device__ __forceinline__ void ldm_x4(uint32_t* r, uint32_t addr) {
    asm volatile("ldmatrix.sync.aligned.m8n8.x4.shared.b16 {%0,%1,%2,%3}, [%4];"
        : "=r"(r[0]), "=r"(r[1]), "=r"(r[2]), "=r"(r[3]) : "r"(addr));
}
__device__ __forceinline__ void mma_f16(float* c, const uint32_t* a, const uint32_t* b) {
    asm volatile("mma.sync.aligned.m16n8k16.row.col.f32.f16.f16.f32 "
        "{%0,%1,%2,%3}, {%4,%5,%6,%7}, {%8,%9}, {%0,%1,%2,%3};"
        : "+f"(c[0]), "+f"(c[1]), "+f"(c[2]), "+f"(c[3])
        : "r"(a[0]), "r"(a[1]), "r"(a[2]), "r"(a[3]), "r"(b[0]), "r"(b[1]));
}
__device__ __forceinline__ void cp_async16(uint32_t s, const void* g) {
    asm volatile("cp.async.cg.shared.global [%0], [%1], 16;" :: "r"(s), "l"(g));
}
__device__ __forceinline__ void cp_commit() { asm volatile("cp.async.commit_group;" ::: "memory"); }
template<int N> __device__ __forceinline__ void cp_wait() {
    asm volatile("cp.async.wait_group %0;" :: "n"(N) : "memory");
}

// ---------------- fp16 split GEMM (mma.sync, 3-stage cp.async pipeline) ------
// C = A@B (+bias). A: SAP fp16 planes [M][K]; B: SBP planes [N][K] (pre-transposed).
// Terms (ci,cj) with ci+cj < max(SAP,SBP) accumulate in fp32.
// OUTM: 0 = fp32 row-major; 1 = fp16 hi plane (+lo plane iff psC!=0);
//       2 = fp16 hi/lo planes written TRANSPOSED batch-split (VT layout).
template<int SAP, int SBP, bool CAUSAL, int OUTM>
__global__ __launch_bounds__(256, 2)
void hgemm(const __half* __restrict__ A, const __half* __restrict__ B,
           void* __restrict__ Cv, const float* __restrict__ bias,
           int K, int lda, int ldb, int ldc,
           size_t psA, size_t psB, size_t psC,
           size_t sA, size_t sB, size_t sC) {
    extern __shared__ char smx[];
    A += (size_t)blockIdx.z * sA;
    B += (size_t)blockIdx.z * sB;
    const int by = CAUSAL ? (gridDim.y - 1 - blockIdx.y) : blockIdx.y;
    const int rowStart = by * 128;
    const int colStart = blockIdx.x * 128;
    const int kmax = CAUSAL ? min(K, rowStart + 128) : K;
    const int tid = threadIdx.x, lane = tid & 31, wid = tid >> 5;
    const int mW = (wid >> 2) * 64, nW = (wid & 3) * 32;
    const uint32_t smBase = smem_u32(smx);
    constexpr uint32_t PL  = 8192u;
    constexpr uint32_t STG = (uint32_t)(SAP + SBP) * PL;
    constexpr int MAXS = (SAP > SBP) ? SAP : SBP;

    float acc[4][4][4];
    #pragma unroll
    for (int i = 0; i < 4; ++i)
        #pragma unroll
        for (int j = 0; j < 4; ++j)
            #pragma unroll
            for (int e = 0; e < 4; ++e) acc[i][j][e] = 0.f;

    const int rA = mW + (lane & 15);
    const int rB = nW + ((lane >> 4) << 3) + (lane & 7);
    const uint32_t swA = (uint32_t)((rA >> 1) & 3);
    const uint32_t swB = (uint32_t)((rB >> 1) & 3);
    const uint32_t cA = (uint32_t)(lane >> 4);
    const uint32_t cB = (uint32_t)((lane >> 3) & 1);
    uint32_t aRow[4], bRow[2];
    #pragma unroll
    for (int am = 0; am < 4; ++am) aRow[am] = (uint32_t)(rA + am * 16) * 64u;
    #pragma unroll
    for (int np = 0; np < 2; ++np) bRow[np] = (uint32_t)(rB + np * 16) * 64u;

    const int r2 = tid >> 2, c2 = tid & 3;

    auto loadStage = [&](int st, int k0) {
        uint32_t sb = smBase + (uint32_t)st * STG;
        #pragma unroll
        for (int p = 0; p < SAP; ++p) {
            const __half* gp = A + (size_t)p * psA + (size_t)rowStart * lda + k0;
            #pragma unroll
            for (int l = 0; l < 2; ++l) {
                int r = l * 64 + r2;
                uint32_t sa = sb + (uint32_t)p * PL + (uint32_t)r * 64u +
                              ((((uint32_t)c2) ^ (((uint32_t)r >> 1) & 3u)) << 4);
                cp_async16(sa, gp + (size_t)r * lda + c2 * 8);
            }
        }
        #pragma unroll
        for (int p = 0; p < SBP; ++p) {
            const __half* gp = B + (size_t)p * psB + (size_t)colStart * ldb + k0;
            #pragma unroll
            for (int l = 0; l < 2; ++l) {
                int r = l * 64 + r2;
                uint32_t sa = sb + (uint32_t)(SAP + p) * PL + (uint32_t)r * 64u +
                              ((((uint32_t)c2) ^ (((uint32_t)r >> 1) & 3u)) << 4);
                cp_async16(sa, gp + (size_t)r * ldb + c2 * 8);
            }
        }
    };

    const int nIter = kmax >> 5;
    if (0 < nIter) loadStage(0, 0);
    cp_commit();
    if (1 < nIter) loadStage(1, 32);
    cp_commit();

    for (int it = 0; it < nIter; ++it) {
        if (it + 1 < nIter) cp_wait<1>(); else cp_wait<0>();
        __syncthreads();
        int nl = it + 2;
        if (nl < nIter) loadStage(nl - (nl / 3) * 3, nl << 5);
        cp_commit();

        uint32_t sb = smBase + (uint32_t)(it - (it / 3) * 3) * STG;
        #pragma unroll
        for (int ks = 0; ks < 2; ++ks) {
            uint32_t af[SAP][4][4], bf[SBP][2][4];
            #pragma unroll
            for (int p = 0; p < SAP; ++p)
                #pragma unroll
                for (int am = 0; am < 4; ++am)
                    ldm_x4(af[p][am], sb + (uint32_t)p * PL + aRow[am] +
                           ((((uint32_t)(2 * ks) + cA) ^ swA) << 4));
            #pragma unroll
            for (int p = 0; p < SBP; ++p)
                #pragma unroll
                for (int np = 0; np < 2; ++np)
                    ldm_x4(bf[p][np], sb + (uint32_t)(SAP + p) * PL + bRow[np] +
                           ((((uint32_t)(2 * ks) + cB) ^ swB) << 4));
            #pragma unroll
            for (int ci = 0; ci < SAP; ++ci)
                #pragma unroll
                for (int cj = 0; cj < SBP; ++cj) {
                    if (ci + cj >= MAXS) continue;
                    #pragma unroll
                    for (int am = 0; am < 4; ++am)
                        #pragma unroll
                        for (int an = 0; an < 4; ++an)
                            mma_f16(acc[am][an], af[ci][am], &bf[cj][an >> 1][(an & 1) * 2]);
                }
        }
    }

    #pragma unroll
    for (int am = 0; am < 4; ++am) {
        int row = rowStart + mW + am * 16 + (lane >> 2);
        #pragma unroll
        for (int an = 0; an < 4; ++an) {
            int col = colStart + nW + an * 8 + (lane & 3) * 2;
            float b0 = bias ? bias[col] : 0.f, b1 = bias ? bias[col + 1] : 0.f;
            float v0 = acc[am][an][0] + b0, v1 = acc[am][an][1] + b1;
            float v2 = acc[am][an][2] + b0, v3 = acc[am][an][3] + b1;
            if (OUTM == 0) {
                float* C = (float*)Cv + (size_t)blockIdx.z * sC;
                *(float2*)(C + (size_t)row * ldc + col) = make_float2(v0, v1);
                *(float2*)(C + (size_t)(row + 8) * ldc + col) = make_float2(v2, v3);
            } else if (OUTM == 1) {
                __half* Cp = (__half*)Cv + (size_t)blockIdx.z * sC;
                __half h0 = __float2half(v0), h1 = __float2half(v1);
                __half h2 = __float2half(v2), h3 = __float2half(v3);
                __half2 hh01; hh01.x = h0; hh01.y = h1;
                __half2 hh23; hh23.x = h2; hh23.y = h3;
                *(__half2*)(Cp + (size_t)row * ldc + col) = hh01;
                *(__half2*)(Cp + (size_t)(row + 8) * ldc + col) = hh23;
                if (psC) {
                    __half2 ll01; ll01.x = __float2half(v0 - __half2float(h0));
                                  ll01.y = __float2half(v1 - __half2float(h1));
                    __half2 ll23; ll23.x = __float2half(v2 - __half2float(h2));
                                  ll23.y = __float2half(v3 - __half2float(h3));
                    *(__half2*)(Cp + psC + (size_t)row * ldc + col) = ll01;
                    *(__half2*)(Cp + psC + (size_t)(row + 8) * ldc + col) = ll23;
                }
            } else {
                // OUTM == 2: transposed batch-split VT write: VT[b][col][row&2047]
                __half* Cp = (__half*)Cv;
                size_t a0 = ((size_t)(row >> 11) << 21) + (size_t)col * 2048 + (row & 2047);
                __half h0 = __float2half(v0), h1 = __float2half(v1);
                __half h2 = __float2half(v2), h3 = __float2half(v3);
                Cp[a0]            = h0;
                Cp[a0 + 2048]     = h1;
                Cp[a0 + 8]        = h2;
                Cp[a0 + 2056]     = h3;
                Cp[psC + a0]        = __float2half(v0 - __half2float(h0));
                Cp[psC + a0 + 2048] = __float2half(v1 - __half2float(h1));
                Cp[psC + a0 + 8]    = __float2half(v2 - __half2float(h2));
                Cp[psC + a0 + 2056] = __float2half(v3 - __half2float(h3));
            }
        }
    }
}

// ---------------- conversion kernels ----------------

// fp32 -> fp16 (hi plane only)
__global__ void k_cvtA(const float* __restrict__ src, __half* __restrict__ dst) {
    size_t i = ((size_t)blockIdx.x * 256 + threadIdx.x) * 4;
    float4 v = *(const float4*)(src + i);
    __half2 a; a.x = __float2half(v.x); a.y = __float2half(v.y);
    __half2 b; b.x = __float2half(v.z); b.y = __float2half(v.w);
    *(__half2*)(dst + i) = a; *(__half2*)(dst + i + 2) = b;
}

// transpose: dst[n][k] = fp16(src[k][n]) (hi only)
__global__ void k_convBt(const float* __restrict__ src, __half* __restrict__ dst,
                         int lds, int ldd) {
    int n0 = blockIdx.x * 32, k0 = blockIdx.y * 32;
    __shared__ float t[32][33];
    int tx = threadIdx.x & 31, ty = threadIdx.x >> 5;
    #pragma unroll
    for (int l = 0; l < 4; ++l)
        t[ty + l * 8][tx] = src[(size_t)(k0 + ty + l * 8) * lds + n0 + tx];
    __syncthreads();
    #pragma unroll
    for (int l = 0; l < 4; ++l) {
        int n = ty + l * 8;
        dst[(size_t)(n0 + n) * ldd + k0 + tx] = __float2half(t[tx][n]);
    }
}

// ---------------- merged prep kernels ----------------

// blocks [0,256): meanpart | 256: compat | [257,405): packfeat | [405,417): packsel
__global__ void k_prep1(const float* __restrict__ x, const float* __restrict__ L,
                        const float* __restrict__ W_charge, const float* __restrict__ b_charge,
                        const float* __restrict__ W_shell,  const float* __restrict__ b_shell,
                        const float* __restrict__ W_class,  const float* __restrict__ b_class,
                        const float* __restrict__ W_mass,   const float* __restrict__ b_mass,
                        const float* __restrict__ W_sel) {
    int blk = blockIdx.x, tid = threadIdx.x;
    if (blk < 256) {
        int d  = (blk & 3) * 256 + tid;
        int bc = blk >> 2;
        int b  = bc >> 4, c = bc & 15;
        const float* xp = x + ((size_t)b * NN + c * 128) * DD + d;
        float s = 0.f;
        #pragma unroll 8
        for (int n = 0; n < 128; n++) s += xp[(size_t)n * DD];
        g_partial[bc * 1024 + d] = s;
    } else if (blk == 256) {
        for (int t = tid; t < 1024; t += 256) {
            int i = t >> 5, j = t & 31;
            float v = (L[i * 32 + j] + L[j * 32 + i]) * 0.5f;
            g_compat[t] = 1.f / (1.f + expf(-v));
        }
    } else if (blk < 405) {
        int idx = (blk - 257) * 256 + tid;
        if (idx < 1024 * NF) {
            int k = idx / NF, c = idx % NF;
            float v;
            if (c == 0)       v = W_charge[k];
            else if (c <= 3)  v = W_shell[k * 3 + (c - 1)];
            else if (c <= 35) v = W_class[k * 32 + (c - 4)];
            else              v = W_mass[k];
            g_Wfeat[k * NF + c] = v;
        }
        if (idx < NF) {
            float v;
            if (idx == 0)       v = b_charge[0];
            else if (idx <= 3)  v = b_shell[idx - 1];
            else if (idx <= 35) v = b_class[idx - 4];
            else                v = b_mass[0];
            g_bfeat[idx] = v;
        }
    } else {
        int idx = (blk - 405) * 256 + tid;    // 0..3071
        if (idx < 3072) {
            int k = idx / 3, s = idx % 3;
            g_Wcomb[k * 128 + 111 + s] = W_sel[(size_t)k * 3 + s];
        }
    }
}

// blocks [0,16): meanfin | 16: bcomb
__global__ void k_prep2(const float* __restrict__ b_sense) {
    int blk = blockIdx.x, tid = threadIdx.x;
    if (blk < 16) {
        int idx = blk * 256 + tid;
        int b = idx >> 10, d = idx & 1023;
        float s = 0.f;
        #pragma unroll
        for (int c = 0; c < 16; c++) s += g_partial[(b * 16 + c) * 1024 + d];
        g_xmean[idx] = s * (1.f / (float)NN);
    } else {
        int c = tid;
        if (c < 3 * NF) {
            int s = c / NF, cc = c % NF;
            float acc = 0.f;
            for (int k = 0; k < 1024; k++)
                acc += b_sense[s * 1024 + k] * g_Wfeat[k * NF + cc];
            g_bcomb[c] = acc;
        }
    }
}

__global__ void k_ctxpart(const float* __restrict__ W_ctx) {
    int d = blockIdx.x * 256 + threadIdx.x;
    int b = blockIdx.y;
    int z = blockIdx.z;
    const float* xm = g_xmean + b * 1024 + z * 128;
    const float* W  = W_ctx + (size_t)(z * 128) * 1024 + d;
    float acc = 0.f;
    #pragma unroll 8
    for (int k = 0; k < 128; k++) acc += xm[k] * W[(size_t)k * 1024];
    g_partial[(z * 4 + b) * 1024 + d] = acc;
}

__global__ void k_ctxfin(const float* __restrict__ b_ctx) {
    int idx = blockIdx.x * 256 + threadIdx.x;
    int b = idx >> 10, d = idx & 1023;
    float s = 0.f;
    #pragma unroll
    for (int z = 0; z < 8; z++) s += g_partial[(z * 4 + b) * 1024 + d];
    g_ctx[idx] = s + b_ctx[d];
}

__global__ void k_selctx(const float* __restrict__ W_sel, const float* __restrict__ b_sel) {
    int s = blockIdx.x, b = blockIdx.y;
    int tid = threadIdx.x;
    const float* c = g_ctx + b * 1024;
    float p = 0.f;
    for (int k = tid; k < 1024; k += 128) p += c[k] * W_sel[(size_t)(1024 + k) * 3 + s];
    __shared__ float red[128];
    red[tid] = p; __syncthreads();
    for (int o = 64; o; o >>= 1) { if (tid < o) red[tid] += red[tid + o]; __syncthreads(); }
    if (tid == 0) g_selctx[b * 3 + s] = red[0] + b_sel[s];
}

// per-row: sel softmax (from xC cols 111..113) -> g_selw, then features -> g_rowf
__global__ void k_rowprep() {
    int row = blockIdx.x;
    int b   = row >> 11;
    int tid = threadIdx.x;   // 64
    __shared__ float fv[NF];
    __shared__ float sw[3];
    const float* xc0 = g_xC + (size_t)row * 128;
    const float* xc1 = g_xC + (size_t)8192 * 128 + (size_t)row * 128;
    if (tid < 3)
        fv[tid] = xc0[111 + tid] + xc1[111 + tid] + g_selctx[b * 3 + tid];
    __syncthreads();
    if (tid == 0) {
        float l0 = fv[0], l1 = fv[1], l2 = fv[2];
        float m = fmaxf(l0, fmaxf(l1, l2));
        float e0 = expf(l0 - m), e1 = expf(l1 - m), e2 = expf(l2 - m);
        float inv = 1.f / (e0 + e1 + e2);
        sw[0] = e0 * inv; sw[1] = e1 * inv; sw[2] = e2 * inv;
        g_selw[row * 3 + 0] = sw[0];
        g_selw[row * 3 + 1] = sw[1];
        g_selw[row * 3 + 2] = sw[2];
    }
    __syncthreads();
    if (tid < NF) {
        float v0 = xc0[tid]          + xc1[tid]          + g_bcomb[tid];
        float v1 = xc0[NF + tid]     + xc1[NF + tid]     + g_bcomb[NF + tid];
        float v2 = xc0[2 * NF + tid] + xc1[2 * NF + tid] + g_bcomb[2 * NF + tid];
        fv[tid] = g_bfeat[tid] + sw[0] * v0 + sw[1] * v1 + sw[2] * v2;
    }
    __syncthreads();
    if (tid == 0) {
        float* rf = g_rowf + (size_t)row * 8;
        rf[0] = tanhf(fv[0]);
        float s0 = fv[1], s1 = fv[2], s2 = fv[3];
        float m = fmaxf(s0, fmaxf(s1, s2));
        float e0 = expf(s0 - m), e1 = expf(s1 - m), e2 = expf(s2 - m);
        float inv = 1.f / (e0 + e1 + e2);
        rf[1] = e0 * inv; rf[2] = e1 * inv; rf[3] = e2 * inv;
        float best = fv[4]; int bi = 0;
        #pragma unroll
        for (int c = 1; c < 32; c++) { float v = fv[4 + c]; if (v > best) { best = v; bi = c; } }
        rf[4] = sp_(fv[36]) + 0.5f;
        rf[5] = __int_as_float(bi);
        rf[6] = 0.f; rf[7] = 0.f;
    }
}

// elementwise combine: xnew = sum_s w_s * senses_s -> fp16 hi plane
__global__ void k_combine2() {
    int row = blockIdx.x;
    int tid = threadIdx.x;   // 256
    float w0 = g_selw[row * 3 + 0];
    float w1 = g_selw[row * 3 + 1];
    float w2 = g_selw[row * 3 + 2];
    const float4* S0 = (const float4*)(g_senses + (size_t)row * 3072);
    const float4* S1 = (const float4*)(g_senses + (size_t)row * 3072 + 1024);
    const float4* S2 = (const float4*)(g_senses + (size_t)row * 3072 + 2048);
    float4 a = S0[tid], bb = S1[tid], c = S2[tid];
    float o0 = w0 * a.x + w1 * bb.x + w2 * c.x;
    float o1 = w0 * a.y + w1 * bb.y + w2 * c.y;
    float o2 = w0 * a.z + w1 * bb.z + w2 * c.z;
    float o3 = w0 * a.w + w1 * bb.w + w2 * c.w;
    size_t off = (size_t)row * 1024 + tid * 4;
    __half2 hh01; hh01.x = __float2half(o0); hh01.y = __float2half(o1);
    __half2 hh23; hh23.x = __float2half(o2); hh23.y = __float2half(o3);
    *(__half2*)(g_xnA + off) = hh01;
    *(__half2*)(g_xnA + off + 2) = hh23;
}

// energy scores + causal softmax (bounded loops) -> fp16 attn plane
__global__ void k_scores(const float* __restrict__ w_charge, const float* __restrict__ w_shell,
                         const float* __restrict__ w_distance, const float* __restrict__ w_mass,
                         const float* __restrict__ w_valence, const float* __restrict__ temperature) {
    int gi = blockIdx.x;
    int b  = gi >> 11;
    int i  = NN - 1 - (gi & 2047);
    int rowEnd = ((i >> 7) + 1) << 7;
    int tid = threadIdx.x;
    __shared__ float sc[2048];
    __shared__ float cp[1024];
    __shared__ float red[256];
    for (int t = tid; t < 1024; t += 256) cp[t] = g_compat[t];

    float spc = sp_(w_charge[0]);
    float sps = sp_(w_shell[0]);
    float spd = sp_(w_distance[0]);
    float spm = sp_(w_mass[0]);
    float spv = sp_(w_valence[0]);
    float invt = 1.f / sp_(temperature[0]);

    const float4* rf = (const float4*)g_rowf;
    int base = b * NN;
    float4 m0 = rf[(size_t)(base + i) * 2];
    float4 m1 = rf[(size_t)(base + i) * 2 + 1];
    float ci = m0.x, si0 = m0.y, si1 = m0.z, si2 = m0.w;
    float mi = m1.x;
    int cli = __float_as_int(m1.y) * 32;
    __syncthreads();

    for (int j = tid; j <= i; j += 256) {
        float4 f0 = rf[(size_t)(base + j) * 2];
        float4 f1 = rf[(size_t)(base + j) * 2 + 1];
        float d0 = fabsf(si0 - f0.y);
        float d1 = fabsf(si1 - f0.z);
        float d2 = fabsf(si2 - f0.w);
        float dist = (float)(i - j);
        float E = spc * ci * f0.x + sps * (d0 + d1 + d2)
                - spd * __fdividef(1.f, 1.f + 0.1f * dist)
                + spm * 0.1f * mi * f1.x - spv;
        sc[j] = -E * invt * cp[cli + __float_as_int(f1.y)];
    }
    __syncthreads();

    float lm = neg_inf_();
    for (int j = tid; j <= i; j += 256) lm = fmaxf(lm, sc[j]);
    red[tid] = lm; __syncthreads();
    for (int o = 128; o; o >>= 1) { if (tid < o) red[tid] = fmaxf(red[tid], red[tid + o]); __syncthreads(); }
    float mx = red[0]; __syncthreads();

    float ls = 0.f;
    for (int j = tid; j <= i; j += 256) { float e = expf(sc[j] - mx); sc[j] = e; ls += e; }
    red[tid] = ls; __syncthreads();
    for (int o = 128; o; o >>= 1) { if (tid < o) red[tid] += red[tid + o]; __syncthreads(); }
    float inv = 1.f / red[0];

    __half* ar = g_attnA + (size_t)(base + i) * NN;
    for (int j = tid; j < rowEnd; j += 256)
        ar[j] = __float2half(j <= i ? sc[j] * inv : 0.f);
}

// ---------------- fp32 tiled SGEMM (feat path, with batch strides) -----------
__global__ __launch_bounds__(256)
void sgemm128(const float* __restrict__ A, const float* __restrict__ B,
              float* __restrict__ C, const float* __restrict__ bias,
              int M, int N, int K, int lda, int ldb, int ldc,
              size_t sA, size_t sB, size_t sC) {
    A += (size_t)blockIdx.z * sA;
    B += (size_t)blockIdx.z * sB;
    C += (size_t)blockIdx.z * sC;
    int rowStart = blockIdx.y * 128;
    int colStart = blockIdx.x * 128;

    __shared__ float As[16][128];
    __shared__ float Bs[16][128];
    int tid = threadIdx.x;
    int tx = tid & 15, ty = tid >> 4;
    float acc[8][8];
    #pragma unroll
    for (int i = 0; i < 8; i++)
        #pragma unroll
        for (int j = 0; j < 8; j++) acc[i][j] = 0.f;

    const bool n_vec = ((N & 3) == 0);

    for (int k0 = 0; k0 < K; k0 += 16) {
        #pragma unroll
        for (int l = 0; l < 2; l++) {
            int idx = tid + l * 256;
            int m = idx >> 2;
            int kq = (idx & 3) * 4;
            float4 v = *reinterpret_cast<const float4*>(
                A + (size_t)(rowStart + m) * lda + k0 + kq);
            As[kq + 0][m] = v.x; As[kq + 1][m] = v.y; As[kq + 2][m] = v.z; As[kq + 3][m] = v.w;
        }
        #pragma unroll
        for (int l = 0; l < 2; l++) {
            int idx = tid + l * 256;
            int kr = idx >> 5;
            int nq = (idx & 31) * 4;
            int col = colStart + nq;
            float4 v;
            if (n_vec && col + 3 < N) {
                v = *reinterpret_cast<const float4*>(B + (size_t)(k0 + kr) * ldb + col);
            } else {
                const float* bp = B + (size_t)(k0 + kr) * ldb;
                v.x = (col + 0 < N) ? bp[col + 0] : 0.f;
                v.y = (col + 1 < N) ? bp[col + 1] : 0.f;
                v.z = (col + 2 < N) ? bp[col + 2] : 0.f;
                v.w = (col + 3 < N) ? bp[col + 3] : 0.f;
            }
            *reinterpret_cast<float4*>(&Bs[kr][nq]) = v;
        }
        __syncthreads();
        #pragma unroll
        for (int kk = 0; kk < 16; kk++) {
            float ra[8], rb[8];
            *(float4*)&ra[0] = *(float4*)&As[kk][ty * 8];
            *(float4*)&ra[4] = *(float4*)&As[kk][ty * 8 + 4];
            *(float4*)&rb[0] = *(float4*)&Bs[kk][tx * 8];
            *(float4*)&rb[4] = *(float4*)&Bs[kk][tx * 8 + 4];
            #pragma unroll
            for (int i = 0; i < 8; i++)
                #pragma unroll
                for (int j = 0; j < 8; j++)
                    acc[i][j] += ra[i] * rb[j];
        }
        __syncthreads();
    }

    #pragma unroll
    for (int i = 0; i < 8; i++) {
        size_t row = rowStart + ty * 8 + i;
        #pragma unroll
        for (int j = 0; j < 8; j++) {
            int col = colStart + tx * 8 + j;
            if (col < N) {
                float v = acc[i][j] + (bias ? bias[col] : 0.f);
                C[row * (size_t)ldc + col] = v;
            }
        }
    }
}

// ---------------- host ----------------
extern "C" void kernel_launch(void* const* d_in, const int* in_sizes, int n_in,
                              void* d_out, int out_size) {
    const float* x         = (const float*)d_in[0];
    const float* W_sense   = (const float*)d_in[1];
    const float* b_sense   = (const float*)d_in[2];
    const float* W_ctx     = (const float*)d_in[3];
    const float* b_ctx     = (const float*)d_in[4];
    const float* W_sel     = (const float*)d_in[5];
    const float* b_sel     = (const float*)d_in[6];
    const float* W_charge  = (const float*)d_in[7];
    const float* b_charge  = (const float*)d_in[8];
    const float* W_shell   = (const float*)d_in[9];
    const float* b_shell   = (const float*)d_in[10];
    const float* W_class   = (const float*)d_in[11];
    const float* b_class   = (const float*)d_in[12];
    const float* W_mass    = (const float*)d_in[13];
    const float* b_mass    = (const float*)d_in[14];
    const float* compatL   = (const float*)d_in[17];
    const float* w_charge  = (const float*)d_in[18];
    const float* w_shell   = (const float*)d_in[19];
    const float* w_distance= (const float*)d_in[20];
    const float* w_mass    = (const float*)d_in[21];
    const float* w_valence = (const float*)d_in[22];
    const float* temperature=(const float*)d_in[23];
    const float* W_v       = (const float*)d_in[24];
    const float* b_v       = (const float*)d_in[25];
    const float* W_out     = (const float*)d_in[26];
    const float* b_out     = (const float*)d_in[27];
    float* out = (float*)d_out;

    void *p_senses, *p_Wfeat, *p_Wcomb, *p_xC;
    void *p_xA, *p_WsT, *p_xnA, *p_WvT, *p_VT, *p_attnA, *p_aoA, *p_WoT;
    cudaGetSymbolAddress(&p_senses, g_senses);
    cudaGetSymbolAddress(&p_Wfeat,  g_Wfeat);
    cudaGetSymbolAddress(&p_Wcomb,  g_Wcomb);
    cudaGetSymbolAddress(&p_xC,     g_xC);
    cudaGetSymbolAddress(&p_xA,     g_xA);
    cudaGetSymbolAddress(&p_WsT,    g_WsT);
    cudaGetSymbolAddress(&p_xnA,    g_xnA);
    cudaGetSymbolAddress(&p_WvT,    g_WvT);
    cudaGetSymbolAddress(&p_VT,     g_VT);
    cudaGetSymbolAddress(&p_attnA,  g_attnA);
    cudaGetSymbolAddress(&p_aoA,    g_aoA);
    cudaGetSymbolAddress(&p_WoT,    g_WoT);

    const int SM11 = 3 * 2 * 8192;   // 49152
    const int SM12 = 3 * 3 * 8192;   // 73728
    cudaFuncSetAttribute(hgemm<1, 1, false, 0>, cudaFuncAttributeMaxDynamicSharedMemorySize, SM11);
    cudaFuncSetAttribute(hgemm<1, 1, false, 2>, cudaFuncAttributeMaxDynamicSharedMemorySize, SM11);
    cudaFuncSetAttribute(hgemm<1, 2, true, 1>,  cudaFuncAttributeMaxDynamicSharedMemorySize, SM12);

    const size_t PSVT = (size_t)4 * 1024 * 2048;

    // ---- prep (merged) ----
    k_prep1<<<417, 256>>>(x, compatL, W_charge, b_charge, W_shell, b_shell,
                          W_class, b_class, W_mass, b_mass, W_sel);
    k_prep2<<<17, 256>>>(b_sense);
    k_ctxpart<<<dim3(4, 4, 8), 256>>>(W_ctx);
    k_ctxfin<<<16, 256>>>(b_ctx);
    k_selctx<<<dim3(3, 4), 128>>>(W_sel, b_sel);
    // Wcomb cols 0..110
    sgemm128<<<dim3(1, 8, 3), 256>>>(W_sense, (const float*)p_Wfeat, (float*)p_Wcomb, nullptr,
                                     1024, NF, 1024, 3072, NF, 128,
                                     1024, 0, NF);
    // xC = x @ Wcomb (feat partials + sel logits), split-K 2
    sgemm128<<<dim3(1, 64, 2), 256>>>(x, (const float*)p_Wcomb, (float*)p_xC, nullptr,
                                      ROWS, 128, 512, 1024, 128, 128,
                                      512, (size_t)512 * 128, (size_t)8192 * 128);
    // sel softmax + row features
    k_rowprep<<<ROWS, 64>>>();

    // ---- operand conversion (hi planes only) ----
    k_cvtA<<<8192, 256>>>(x, (__half*)p_xA);
    k_convBt<<<dim3(96, 32, 1), 256>>>(W_sense, (__half*)p_WsT, 3072, 1024);

    // ---- senses = x @ W_sense + b_sense (1-term fp16) ----
    hgemm<1, 1, false, 0><<<dim3(24, 64, 1), 256, SM11>>>(
        (const __half*)p_xA, (const __half*)p_WsT, p_senses, b_sense,
        1024, 1024, 1024, 3072, 0, 0, 0, 0, 0, 0);

    // ---- combine (elementwise) -> xnew hi plane ----
    k_combine2<<<ROWS, 256>>>();

    // ---- scores + causal softmax -> fp16 attn ----
    k_scores<<<ROWS, 256>>>(w_charge, w_shell, w_distance, w_mass, w_valence, temperature);

    // ---- V = xnew @ W_v + b_v -> VT hi/lo planes (transposed epilogue) ----
    k_convBt<<<dim3(32, 32, 1), 256>>>(W_v, (__half*)p_WvT, 1024, 1024);
    hgemm<1, 1, false, 2><<<dim3(8, 64, 1), 256, SM11>>>(
        (const __half*)p_xnA, (const __half*)p_WvT, p_VT, b_v,
        1024, 1024, 1024, 0, 0, 0, PSVT, 0, 0, 0);

    // ---- attnout = attn @ V (causal, batched) -> aoA hi plane only ----
    hgemm<1, 2, true, 1><<<dim3(8, 16, 4), 256, SM12>>>(
        (const __half*)p_attnA, (const __half*)p_VT, p_aoA, nullptr,
        2048, 2048, 2048, 1024, 0, PSVT, 0,
        (size_t)2048 * 2048, (size_t)1024 * 2048, (size_t)2048 * 1024);

    // ---- out = attnout @ W_out + b_out (1-term) ----
    k_convBt<<<dim3(32, 32, 1), 256>>>(W_out, (__half*)p_WoT, 1024, 1024);
    hgemm<1, 1, false, 0><<<dim3(8, 64, 1), 256, SM11>>>(
        (const __half*)p_aoA, (const __half*)p_WoT, out, b_out,
        1024, 1024, 1024, 1024, 0, 0, 0, 0, 0, 0);

    (void)in_sizes; (void)n_in; (void)out_size;
}